// round 2
// baseline (speedup 1.0000x reference)
#include <cuda_runtime.h>
#include <math.h>

#define ROWS 8192
#define DIM  512
#define NSEQ 2048
#define NBATCH 4
#define NHEAD 8
#define DHEAD 64
#define IFF  2048

// ---------------- scratch (static device globals; no allocations) ----------------
__device__ float g_xn [ROWS * DIM];
__device__ float g_q  [ROWS * DIM];
__device__ float g_v  [ROWS * DIM];
__device__ float g_att[ROWS * DIM];
__device__ float g_x1 [ROWS * DIM];
__device__ float g_x2 [ROWS * DIM];
__device__ float g_aa [NBATCH * NHEAD * NSEQ];
__device__ float g_h  [ROWS * 2 * IFF];   // FF1 raw output (a | gate)
__device__ float g_g  [ROWS * IFF];       // a * gelu(gate)

// ---------------- LayerNorm: one block per row of 512 ----------------
__global__ __launch_bounds__(128) void ln_kernel(
    const float* __restrict__ X, const float* __restrict__ w,
    const float* __restrict__ bb, float* __restrict__ Y)
{
    int row = blockIdx.x;
    int tid = threadIdx.x;
    const float* xp = X + (size_t)row * DIM;
    float4 v = *(const float4*)(xp + tid * 4);
    float s  = v.x + v.y + v.z + v.w;
    float sq = v.x*v.x + v.y*v.y + v.z*v.z + v.w*v.w;
    #pragma unroll
    for (int o = 16; o > 0; o >>= 1) {
        s  += __shfl_xor_sync(0xffffffffu, s,  o);
        sq += __shfl_xor_sync(0xffffffffu, sq, o);
    }
    __shared__ float reds[4], redq[4];
    int wid = tid >> 5, lane = tid & 31;
    if (lane == 0) { reds[wid] = s; redq[wid] = sq; }
    __syncthreads();
    s  = reds[0] + reds[1] + reds[2] + reds[3];
    sq = redq[0] + redq[1] + redq[2] + redq[3];
    float mu   = s * (1.0f / DIM);
    float var  = sq * (1.0f / DIM) - mu * mu;
    float rstd = rsqrtf(var + 1e-5f);
    float4 wv = *(const float4*)(w  + tid * 4);
    float4 bv = *(const float4*)(bb + tid * 4);
    float4 out;
    out.x = (v.x - mu) * rstd * wv.x + bv.x;
    out.y = (v.y - mu) * rstd * wv.y + bv.y;
    out.z = (v.z - mu) * rstd * wv.z + bv.z;
    out.w = (v.w - mu) * rstd * wv.w + bv.w;
    *(float4*)(Y + (size_t)row * DIM + tid * 4) = out;
}

// ---------------- SGEMM: C = A[M,K] @ B[K,N] + bias (+ residual) ----------------
// BM=BN=128, BK=8, 256 threads, 8x8 per thread
#define SG_BM 128
#define SG_BN 128
#define SG_BK 8
__global__ __launch_bounds__(256) void sgemm_kernel(
    const float* __restrict__ A, const float* __restrict__ B,
    const float* __restrict__ bias, const float* __restrict__ res,
    float* __restrict__ C, int M, int N, int K)
{
    __shared__ float As[SG_BK][SG_BM];
    __shared__ float Bs[SG_BK][SG_BN];
    int tid  = threadIdx.x;
    int bcol = blockIdx.x, brow = blockIdx.y;
    int tcol = tid & 15;   // 0..15
    int trow = tid >> 4;   // 0..15

    const float* Ab = A + (size_t)brow * SG_BM * K;
    const float* Bb = B + (size_t)bcol * SG_BN;

    int a_r = tid >> 1;          // 0..127
    int a_c = (tid & 1) * 4;     // 0 or 4
    int b_r = tid >> 5;          // 0..7
    int b_c = (tid & 31) * 4;    // 0..124

    float acc[8][8];
    #pragma unroll
    for (int i = 0; i < 8; i++)
        #pragma unroll
        for (int j = 0; j < 8; j++) acc[i][j] = 0.0f;

    for (int k0 = 0; k0 < K; k0 += SG_BK) {
        float4 av = *(const float4*)(Ab + (size_t)a_r * K + k0 + a_c);
        As[a_c + 0][a_r] = av.x;
        As[a_c + 1][a_r] = av.y;
        As[a_c + 2][a_r] = av.z;
        As[a_c + 3][a_r] = av.w;
        *(float4*)&Bs[b_r][b_c] = *(const float4*)(Bb + (size_t)(k0 + b_r) * N + b_c);
        __syncthreads();
        #pragma unroll
        for (int k = 0; k < SG_BK; k++) {
            float ra[8], rb[8];
            *(float4*)&ra[0] = *(float4*)&As[k][trow * 8];
            *(float4*)&ra[4] = *(float4*)&As[k][trow * 8 + 4];
            *(float4*)&rb[0] = *(float4*)&Bs[k][tcol * 8];
            *(float4*)&rb[4] = *(float4*)&Bs[k][tcol * 8 + 4];
            #pragma unroll
            for (int i = 0; i < 8; i++)
                #pragma unroll
                for (int j = 0; j < 8; j++)
                    acc[i][j] += ra[i] * rb[j];
        }
        __syncthreads();
    }

    #pragma unroll
    for (int i = 0; i < 8; i++) {
        int row = brow * SG_BM + trow * 8 + i;
        #pragma unroll
        for (int j4 = 0; j4 < 8; j4 += 4) {
            int col = bcol * SG_BN + tcol * 8 + j4;
            float4 bv = *(const float4*)(bias + col);
            float4 out;
            out.x = acc[i][j4 + 0] + bv.x;
            out.y = acc[i][j4 + 1] + bv.y;
            out.z = acc[i][j4 + 2] + bv.z;
            out.w = acc[i][j4 + 3] + bv.w;
            if (res) {
                float4 rv = *(const float4*)(res + (size_t)row * N + col);
                out.x += rv.x; out.y += rv.y; out.z += rv.z; out.w += rv.w;
            }
            *(float4*)(C + (size_t)row * N + col) = out;
        }
    }
}

// ---------------- AA_j = |q_j|^2 per (b,h,n) ----------------
__global__ void aa_kernel(const float* __restrict__ Q, float* __restrict__ AA)
{
    int idx = blockIdx.x * blockDim.x + threadIdx.x;  // row*8 + h
    if (idx >= ROWS * NHEAD) return;
    int h = idx & 7;
    int row = idx >> 3;
    const float* qp = Q + (size_t)row * DIM + h * DHEAD;
    float s = 0.0f;
    #pragma unroll
    for (int i = 0; i < 16; i++) {
        float4 v = *(const float4*)(qp + i * 4);
        s += v.x*v.x + v.y*v.y + v.z*v.z + v.w*v.w;
    }
    int b = row >> 11, n = row & 2047;
    AA[((size_t)(b * NHEAD + h)) * NSEQ + n] = s;
}

// ---------------- Flash L2-distance attention ----------------
// logits_ij = 2*SCALE*(q_i . q_j) - SCALE*|q_j|^2   (row-constant -SCALE*|q_i|^2 dropped)
// 64 query rows / block, 128 threads (2 per row, dims split 32/32), K/V tiles of 64 in SMEM.
#define FA_BQ 64
#define FA_BK 64
__global__ __launch_bounds__(128) void flash_l2_kernel(
    const float* __restrict__ Q, const float* __restrict__ V,
    const float* __restrict__ AA, float* __restrict__ O)
{
    __shared__ float ks[FA_BK][DHEAD];
    __shared__ float vs[FA_BK][DHEAD];
    __shared__ float aas[FA_BK];

    int b = blockIdx.z, h = blockIdx.y;
    int q0 = blockIdx.x * FA_BQ;
    int tid = threadIdx.x;
    int r   = tid >> 1;
    int par = tid & 1;
    int row = b * NSEQ + q0 + r;

    const float* qrow = Q + (size_t)row * DIM + h * DHEAD + par * 32;
    float4 qr[8];
    #pragma unroll
    for (int i = 0; i < 8; i++) qr[i] = *(const float4*)(qrow + i * 4);

    float m = -1e30f, l = 0.0f;
    float o[32];
    #pragma unroll
    for (int i = 0; i < 32; i++) o[i] = 0.0f;

    const float scale = 0.125f;  // DHEAD^-0.5
    const float* aab = AA + ((size_t)(b * NHEAD + h)) * NSEQ;

    for (int kt = 0; kt < NSEQ; kt += FA_BK) {
        __syncthreads();
        for (int idx = tid; idx < FA_BK * 16; idx += 128) {
            int kr = idx >> 4, c4 = (idx & 15) * 4;
            size_t goff = (size_t)(b * NSEQ + kt + kr) * DIM + h * DHEAD + c4;
            *(float4*)&ks[kr][c4] = *(const float4*)(Q + goff);
            *(float4*)&vs[kr][c4] = *(const float4*)(V + goff);
        }
        if (tid < FA_BK) aas[tid] = aab[kt + tid];
        __syncthreads();

        #pragma unroll 2
        for (int j = 0; j < FA_BK; j++) {
            float s = 0.0f;
            const float4* kp = (const float4*)&ks[j][par * 32];
            #pragma unroll
            for (int i = 0; i < 8; i++) {
                float4 kv = kp[i];
                s += qr[i].x*kv.x + qr[i].y*kv.y + qr[i].z*kv.z + qr[i].w*kv.w;
            }
            s += __shfl_xor_sync(0xffffffffu, s, 1);   // combine dim halves
            s = 2.0f * scale * s - scale * aas[j];
            if (s > m) {
                float c = __expf(m - s);
                l *= c;
                #pragma unroll
                for (int i = 0; i < 32; i++) o[i] *= c;
                m = s;
            }
            float p = __expf(s - m);
            l += p;
            const float4* vp = (const float4*)&vs[j][par * 32];
            #pragma unroll
            for (int i = 0; i < 8; i++) {
                float4 vv = vp[i];
                o[i*4+0] += p * vv.x;
                o[i*4+1] += p * vv.y;
                o[i*4+2] += p * vv.z;
                o[i*4+3] += p * vv.w;
            }
        }
    }

    float inv = 1.0f / l;
    float* orow = O + (size_t)row * DIM + h * DHEAD + par * 32;
    #pragma unroll
    for (int i = 0; i < 8; i++) {
        float4 ov;
        ov.x = o[i*4+0] * inv;
        ov.y = o[i*4+1] * inv;
        ov.z = o[i*4+2] * inv;
        ov.w = o[i*4+3] * inv;
        *(float4*)(orow + i * 4) = ov;
    }
}

// ---------------- GEGLU activation: g = a * gelu_exact(gate) ----------------
__device__ __forceinline__ float gelu_exact(float x) {
    return 0.5f * x * (1.0f + erff(x * 0.70710678118654752f));
}
__global__ void geglu_kernel(const float* __restrict__ H, float* __restrict__ G)
{
    int idx = blockIdx.x * blockDim.x + threadIdx.x;   // float4 index over ROWS*IFF
    if (idx >= ROWS * (IFF / 4)) return;
    int row = idx / (IFF / 4);
    int c4  = idx % (IFF / 4);
    const float* base = H + (size_t)row * (2 * IFF);
    float4 a  = *(const float4*)(base + c4 * 4);
    float4 gt = *(const float4*)(base + IFF + c4 * 4);
    float4 r;
    r.x = a.x * gelu_exact(gt.x);
    r.y = a.y * gelu_exact(gt.y);
    r.z = a.z * gelu_exact(gt.z);
    r.w = a.w * gelu_exact(gt.w);
    *(float4*)(G + (size_t)row * IFF + c4 * 4) = r;
}

// ---------------- host orchestration ----------------
static inline void run_sgemm(const float* A, const float* B, const float* bias,
                             const float* res, float* C, int M, int N, int K)
{
    dim3 grid(N / SG_BN, M / SG_BM);
    sgemm_kernel<<<grid, 256>>>(A, B, bias, res, C, M, N, K);
}

extern "C" void kernel_launch(void* const* d_in, const int* in_sizes, int n_in,
                              void* d_out, int out_size)
{
    const float* x        = (const float*)d_in[0];
    const float* sa_w     = (const float*)d_in[1];
    const float* sa_b     = (const float*)d_in[2];
    const float* ca_w     = (const float*)d_in[3];
    const float* ca_b     = (const float*)d_in[4];
    const float* ff_nw    = (const float*)d_in[5];
    const float* ff_nb    = (const float*)d_in[6];
    const float* a1_wq    = (const float*)d_in[7];
    const float* a1_bq    = (const float*)d_in[8];
    const float* a1_wv    = (const float*)d_in[9];
    const float* a1_bv    = (const float*)d_in[10];
    const float* a1_wo    = (const float*)d_in[11];
    const float* a1_bo    = (const float*)d_in[12];
    const float* a2_wq    = (const float*)d_in[13];
    const float* a2_bq    = (const float*)d_in[14];
    const float* a2_wv    = (const float*)d_in[15];
    const float* a2_bv    = (const float*)d_in[16];
    const float* a2_wo    = (const float*)d_in[17];
    const float* a2_bo    = (const float*)d_in[18];
    const float* ff_w1    = (const float*)d_in[19];
    const float* ff_b1    = (const float*)d_in[20];
    const float* ff_w2    = (const float*)d_in[21];
    const float* ff_b2    = (const float*)d_in[22];
    float* out = (float*)d_out;

    float *xn, *q, *v, *att, *x1, *x2, *aa, *hh, *gg;
    cudaGetSymbolAddress((void**)&xn,  g_xn);
    cudaGetSymbolAddress((void**)&q,   g_q);
    cudaGetSymbolAddress((void**)&v,   g_v);
    cudaGetSymbolAddress((void**)&att, g_att);
    cudaGetSymbolAddress((void**)&x1,  g_x1);
    cudaGetSymbolAddress((void**)&x2,  g_x2);
    cudaGetSymbolAddress((void**)&aa,  g_aa);
    cudaGetSymbolAddress((void**)&hh,  g_h);
    cudaGetSymbolAddress((void**)&gg,  g_g);

    dim3 fa_grid(NSEQ / FA_BQ, NHEAD, NBATCH);
    int aa_blocks = (ROWS * NHEAD + 255) / 256;

    // ---- self-attention (attn1) ----
    ln_kernel<<<ROWS, 128>>>(x, sa_w, sa_b, xn);
    run_sgemm(xn, a1_wq, a1_bq, nullptr, q, ROWS, DIM, DIM);
    run_sgemm(xn, a1_wv, a1_bv, nullptr, v, ROWS, DIM, DIM);
    aa_kernel<<<aa_blocks, 256>>>(q, aa);
    flash_l2_kernel<<<fa_grid, 128>>>(q, v, aa, att);
    run_sgemm(att, a1_wo, a1_bo, x, x1, ROWS, DIM, DIM);      // + residual x

    // ---- "cross"-attention (attn2, k=q=v-from-x) ----
    ln_kernel<<<ROWS, 128>>>(x1, ca_w, ca_b, xn);
    run_sgemm(xn, a2_wq, a2_bq, nullptr, q, ROWS, DIM, DIM);
    run_sgemm(xn, a2_wv, a2_bv, nullptr, v, ROWS, DIM, DIM);
    aa_kernel<<<aa_blocks, 256>>>(q, aa);
    flash_l2_kernel<<<fa_grid, 128>>>(q, v, aa, att);
    run_sgemm(att, a2_wo, a2_bo, x1, x2, ROWS, DIM, DIM);     // + residual x1

    // ---- GEGLU FFN ----
    ln_kernel<<<ROWS, 128>>>(x2, ff_nw, ff_nb, xn);
    run_sgemm(xn, ff_w1, ff_b1, nullptr, hh, ROWS, 2 * IFF, DIM);
    int ge_blocks = (ROWS * (IFF / 4) + 255) / 256;
    geglu_kernel<<<ge_blocks, 256>>>(hh, gg);
    run_sgemm(gg, ff_w2, ff_b2, x2, out, ROWS, DIM, IFF);     // + residual x2 -> output
}

// round 4
// speedup vs baseline: 1.1529x; 1.1529x over previous
#include <cuda_runtime.h>
#include <cuda_bf16.h>
#include <cstdint>
#include <math.h>

#define ROWS 8192
#define DIM  512
#define NSEQ 2048
#define NBATCH 4
#define NHEAD 8
#define DHEAD 64
#define IFF  2048

// ---------------- scratch (static device globals; no allocations) ----------------
__device__ float g_xn [ROWS * DIM];
__device__ float g_q  [ROWS * DIM];
__device__ float g_v  [ROWS * DIM];
__device__ float g_att[ROWS * DIM];
__device__ float g_x1 [ROWS * DIM];
__device__ float g_x2 [ROWS * DIM];
__device__ float g_aa [NBATCH * NHEAD * NSEQ];
__device__ float g_h  [ROWS * 2 * IFF];   // FF1 raw output (a | gate)
__device__ float g_g  [ROWS * IFF];       // a * gelu(gate)
// bf16 hi/lo split buffers
__device__ __nv_bfloat16 g_ahi[ROWS * IFF];      // activations [M,K], max K=2048
__device__ __nv_bfloat16 g_alo[ROWS * IFF];
__device__ __nv_bfloat16 g_whi[4096 * 512];      // transposed weights [N,K]
__device__ __nv_bfloat16 g_wlo[4096 * 512];

// =================== helpers ===================
__device__ __forceinline__ uint32_t smem_u32(const void* p) {
    uint32_t a;
    asm("{ .reg .u64 t; cvta.to.shared.u64 t, %1; cvt.u32.u64 %0, t; }" : "=r"(a) : "l"(p));
    return a;
}
#define LDSM4(r, addr) \
    asm volatile("ldmatrix.sync.aligned.m8n8.x4.shared.b16 {%0,%1,%2,%3}, [%4];" \
        : "=r"((r)[0]), "=r"((r)[1]), "=r"((r)[2]), "=r"((r)[3]) : "r"(addr))

__device__ __forceinline__ void mma_bf16(float* d, const uint32_t* a, const uint32_t* b) {
    asm volatile("mma.sync.aligned.m16n8k16.row.col.f32.bf16.bf16.f32 "
        "{%0,%1,%2,%3}, {%4,%5,%6,%7}, {%8,%9}, {%0,%1,%2,%3};"
        : "+f"(d[0]), "+f"(d[1]), "+f"(d[2]), "+f"(d[3])
        : "r"(a[0]), "r"(a[1]), "r"(a[2]), "r"(a[3]), "r"(b[0]), "r"(b[1]));
}

// =================== HMMA GEMM: C[M,N] = A[M,K] @ Bt[N,K]^T + bias (+res) ===================
// hi/lo bf16 split: C = Ahi*Bhi + Ahi*Blo + Alo*Bhi (fp32 accum).
// 128x128 CTA tile, 8 warps (4x2), warp tile 32x64, BK=32.
#define MG_PAD 40   // smem row stride in bf16 elems (80B, 16B-aligned)

__global__ __launch_bounds__(256, 1) void mma_gemm_kernel(
    const __nv_bfloat16* __restrict__ Ahi, const __nv_bfloat16* __restrict__ Alo,
    const __nv_bfloat16* __restrict__ Bhi, const __nv_bfloat16* __restrict__ Blo,
    const float* __restrict__ bias, const float* __restrict__ res,
    float* __restrict__ C, int M, int N, int K)
{
    __shared__ __nv_bfloat16 sAh[128 * MG_PAD], sAl[128 * MG_PAD];
    __shared__ __nv_bfloat16 sBh[128 * MG_PAD], sBl[128 * MG_PAD];

    int tid = threadIdx.x, lane = tid & 31, wid = tid >> 5;
    int brow = blockIdx.y, bcol = blockIdx.x;
    int warp_m = (wid >> 1) * 32;
    int warp_n = (wid & 1) * 64;

    float acc[2][8][4];
    #pragma unroll
    for (int t = 0; t < 2; t++)
        #pragma unroll
        for (int nt = 0; nt < 8; nt++)
            #pragma unroll
            for (int j = 0; j < 4; j++) acc[t][nt][j] = 0.0f;

    uint32_t sa_h = smem_u32(sAh), sa_l = smem_u32(sAl);
    uint32_t sb_h = smem_u32(sBh), sb_l = smem_u32(sBl);

    for (int k0 = 0; k0 < K; k0 += 32) {
        __syncthreads();
        #pragma unroll
        for (int it = 0; it < 2; it++) {
            int idx = tid + it * 256;     // 0..511
            int row = idx >> 2;           // 0..127
            int ch  = idx & 3;            // 16B chunk (8 bf16)
            uint32_t so = (uint32_t)(row * MG_PAD + ch * 8) * 2;
            size_t ao = (size_t)(brow * 128 + row) * K + k0 + ch * 8;
            size_t bo = (size_t)(bcol * 128 + row) * K + k0 + ch * 8;
            *(uint4*)((char*)sAh + so) = *(const uint4*)(Ahi + ao);
            *(uint4*)((char*)sAl + so) = *(const uint4*)(Alo + ao);
            *(uint4*)((char*)sBh + so) = *(const uint4*)(Bhi + bo);
            *(uint4*)((char*)sBl + so) = *(const uint4*)(Blo + bo);
        }
        __syncthreads();

        #pragma unroll
        for (int ks = 0; ks < 2; ks++) {
            int kk = ks * 16;
            uint32_t ah[2][4], al[2][4];
            #pragma unroll
            for (int t = 0; t < 2; t++) {
                uint32_t off = (uint32_t)((warp_m + t * 16 + (lane & 15)) * MG_PAD
                             + kk + ((lane >> 4) << 3)) * 2;
                LDSM4(ah[t], sa_h + off);
                LDSM4(al[t], sa_l + off);
            }
            uint32_t bh[8][2], bl[8][2];
            #pragma unroll
            for (int p = 0; p < 4; p++) {
                uint32_t off = (uint32_t)((warp_n + p * 16 + ((lane >> 3) & 1) * 8 + (lane & 7)) * MG_PAD
                             + kk + ((lane >> 4) << 3)) * 2;
                uint32_t r[4];
                LDSM4(r, sb_h + off);
                bh[2*p][0] = r[0]; bh[2*p][1] = r[2];
                bh[2*p+1][0] = r[1]; bh[2*p+1][1] = r[3];
                LDSM4(r, sb_l + off);
                bl[2*p][0] = r[0]; bl[2*p][1] = r[2];
                bl[2*p+1][0] = r[1]; bl[2*p+1][1] = r[3];
            }
            #pragma unroll
            for (int t = 0; t < 2; t++)
                #pragma unroll
                for (int nt = 0; nt < 8; nt++) {
                    mma_bf16(acc[t][nt], ah[t], bh[nt]);
                    mma_bf16(acc[t][nt], ah[t], bl[nt]);
                    mma_bf16(acc[t][nt], al[t], bh[nt]);
                }
        }
    }

    // epilogue: acc layout — lane l: rows l/4, l/4+8; cols (l%4)*2, +1 within n8 tile
    int r0 = lane >> 2, c0 = (lane & 3) * 2;
    #pragma unroll
    for (int t = 0; t < 2; t++) {
        #pragma unroll
        for (int half = 0; half < 2; half++) {
            int grow = brow * 128 + warp_m + t * 16 + r0 + half * 8;
            #pragma unroll
            for (int nt = 0; nt < 8; nt++) {
                int gcol = bcol * 128 + warp_n + nt * 8 + c0;
                float2 o;
                o.x = acc[t][nt][half * 2 + 0] + bias[gcol];
                o.y = acc[t][nt][half * 2 + 1] + bias[gcol + 1];
                if (res) {
                    float2 rv = *(const float2*)(res + (size_t)grow * N + gcol);
                    o.x += rv.x; o.y += rv.y;
                }
                *(float2*)(C + (size_t)grow * N + gcol) = o;
            }
        }
    }
}

// ---------------- activation split: fp32 -> bf16 hi + bf16 lo ----------------
__global__ void conv_act_kernel(const float* __restrict__ X,
                                __nv_bfloat16* __restrict__ hi,
                                __nv_bfloat16* __restrict__ lo, int n4)
{
    int idx = blockIdx.x * blockDim.x + threadIdx.x;
    if (idx >= n4) return;
    float4 v = ((const float4*)X)[idx];
    __nv_bfloat16 h0 = __float2bfloat16_rn(v.x);
    __nv_bfloat16 h1 = __float2bfloat16_rn(v.y);
    __nv_bfloat16 h2 = __float2bfloat16_rn(v.z);
    __nv_bfloat16 h3 = __float2bfloat16_rn(v.w);
    __nv_bfloat16 l0 = __float2bfloat16_rn(v.x - __bfloat162float(h0));
    __nv_bfloat16 l1 = __float2bfloat16_rn(v.y - __bfloat162float(h1));
    __nv_bfloat16 l2 = __float2bfloat16_rn(v.z - __bfloat162float(h2));
    __nv_bfloat16 l3 = __float2bfloat16_rn(v.w - __bfloat162float(h3));
    __nv_bfloat162* hp = (__nv_bfloat162*)(hi + idx * 4);
    __nv_bfloat162* lp = (__nv_bfloat162*)(lo + idx * 4);
    hp[0] = __nv_bfloat162(h0, h1); hp[1] = __nv_bfloat162(h2, h3);
    lp[0] = __nv_bfloat162(l0, l1); lp[1] = __nv_bfloat162(l2, l3);
}

// ---------------- weight transpose+split: W[K,N] fp32 -> Wt_hi/lo[N,K] bf16 ----------------
__global__ __launch_bounds__(256) void conv_wt_kernel(
    const float* __restrict__ W, __nv_bfloat16* __restrict__ Thi,
    __nv_bfloat16* __restrict__ Tlo, int K, int N)
{
    __shared__ __nv_bfloat16 shi[32][33];
    __shared__ __nv_bfloat16 slo[32][33];
    int tx = threadIdx.x & 31, ty = threadIdx.x >> 5;   // 32 x 8
    int n0 = blockIdx.x * 32, k0 = blockIdx.y * 32;
    #pragma unroll
    for (int j = 0; j < 4; j++) {
        int k = ty + j * 8;
        float v = W[(size_t)(k0 + k) * N + n0 + tx];
        __nv_bfloat16 h = __float2bfloat16_rn(v);
        shi[k][tx] = h;
        slo[k][tx] = __float2bfloat16_rn(v - __bfloat162float(h));
    }
    __syncthreads();
    #pragma unroll
    for (int j = 0; j < 4; j++) {
        int n = ty + j * 8;
        Thi[(size_t)(n0 + n) * K + k0 + tx] = shi[tx][n];
        Tlo[(size_t)(n0 + n) * K + k0 + tx] = slo[tx][n];
    }
}

// ---------------- LayerNorm: one block per row of 512 ----------------
__global__ __launch_bounds__(128) void ln_kernel(
    const float* __restrict__ X, const float* __restrict__ w,
    const float* __restrict__ bb, float* __restrict__ Y)
{
    int row = blockIdx.x;
    int tid = threadIdx.x;
    const float* xp = X + (size_t)row * DIM;
    float4 v = *(const float4*)(xp + tid * 4);
    float s  = v.x + v.y + v.z + v.w;
    float sq = v.x*v.x + v.y*v.y + v.z*v.z + v.w*v.w;
    #pragma unroll
    for (int o = 16; o > 0; o >>= 1) {
        s  += __shfl_xor_sync(0xffffffffu, s,  o);
        sq += __shfl_xor_sync(0xffffffffu, sq, o);
    }
    __shared__ float reds[4], redq[4];
    int wid = tid >> 5, lane = tid & 31;
    if (lane == 0) { reds[wid] = s; redq[wid] = sq; }
    __syncthreads();
    s  = reds[0] + reds[1] + reds[2] + reds[3];
    sq = redq[0] + redq[1] + redq[2] + redq[3];
    float mu   = s * (1.0f / DIM);
    float var  = sq * (1.0f / DIM) - mu * mu;
    float rstd = rsqrtf(var + 1e-5f);
    float4 wv = *(const float4*)(w  + tid * 4);
    float4 bv = *(const float4*)(bb + tid * 4);
    float4 out;
    out.x = (v.x - mu) * rstd * wv.x + bv.x;
    out.y = (v.y - mu) * rstd * wv.y + bv.y;
    out.z = (v.z - mu) * rstd * wv.z + bv.z;
    out.w = (v.w - mu) * rstd * wv.w + bv.w;
    *(float4*)(Y + (size_t)row * DIM + tid * 4) = out;
}

// ---------------- AA_j = |q_j|^2 per (b,h,n) ----------------
__global__ void aa_kernel(const float* __restrict__ Q, float* __restrict__ AA)
{
    int idx = blockIdx.x * blockDim.x + threadIdx.x;  // row*8 + h
    if (idx >= ROWS * NHEAD) return;
    int h = idx & 7;
    int row = idx >> 3;
    const float* qp = Q + (size_t)row * DIM + h * DHEAD;
    float s = 0.0f;
    #pragma unroll
    for (int i = 0; i < 16; i++) {
        float4 v = *(const float4*)(qp + i * 4);
        s += v.x*v.x + v.y*v.y + v.z*v.z + v.w*v.w;
    }
    int b = row >> 11, n = row & 2047;
    AA[((size_t)(b * NHEAD + h)) * NSEQ + n] = s;
}

// ---------------- Flash L2-distance attention (scalar fp32) ----------------
#define FA_BQ 64
#define FA_BK 64
__global__ __launch_bounds__(128) void flash_l2_kernel(
    const float* __restrict__ Q, const float* __restrict__ V,
    const float* __restrict__ AA, float* __restrict__ O)
{
    __shared__ float ks[FA_BK][DHEAD];
    __shared__ float vs[FA_BK][DHEAD];
    __shared__ float aas[FA_BK];

    int b = blockIdx.z, h = blockIdx.y;
    int q0 = blockIdx.x * FA_BQ;
    int tid = threadIdx.x;
    int r   = tid >> 1;
    int par = tid & 1;
    int row = b * NSEQ + q0 + r;

    const float* qrow = Q + (size_t)row * DIM + h * DHEAD + par * 32;
    float4 qr[8];
    #pragma unroll
    for (int i = 0; i < 8; i++) qr[i] = *(const float4*)(qrow + i * 4);

    float m = -1e30f, l = 0.0f;
    float o[32];
    #pragma unroll
    for (int i = 0; i < 32; i++) o[i] = 0.0f;

    const float scale = 0.125f;
    const float* aab = AA + ((size_t)(b * NHEAD + h)) * NSEQ;

    for (int kt = 0; kt < NSEQ; kt += FA_BK) {
        __syncthreads();
        for (int idx = tid; idx < FA_BK * 16; idx += 128) {
            int kr = idx >> 4, c4 = (idx & 15) * 4;
            size_t goff = (size_t)(b * NSEQ + kt + kr) * DIM + h * DHEAD + c4;
            *(float4*)&ks[kr][c4] = *(const float4*)(Q + goff);
            *(float4*)&vs[kr][c4] = *(const float4*)(V + goff);
        }
        if (tid < FA_BK) aas[tid] = aab[kt + tid];
        __syncthreads();

        #pragma unroll 2
        for (int j = 0; j < FA_BK; j++) {
            float s = 0.0f;
            const float4* kp = (const float4*)&ks[j][par * 32];
            #pragma unroll
            for (int i = 0; i < 8; i++) {
                float4 kv = kp[i];
                s += qr[i].x*kv.x + qr[i].y*kv.y + qr[i].z*kv.z + qr[i].w*kv.w;
            }
            s += __shfl_xor_sync(0xffffffffu, s, 1);
            s = 2.0f * scale * s - scale * aas[j];
            if (s > m) {
                float c = __expf(m - s);
                l *= c;
                #pragma unroll
                for (int i = 0; i < 32; i++) o[i] *= c;
                m = s;
            }
            float p = __expf(s - m);
            l += p;
            const float4* vp = (const float4*)&vs[j][par * 32];
            #pragma unroll
            for (int i = 0; i < 8; i++) {
                float4 vv = vp[i];
                o[i*4+0] += p * vv.x;
                o[i*4+1] += p * vv.y;
                o[i*4+2] += p * vv.z;
                o[i*4+3] += p * vv.w;
            }
        }
    }

    float inv = 1.0f / l;
    float* orow = O + (size_t)row * DIM + h * DHEAD + par * 32;
    #pragma unroll
    for (int i = 0; i < 8; i++) {
        float4 ov;
        ov.x = o[i*4+0] * inv;
        ov.y = o[i*4+1] * inv;
        ov.z = o[i*4+2] * inv;
        ov.w = o[i*4+3] * inv;
        *(float4*)(orow + i * 4) = ov;
    }
}

// ---------------- GEGLU activation ----------------
__device__ __forceinline__ float gelu_exact(float x) {
    return 0.5f * x * (1.0f + erff(x * 0.70710678118654752f));
}
__global__ void geglu_kernel(const float* __restrict__ H, float* __restrict__ G)
{
    int idx = blockIdx.x * blockDim.x + threadIdx.x;
    if (idx >= ROWS * (IFF / 4)) return;
    int row = idx / (IFF / 4);
    int c4  = idx % (IFF / 4);
    const float* base = H + (size_t)row * (2 * IFF);
    float4 a  = *(const float4*)(base + c4 * 4);
    float4 gt = *(const float4*)(base + IFF + c4 * 4);
    float4 r;
    r.x = a.x * gelu_exact(gt.x);
    r.y = a.y * gelu_exact(gt.y);
    r.z = a.z * gelu_exact(gt.z);
    r.w = a.w * gelu_exact(gt.w);
    *(float4*)(G + (size_t)row * IFF + c4 * 4) = r;
}

// ---------------- host orchestration ----------------
struct Bufs {
    float *xn, *q, *v, *att, *x1, *x2, *aa, *hh, *gg;
    __nv_bfloat16 *ahi, *alo, *whi, *wlo;
};

static void conv_act(const float* X, __nv_bfloat16* hi, __nv_bfloat16* lo, int n) {
    int n4 = n / 4;
    conv_act_kernel<<<(n4 + 255) / 256, 256>>>(X, hi, lo, n4);
}
static void conv_wt(const float* W, __nv_bfloat16* hi, __nv_bfloat16* lo, int K, int N) {
    dim3 grid(N / 32, K / 32);
    conv_wt_kernel<<<grid, 256>>>(W, hi, lo, K, N);
}
static void tc_gemm(const Bufs& B, const float* bias, const float* res,
                    float* C, int M, int N, int K) {
    dim3 grid(N / 128, M / 128);
    mma_gemm_kernel<<<grid, 256>>>(B.ahi, B.alo, B.whi, B.wlo, bias, res, C, M, N, K);
}

extern "C" void kernel_launch(void* const* d_in, const int* in_sizes, int n_in,
                              void* d_out, int out_size)
{
    const float* x     = (const float*)d_in[0];
    const float* sa_w  = (const float*)d_in[1];
    const float* sa_b  = (const float*)d_in[2];
    const float* ca_w  = (const float*)d_in[3];
    const float* ca_b  = (const float*)d_in[4];
    const float* ff_nw = (const float*)d_in[5];
    const float* ff_nb = (const float*)d_in[6];
    const float* a1_wq = (const float*)d_in[7];
    const float* a1_bq = (const float*)d_in[8];
    const float* a1_wv = (const float*)d_in[9];
    const float* a1_bv = (const float*)d_in[10];
    const float* a1_wo = (const float*)d_in[11];
    const float* a1_bo = (const float*)d_in[12];
    const float* a2_wq = (const float*)d_in[13];
    const float* a2_bq = (const float*)d_in[14];
    const float* a2_wv = (const float*)d_in[15];
    const float* a2_bv = (const float*)d_in[16];
    const float* a2_wo = (const float*)d_in[17];
    const float* a2_bo = (const float*)d_in[18];
    const float* ff_w1 = (const float*)d_in[19];
    const float* ff_b1 = (const float*)d_in[20];
    const float* ff_w2 = (const float*)d_in[21];
    const float* ff_b2 = (const float*)d_in[22];
    float* out = (float*)d_out;

    Bufs B;
    cudaGetSymbolAddress((void**)&B.xn,  g_xn);
    cudaGetSymbolAddress((void**)&B.q,   g_q);
    cudaGetSymbolAddress((void**)&B.v,   g_v);
    cudaGetSymbolAddress((void**)&B.att, g_att);
    cudaGetSymbolAddress((void**)&B.x1,  g_x1);
    cudaGetSymbolAddress((void**)&B.x2,  g_x2);
    cudaGetSymbolAddress((void**)&B.aa,  g_aa);
    cudaGetSymbolAddress((void**)&B.hh,  g_h);
    cudaGetSymbolAddress((void**)&B.gg,  g_g);
    cudaGetSymbolAddress((void**)&B.ahi, g_ahi);
    cudaGetSymbolAddress((void**)&B.alo, g_alo);
    cudaGetSymbolAddress((void**)&B.whi, g_whi);
    cudaGetSymbolAddress((void**)&B.wlo, g_wlo);

    dim3 fa_grid(NSEQ / FA_BQ, NHEAD, NBATCH);
    int aa_blocks = (ROWS * NHEAD + 255) / 256;

    // ---- self-attention (attn1) ----
    ln_kernel<<<ROWS, 128>>>(x, sa_w, sa_b, B.xn);
    conv_act(B.xn, B.ahi, B.alo, ROWS * DIM);
    conv_wt(a1_wq, B.whi, B.wlo, DIM, DIM);
    tc_gemm(B, a1_bq, nullptr, B.q, ROWS, DIM, DIM);
    conv_wt(a1_wv, B.whi, B.wlo, DIM, DIM);
    tc_gemm(B, a1_bv, nullptr, B.v, ROWS, DIM, DIM);
    aa_kernel<<<aa_blocks, 256>>>(B.q, B.aa);
    flash_l2_kernel<<<fa_grid, 128>>>(B.q, B.v, B.aa, B.att);
    conv_act(B.att, B.ahi, B.alo, ROWS * DIM);
    conv_wt(a1_wo, B.whi, B.wlo, DIM, DIM);
    tc_gemm(B, a1_bo, x, B.x1, ROWS, DIM, DIM);

    // ---- attn2 (k=q, v from x) ----
    ln_kernel<<<ROWS, 128>>>(B.x1, ca_w, ca_b, B.xn);
    conv_act(B.xn, B.ahi, B.alo, ROWS * DIM);
    conv_wt(a2_wq, B.whi, B.wlo, DIM, DIM);
    tc_gemm(B, a2_bq, nullptr, B.q, ROWS, DIM, DIM);
    conv_wt(a2_wv, B.whi, B.wlo, DIM, DIM);
    tc_gemm(B, a2_bv, nullptr, B.v, ROWS, DIM, DIM);
    aa_kernel<<<aa_blocks, 256>>>(B.q, B.aa);
    flash_l2_kernel<<<fa_grid, 128>>>(B.q, B.v, B.aa, B.att);
    conv_act(B.att, B.ahi, B.alo, ROWS * DIM);
    conv_wt(a2_wo, B.whi, B.wlo, DIM, DIM);
    tc_gemm(B, a2_bo, B.x1, B.x2, ROWS, DIM, DIM);

    // ---- GEGLU FFN ----
    ln_kernel<<<ROWS, 128>>>(B.x2, ff_nw, ff_nb, B.xn);
    conv_act(B.xn, B.ahi, B.alo, ROWS * DIM);
    conv_wt(ff_w1, B.whi, B.wlo, DIM, 2 * IFF);
    tc_gemm(B, ff_b1, nullptr, B.hh, ROWS, 2 * IFF, DIM);
    int ge_blocks = (ROWS * (IFF / 4) + 255) / 256;
    geglu_kernel<<<ge_blocks, 256>>>(B.hh, B.gg);
    conv_act(B.gg, B.ahi, B.alo, ROWS * IFF);
    conv_wt(ff_w2, B.whi, B.wlo, IFF, DIM);
    tc_gemm(B, ff_b2, B.x2, out, ROWS, DIM, IFF);
}

// round 5
// speedup vs baseline: 3.7007x; 3.2099x over previous
#include <cuda_runtime.h>
#include <cuda_bf16.h>
#include <cstdint>
#include <math.h>

#define ROWS 8192
#define DIM  512
#define NSEQ 2048
#define NBATCH 4
#define NHEAD 8
#define DHEAD 64
#define IFF  2048

// ---------------- scratch (static device globals; no allocations) ----------------
__device__ float g_xn [ROWS * DIM];
__device__ float g_q  [ROWS * DIM];
__device__ float g_v  [ROWS * DIM];
__device__ float g_att[ROWS * DIM];
__device__ float g_x1 [ROWS * DIM];
__device__ float g_x2 [ROWS * DIM];
__device__ float g_aa [NBATCH * NHEAD * NSEQ];
__device__ float g_h  [ROWS * 2 * IFF];
__device__ float g_g  [ROWS * IFF];
// bf16 hi/lo split buffers (GEMM)
__device__ __nv_bfloat16 g_ahi[ROWS * IFF];
__device__ __nv_bfloat16 g_alo[ROWS * IFF];
__device__ __nv_bfloat16 g_whi[4096 * 512];
__device__ __nv_bfloat16 g_wlo[4096 * 512];
// bf16 Q/V for flash attention
__device__ __nv_bfloat16 g_qb[ROWS * DIM];
__device__ __nv_bfloat16 g_vb[ROWS * DIM];

// =================== helpers ===================
__device__ __forceinline__ uint32_t smem_u32(const void* p) {
    uint32_t a;
    asm("{ .reg .u64 t; cvta.to.shared.u64 t, %1; cvt.u32.u64 %0, t; }" : "=r"(a) : "l"(p));
    return a;
}
#define LDSM4(r, addr) \
    asm volatile("ldmatrix.sync.aligned.m8n8.x4.shared.b16 {%0,%1,%2,%3}, [%4];" \
        : "=r"((r)[0]), "=r"((r)[1]), "=r"((r)[2]), "=r"((r)[3]) : "r"(addr))
#define LDSM4T(r, addr) \
    asm volatile("ldmatrix.sync.aligned.m8n8.x4.trans.shared.b16 {%0,%1,%2,%3}, [%4];" \
        : "=r"((r)[0]), "=r"((r)[1]), "=r"((r)[2]), "=r"((r)[3]) : "r"(addr))

__device__ __forceinline__ void mma_bf16(float* d, const uint32_t* a, const uint32_t* b) {
    asm volatile("mma.sync.aligned.m16n8k16.row.col.f32.bf16.bf16.f32 "
        "{%0,%1,%2,%3}, {%4,%5,%6,%7}, {%8,%9}, {%0,%1,%2,%3};"
        : "+f"(d[0]), "+f"(d[1]), "+f"(d[2]), "+f"(d[3])
        : "r"(a[0]), "r"(a[1]), "r"(a[2]), "r"(a[3]), "r"(b[0]), "r"(b[1]));
}

// =================== HMMA GEMM (unchanged from R4, passing) ===================
#define MG_PAD 40

__global__ __launch_bounds__(256, 1) void mma_gemm_kernel(
    const __nv_bfloat16* __restrict__ Ahi, const __nv_bfloat16* __restrict__ Alo,
    const __nv_bfloat16* __restrict__ Bhi, const __nv_bfloat16* __restrict__ Blo,
    const float* __restrict__ bias, const float* __restrict__ res,
    float* __restrict__ C, int M, int N, int K)
{
    __shared__ __nv_bfloat16 sAh[128 * MG_PAD], sAl[128 * MG_PAD];
    __shared__ __nv_bfloat16 sBh[128 * MG_PAD], sBl[128 * MG_PAD];

    int tid = threadIdx.x, lane = tid & 31, wid = tid >> 5;
    int brow = blockIdx.y, bcol = blockIdx.x;
    int warp_m = (wid >> 1) * 32;
    int warp_n = (wid & 1) * 64;

    float acc[2][8][4];
    #pragma unroll
    for (int t = 0; t < 2; t++)
        #pragma unroll
        for (int nt = 0; nt < 8; nt++)
            #pragma unroll
            for (int j = 0; j < 4; j++) acc[t][nt][j] = 0.0f;

    uint32_t sa_h = smem_u32(sAh), sa_l = smem_u32(sAl);
    uint32_t sb_h = smem_u32(sBh), sb_l = smem_u32(sBl);

    for (int k0 = 0; k0 < K; k0 += 32) {
        __syncthreads();
        #pragma unroll
        for (int it = 0; it < 2; it++) {
            int idx = tid + it * 256;
            int row = idx >> 2;
            int ch  = idx & 3;
            uint32_t so = (uint32_t)(row * MG_PAD + ch * 8) * 2;
            size_t ao = (size_t)(brow * 128 + row) * K + k0 + ch * 8;
            size_t bo = (size_t)(bcol * 128 + row) * K + k0 + ch * 8;
            *(uint4*)((char*)sAh + so) = *(const uint4*)(Ahi + ao);
            *(uint4*)((char*)sAl + so) = *(const uint4*)(Alo + ao);
            *(uint4*)((char*)sBh + so) = *(const uint4*)(Bhi + bo);
            *(uint4*)((char*)sBl + so) = *(const uint4*)(Blo + bo);
        }
        __syncthreads();

        #pragma unroll
        for (int ks = 0; ks < 2; ks++) {
            int kk = ks * 16;
            uint32_t ah[2][4], al[2][4];
            #pragma unroll
            for (int t = 0; t < 2; t++) {
                uint32_t off = (uint32_t)((warp_m + t * 16 + (lane & 15)) * MG_PAD
                             + kk + ((lane >> 4) << 3)) * 2;
                LDSM4(ah[t], sa_h + off);
                LDSM4(al[t], sa_l + off);
            }
            uint32_t bh[8][2], bl[8][2];
            #pragma unroll
            for (int p = 0; p < 4; p++) {
                uint32_t off = (uint32_t)((warp_n + p * 16 + ((lane >> 3) & 1) * 8 + (lane & 7)) * MG_PAD
                             + kk + ((lane >> 4) << 3)) * 2;
                uint32_t r[4];
                LDSM4(r, sb_h + off);
                bh[2*p][0] = r[0]; bh[2*p][1] = r[2];
                bh[2*p+1][0] = r[1]; bh[2*p+1][1] = r[3];
                LDSM4(r, sb_l + off);
                bl[2*p][0] = r[0]; bl[2*p][1] = r[2];
                bl[2*p+1][0] = r[1]; bl[2*p+1][1] = r[3];
            }
            #pragma unroll
            for (int t = 0; t < 2; t++)
                #pragma unroll
                for (int nt = 0; nt < 8; nt++) {
                    mma_bf16(acc[t][nt], ah[t], bh[nt]);
                    mma_bf16(acc[t][nt], ah[t], bl[nt]);
                    mma_bf16(acc[t][nt], al[t], bh[nt]);
                }
        }
    }

    int r0 = lane >> 2, c0 = (lane & 3) * 2;
    #pragma unroll
    for (int t = 0; t < 2; t++) {
        #pragma unroll
        for (int half = 0; half < 2; half++) {
            int grow = brow * 128 + warp_m + t * 16 + r0 + half * 8;
            #pragma unroll
            for (int nt = 0; nt < 8; nt++) {
                int gcol = bcol * 128 + warp_n + nt * 8 + c0;
                float2 o;
                o.x = acc[t][nt][half * 2 + 0] + bias[gcol];
                o.y = acc[t][nt][half * 2 + 1] + bias[gcol + 1];
                if (res) {
                    float2 rv = *(const float2*)(res + (size_t)grow * N + gcol);
                    o.x += rv.x; o.y += rv.y;
                }
                *(float2*)(C + (size_t)grow * N + gcol) = o;
            }
        }
    }
}

// =================== HMMA flash attention (L2-distance softmax) ===================
// logits = 0.25*(q_i.q_j) - 0.125*|q_j|^2  (row-constant term dropped)
#define FB_BQ 64
#define FB_BK 64
#define FB_PAD 72

__global__ __launch_bounds__(128) void flash_mma_kernel(
    const __nv_bfloat16* __restrict__ Qb, const __nv_bfloat16* __restrict__ Vb,
    const float* __restrict__ AA, float* __restrict__ O)
{
    __shared__ __nv_bfloat16 sQ[FB_BQ * FB_PAD];
    __shared__ __nv_bfloat16 sK[FB_BK * FB_PAD];
    __shared__ __nv_bfloat16 sV[FB_BK * FB_PAD];
    __shared__ float sAA[FB_BK];

    int b = blockIdx.z, h = blockIdx.y;
    int q0 = blockIdx.x * FB_BQ;
    int tid = threadIdx.x, lane = tid & 31, w = tid >> 5;

    uint32_t sq_a = smem_u32(sQ), sk_a = smem_u32(sK), sv_a = smem_u32(sV);

    // load Q tile (64 rows x 64 bf16)
    #pragma unroll
    for (int i = 0; i < 4; i++) {
        int idx = tid + i * 128;
        int r = idx >> 3, c = idx & 7;
        size_t off = (size_t)(b * NSEQ + q0 + r) * DIM + h * DHEAD + c * 8;
        *(uint4*)&sQ[r * FB_PAD + c * 8] = *(const uint4*)(Qb + off);
    }
    __syncthreads();

    // Q fragments: warp's m16 rows, 4 k16-steps
    uint32_t qa[4][4];
    #pragma unroll
    for (int ks = 0; ks < 4; ks++) {
        uint32_t off = (uint32_t)((w * 16 + (lane & 15)) * FB_PAD + ks * 16 + ((lane >> 4) << 3)) * 2;
        LDSM4(qa[ks], sq_a + off);
    }

    float m0 = -1e30f, m1 = -1e30f, l0 = 0.0f, l1 = 0.0f;
    float o[8][4];
    #pragma unroll
    for (int t = 0; t < 8; t++)
        #pragma unroll
        for (int j = 0; j < 4; j++) o[t][j] = 0.0f;

    const float* aab = AA + ((size_t)(b * NHEAD + h)) * NSEQ;

    for (int kt = 0; kt < NSEQ; kt += FB_BK) {
        __syncthreads();
        #pragma unroll
        for (int i = 0; i < 4; i++) {
            int idx = tid + i * 128;
            int r = idx >> 3, c = idx & 7;
            size_t off = (size_t)(b * NSEQ + kt + r) * DIM + h * DHEAD + c * 8;
            *(uint4*)&sK[r * FB_PAD + c * 8] = *(const uint4*)(Qb + off);
            *(uint4*)&sV[r * FB_PAD + c * 8] = *(const uint4*)(Vb + off);
        }
        if (tid < FB_BK) sAA[tid] = aab[kt + tid];
        __syncthreads();

        // S = Q @ K^T   (8 n8-tiles over keys)
        float sc[8][4];
        #pragma unroll
        for (int t = 0; t < 8; t++)
            #pragma unroll
            for (int j = 0; j < 4; j++) sc[t][j] = 0.0f;

        #pragma unroll
        for (int ks = 0; ks < 4; ks++) {
            uint32_t kb[8][2];
            #pragma unroll
            for (int p = 0; p < 4; p++) {
                uint32_t off = (uint32_t)((p * 16 + ((lane >> 3) & 1) * 8 + (lane & 7)) * FB_PAD
                             + ks * 16 + ((lane >> 4) << 3)) * 2;
                uint32_t r[4];
                LDSM4(r, sk_a + off);
                kb[2*p][0] = r[0]; kb[2*p][1] = r[2];
                kb[2*p+1][0] = r[1]; kb[2*p+1][1] = r[3];
            }
            #pragma unroll
            for (int t = 0; t < 8; t++) mma_bf16(sc[t], qa[ks], kb[t]);
        }

        // bias + row max
        float mt0 = -1e30f, mt1 = -1e30f;
        #pragma unroll
        for (int t = 0; t < 8; t++) {
            float a0 = sAA[t * 8 + (lane & 3) * 2];
            float a1 = sAA[t * 8 + (lane & 3) * 2 + 1];
            sc[t][0] = 0.25f * sc[t][0] - 0.125f * a0;
            sc[t][1] = 0.25f * sc[t][1] - 0.125f * a1;
            sc[t][2] = 0.25f * sc[t][2] - 0.125f * a0;
            sc[t][3] = 0.25f * sc[t][3] - 0.125f * a1;
            mt0 = fmaxf(mt0, fmaxf(sc[t][0], sc[t][1]));
            mt1 = fmaxf(mt1, fmaxf(sc[t][2], sc[t][3]));
        }
        mt0 = fmaxf(mt0, __shfl_xor_sync(0xffffffffu, mt0, 1));
        mt0 = fmaxf(mt0, __shfl_xor_sync(0xffffffffu, mt0, 2));
        mt1 = fmaxf(mt1, __shfl_xor_sync(0xffffffffu, mt1, 1));
        mt1 = fmaxf(mt1, __shfl_xor_sync(0xffffffffu, mt1, 2));

        float mn0 = fmaxf(m0, mt0), mn1 = fmaxf(m1, mt1);
        float al0 = __expf(m0 - mn0), al1 = __expf(m1 - mn1);
        m0 = mn0; m1 = mn1;
        l0 *= al0; l1 *= al1;
        #pragma unroll
        for (int t = 0; t < 8; t++) {
            o[t][0] *= al0; o[t][1] *= al0;
            o[t][2] *= al1; o[t][3] *= al1;
        }

        // P = exp(S - m) in place; accumulate row sums
        #pragma unroll
        for (int t = 0; t < 8; t++) {
            sc[t][0] = __expf(sc[t][0] - m0);
            sc[t][1] = __expf(sc[t][1] - m0);
            sc[t][2] = __expf(sc[t][2] - m1);
            sc[t][3] = __expf(sc[t][3] - m1);
            l0 += sc[t][0] + sc[t][1];
            l1 += sc[t][2] + sc[t][3];
        }

        // O += P @ V   (k over 64 keys, n over 64 head dims)
        #pragma unroll
        for (int j = 0; j < 4; j++) {
            uint32_t pa[4];
            __nv_bfloat162 t2;
            t2 = __floats2bfloat162_rn(sc[2*j][0],   sc[2*j][1]);   pa[0] = *(uint32_t*)&t2;
            t2 = __floats2bfloat162_rn(sc[2*j][2],   sc[2*j][3]);   pa[1] = *(uint32_t*)&t2;
            t2 = __floats2bfloat162_rn(sc[2*j+1][0], sc[2*j+1][1]); pa[2] = *(uint32_t*)&t2;
            t2 = __floats2bfloat162_rn(sc[2*j+1][2], sc[2*j+1][3]); pa[3] = *(uint32_t*)&t2;

            uint32_t vb[8][2];
            #pragma unroll
            for (int dp = 0; dp < 4; dp++) {
                int g = lane >> 3, rr = lane & 7;
                uint32_t off = (uint32_t)((j * 16 + (g & 1) * 8 + rr) * FB_PAD
                             + dp * 16 + (g >> 1) * 8) * 2;
                uint32_t r[4];
                LDSM4T(r, sv_a + off);
                vb[2*dp][0]   = r[0]; vb[2*dp][1]   = r[1];
                vb[2*dp+1][0] = r[2]; vb[2*dp+1][1] = r[3];
            }
            #pragma unroll
            for (int t = 0; t < 8; t++) mma_bf16(o[t], pa, vb[t]);
        }
    }

    l0 += __shfl_xor_sync(0xffffffffu, l0, 1);
    l0 += __shfl_xor_sync(0xffffffffu, l0, 2);
    l1 += __shfl_xor_sync(0xffffffffu, l1, 1);
    l1 += __shfl_xor_sync(0xffffffffu, l1, 2);
    float inv0 = 1.0f / l0, inv1 = 1.0f / l1;

    int r0g = q0 + w * 16 + (lane >> 2);
    #pragma unroll
    for (int t = 0; t < 8; t++) {
        int c = h * DHEAD + t * 8 + (lane & 3) * 2;
        float2 o0; o0.x = o[t][0] * inv0; o0.y = o[t][1] * inv0;
        float2 o1; o1.x = o[t][2] * inv1; o1.y = o[t][3] * inv1;
        *(float2*)(O + (size_t)(b * NSEQ + r0g) * DIM + c) = o0;
        *(float2*)(O + (size_t)(b * NSEQ + r0g + 8) * DIM + c) = o1;
    }
}

// ---------------- conversions ----------------
__global__ void conv_act_kernel(const float* __restrict__ X,
                                __nv_bfloat16* __restrict__ hi,
                                __nv_bfloat16* __restrict__ lo, int n4)
{
    int idx = blockIdx.x * blockDim.x + threadIdx.x;
    if (idx >= n4) return;
    float4 v = ((const float4*)X)[idx];
    __nv_bfloat16 h0 = __float2bfloat16_rn(v.x);
    __nv_bfloat16 h1 = __float2bfloat16_rn(v.y);
    __nv_bfloat16 h2 = __float2bfloat16_rn(v.z);
    __nv_bfloat16 h3 = __float2bfloat16_rn(v.w);
    __nv_bfloat16 l0 = __float2bfloat16_rn(v.x - __bfloat162float(h0));
    __nv_bfloat16 l1 = __float2bfloat16_rn(v.y - __bfloat162float(h1));
    __nv_bfloat16 l2 = __float2bfloat16_rn(v.z - __bfloat162float(h2));
    __nv_bfloat16 l3 = __float2bfloat16_rn(v.w - __bfloat162float(h3));
    __nv_bfloat162* hp = (__nv_bfloat162*)(hi + idx * 4);
    __nv_bfloat162* lp = (__nv_bfloat162*)(lo + idx * 4);
    hp[0] = __nv_bfloat162(h0, h1); hp[1] = __nv_bfloat162(h2, h3);
    lp[0] = __nv_bfloat162(l0, l1); lp[1] = __nv_bfloat162(l2, l3);
}

__global__ void conv_b16_kernel(const float* __restrict__ X,
                                __nv_bfloat16* __restrict__ Y, int n4)
{
    int idx = blockIdx.x * blockDim.x + threadIdx.x;
    if (idx >= n4) return;
    float4 v = ((const float4*)X)[idx];
    __nv_bfloat162* yp = (__nv_bfloat162*)(Y + idx * 4);
    yp[0] = __nv_bfloat162(__float2bfloat16_rn(v.x), __float2bfloat16_rn(v.y));
    yp[1] = __nv_bfloat162(__float2bfloat16_rn(v.z), __float2bfloat16_rn(v.w));
}

__global__ __launch_bounds__(256) void conv_wt_kernel(
    const float* __restrict__ W, __nv_bfloat16* __restrict__ Thi,
    __nv_bfloat16* __restrict__ Tlo, int K, int N)
{
    __shared__ __nv_bfloat16 shi[32][33];
    __shared__ __nv_bfloat16 slo[32][33];
    int tx = threadIdx.x & 31, ty = threadIdx.x >> 5;
    int n0 = blockIdx.x * 32, k0 = blockIdx.y * 32;
    #pragma unroll
    for (int j = 0; j < 4; j++) {
        int k = ty + j * 8;
        float v = W[(size_t)(k0 + k) * N + n0 + tx];
        __nv_bfloat16 h = __float2bfloat16_rn(v);
        shi[k][tx] = h;
        slo[k][tx] = __float2bfloat16_rn(v - __bfloat162float(h));
    }
    __syncthreads();
    #pragma unroll
    for (int j = 0; j < 4; j++) {
        int n = ty + j * 8;
        Thi[(size_t)(n0 + n) * K + k0 + tx] = shi[tx][n];
        Tlo[(size_t)(n0 + n) * K + k0 + tx] = slo[tx][n];
    }
}

// ---------------- LayerNorm ----------------
__global__ __launch_bounds__(128) void ln_kernel(
    const float* __restrict__ X, const float* __restrict__ w,
    const float* __restrict__ bb, float* __restrict__ Y)
{
    int row = blockIdx.x;
    int tid = threadIdx.x;
    const float* xp = X + (size_t)row * DIM;
    float4 v = *(const float4*)(xp + tid * 4);
    float s  = v.x + v.y + v.z + v.w;
    float sq = v.x*v.x + v.y*v.y + v.z*v.z + v.w*v.w;
    #pragma unroll
    for (int o = 16; o > 0; o >>= 1) {
        s  += __shfl_xor_sync(0xffffffffu, s,  o);
        sq += __shfl_xor_sync(0xffffffffu, sq, o);
    }
    __shared__ float reds[4], redq[4];
    int wid = tid >> 5, lane = tid & 31;
    if (lane == 0) { reds[wid] = s; redq[wid] = sq; }
    __syncthreads();
    s  = reds[0] + reds[1] + reds[2] + reds[3];
    sq = redq[0] + redq[1] + redq[2] + redq[3];
    float mu   = s * (1.0f / DIM);
    float var  = sq * (1.0f / DIM) - mu * mu;
    float rstd = rsqrtf(var + 1e-5f);
    float4 wv = *(const float4*)(w  + tid * 4);
    float4 bv = *(const float4*)(bb + tid * 4);
    float4 out;
    out.x = (v.x - mu) * rstd * wv.x + bv.x;
    out.y = (v.y - mu) * rstd * wv.y + bv.y;
    out.z = (v.z - mu) * rstd * wv.z + bv.z;
    out.w = (v.w - mu) * rstd * wv.w + bv.w;
    *(float4*)(Y + (size_t)row * DIM + tid * 4) = out;
}

// ---------------- AA_j = |q_j|^2 ----------------
__global__ void aa_kernel(const float* __restrict__ Q, float* __restrict__ AA)
{
    int idx = blockIdx.x * blockDim.x + threadIdx.x;
    if (idx >= ROWS * NHEAD) return;
    int h = idx & 7;
    int row = idx >> 3;
    const float* qp = Q + (size_t)row * DIM + h * DHEAD;
    float s = 0.0f;
    #pragma unroll
    for (int i = 0; i < 16; i++) {
        float4 v = *(const float4*)(qp + i * 4);
        s += v.x*v.x + v.y*v.y + v.z*v.z + v.w*v.w;
    }
    int b = row >> 11, n = row & 2047;
    AA[((size_t)(b * NHEAD + h)) * NSEQ + n] = s;
}

// ---------------- GEGLU ----------------
__device__ __forceinline__ float gelu_exact(float x) {
    return 0.5f * x * (1.0f + erff(x * 0.70710678118654752f));
}
__global__ void geglu_kernel(const float* __restrict__ H, float* __restrict__ G)
{
    int idx = blockIdx.x * blockDim.x + threadIdx.x;
    if (idx >= ROWS * (IFF / 4)) return;
    int row = idx / (IFF / 4);
    int c4  = idx % (IFF / 4);
    const float* base = H + (size_t)row * (2 * IFF);
    float4 a  = *(const float4*)(base + c4 * 4);
    float4 gt = *(const float4*)(base + IFF + c4 * 4);
    float4 r;
    r.x = a.x * gelu_exact(gt.x);
    r.y = a.y * gelu_exact(gt.y);
    r.z = a.z * gelu_exact(gt.z);
    r.w = a.w * gelu_exact(gt.w);
    *(float4*)(G + (size_t)row * IFF + c4 * 4) = r;
}

// ---------------- host orchestration ----------------
struct Bufs {
    float *xn, *q, *v, *att, *x1, *x2, *aa, *hh, *gg;
    __nv_bfloat16 *ahi, *alo, *whi, *wlo, *qb, *vb;
};

static void conv_act(const float* X, __nv_bfloat16* hi, __nv_bfloat16* lo, int n) {
    int n4 = n / 4;
    conv_act_kernel<<<(n4 + 255) / 256, 256>>>(X, hi, lo, n4);
}
static void conv_b16(const float* X, __nv_bfloat16* Y, int n) {
    int n4 = n / 4;
    conv_b16_kernel<<<(n4 + 255) / 256, 256>>>(X, Y, n4);
}
static void conv_wt(const float* W, __nv_bfloat16* hi, __nv_bfloat16* lo, int K, int N) {
    dim3 grid(N / 32, K / 32);
    conv_wt_kernel<<<grid, 256>>>(W, hi, lo, K, N);
}
static void tc_gemm(const Bufs& B, const float* bias, const float* res,
                    float* C, int M, int N, int K) {
    dim3 grid(N / 128, M / 128);
    mma_gemm_kernel<<<grid, 256>>>(B.ahi, B.alo, B.whi, B.wlo, bias, res, C, M, N, K);
}
static void run_attention(const Bufs& B, float* attn_out) {
    int aa_blocks = (ROWS * NHEAD + 255) / 256;
    aa_kernel<<<aa_blocks, 256>>>(B.q, B.aa);
    conv_b16(B.q, B.qb, ROWS * DIM);
    conv_b16(B.v, B.vb, ROWS * DIM);
    dim3 fa_grid(NSEQ / FB_BQ, NHEAD, NBATCH);
    flash_mma_kernel<<<fa_grid, 128>>>(B.qb, B.vb, B.aa, attn_out);
}

extern "C" void kernel_launch(void* const* d_in, const int* in_sizes, int n_in,
                              void* d_out, int out_size)
{
    const float* x     = (const float*)d_in[0];
    const float* sa_w  = (const float*)d_in[1];
    const float* sa_b  = (const float*)d_in[2];
    const float* ca_w  = (const float*)d_in[3];
    const float* ca_b  = (const float*)d_in[4];
    const float* ff_nw = (const float*)d_in[5];
    const float* ff_nb = (const float*)d_in[6];
    const float* a1_wq = (const float*)d_in[7];
    const float* a1_bq = (const float*)d_in[8];
    const float* a1_wv = (const float*)d_in[9];
    const float* a1_bv = (const float*)d_in[10];
    const float* a1_wo = (const float*)d_in[11];
    const float* a1_bo = (const float*)d_in[12];
    const float* a2_wq = (const float*)d_in[13];
    const float* a2_bq = (const float*)d_in[14];
    const float* a2_wv = (const float*)d_in[15];
    const float* a2_bv = (const float*)d_in[16];
    const float* a2_wo = (const float*)d_in[17];
    const float* a2_bo = (const float*)d_in[18];
    const float* ff_w1 = (const float*)d_in[19];
    const float* ff_b1 = (const float*)d_in[20];
    const float* ff_w2 = (const float*)d_in[21];
    const float* ff_b2 = (const float*)d_in[22];
    float* out = (float*)d_out;

    Bufs B;
    cudaGetSymbolAddress((void**)&B.xn,  g_xn);
    cudaGetSymbolAddress((void**)&B.q,   g_q);
    cudaGetSymbolAddress((void**)&B.v,   g_v);
    cudaGetSymbolAddress((void**)&B.att, g_att);
    cudaGetSymbolAddress((void**)&B.x1,  g_x1);
    cudaGetSymbolAddress((void**)&B.x2,  g_x2);
    cudaGetSymbolAddress((void**)&B.aa,  g_aa);
    cudaGetSymbolAddress((void**)&B.hh,  g_h);
    cudaGetSymbolAddress((void**)&B.gg,  g_g);
    cudaGetSymbolAddress((void**)&B.ahi, g_ahi);
    cudaGetSymbolAddress((void**)&B.alo, g_alo);
    cudaGetSymbolAddress((void**)&B.whi, g_whi);
    cudaGetSymbolAddress((void**)&B.wlo, g_wlo);
    cudaGetSymbolAddress((void**)&B.qb,  g_qb);
    cudaGetSymbolAddress((void**)&B.vb,  g_vb);

    // ---- self-attention (attn1) ----
    ln_kernel<<<ROWS, 128>>>(x, sa_w, sa_b, B.xn);
    conv_act(B.xn, B.ahi, B.alo, ROWS * DIM);
    conv_wt(a1_wq, B.whi, B.wlo, DIM, DIM);
    tc_gemm(B, a1_bq, nullptr, B.q, ROWS, DIM, DIM);
    conv_wt(a1_wv, B.whi, B.wlo, DIM, DIM);
    tc_gemm(B, a1_bv, nullptr, B.v, ROWS, DIM, DIM);
    run_attention(B, B.att);
    conv_act(B.att, B.ahi, B.alo, ROWS * DIM);
    conv_wt(a1_wo, B.whi, B.wlo, DIM, DIM);
    tc_gemm(B, a1_bo, x, B.x1, ROWS, DIM, DIM);

    // ---- attn2 (k=q, v from x) ----
    ln_kernel<<<ROWS, 128>>>(B.x1, ca_w, ca_b, B.xn);
    conv_act(B.xn, B.ahi, B.alo, ROWS * DIM);
    conv_wt(a2_wq, B.whi, B.wlo, DIM, DIM);
    tc_gemm(B, a2_bq, nullptr, B.q, ROWS, DIM, DIM);
    conv_wt(a2_wv, B.whi, B.wlo, DIM, DIM);
    tc_gemm(B, a2_bv, nullptr, B.v, ROWS, DIM, DIM);
    run_attention(B, B.att);
    conv_act(B.att, B.ahi, B.alo, ROWS * DIM);
    conv_wt(a2_wo, B.whi, B.wlo, DIM, DIM);
    tc_gemm(B, a2_bo, B.x1, B.x2, ROWS, DIM, DIM);

    // ---- GEGLU FFN ----
    ln_kernel<<<ROWS, 128>>>(B.x2, ff_nw, ff_nb, B.xn);
    conv_act(B.xn, B.ahi, B.alo, ROWS * DIM);
    conv_wt(ff_w1, B.whi, B.wlo, DIM, 2 * IFF);
    tc_gemm(B, ff_b1, nullptr, B.hh, ROWS, 2 * IFF, DIM);
    int ge_blocks = (ROWS * (IFF / 4) + 255) / 256;
    geglu_kernel<<<ge_blocks, 256>>>(B.hh, B.gg);
    conv_act(B.gg, B.ahi, B.alo, ROWS * IFF);
    conv_wt(ff_w2, B.whi, B.wlo, IFF, DIM);
    tc_gemm(B, ff_b2, B.x2, out, ROWS, DIM, IFF);
}

// round 9
// speedup vs baseline: 4.3068x; 1.1638x over previous
#include <cuda_runtime.h>
#include <cuda_bf16.h>
#include <cstdint>
#include <math.h>

#define ROWS 8192
#define DIM  512
#define NSEQ 2048
#define NBATCH 4
#define NHEAD 8
#define DHEAD 64
#define IFF  2048

// ---------------- scratch ----------------
__device__ float g_q32[1];   // unused placeholder to keep symbol table stable
__device__ float g_x1 [ROWS * DIM];
__device__ float g_x2 [ROWS * DIM];
__device__ float g_aa [NBATCH * NHEAD * NSEQ];
__device__ float g_h  [ROWS * 2 * IFF];
// bf16 hi/lo activation split (GEMM A operand), max K=2048
__device__ __nv_bfloat16 g_ahi[ROWS * IFF];
__device__ __nv_bfloat16 g_alo[ROWS * IFF];
// transposed weights [N,K] hi/lo, max 4096*512
__device__ __nv_bfloat16 g_whi[4096 * 512];
__device__ __nv_bfloat16 g_wlo[4096 * 512];
// bf16 Q/V for flash attention
__device__ __nv_bfloat16 g_qb[ROWS * DIM];
__device__ __nv_bfloat16 g_vb[ROWS * DIM];

// =================== helpers ===================
__device__ __forceinline__ uint32_t smem_u32(const void* p) {
    uint32_t a;
    asm("{ .reg .u64 t; cvta.to.shared.u64 t, %1; cvt.u32.u64 %0, t; }" : "=r"(a) : "l"(p));
    return a;
}
#define LDSM4(r, addr) \
    asm volatile("ldmatrix.sync.aligned.m8n8.x4.shared.b16 {%0,%1,%2,%3}, [%4];" \
        : "=r"((r)[0]), "=r"((r)[1]), "=r"((r)[2]), "=r"((r)[3]) : "r"(addr))
#define LDSM4T(r, addr) \
    asm volatile("ldmatrix.sync.aligned.m8n8.x4.trans.shared.b16 {%0,%1,%2,%3}, [%4];" \
        : "=r"((r)[0]), "=r"((r)[1]), "=r"((r)[2]), "=r"((r)[3]) : "r"(addr))

__device__ __forceinline__ void mma_bf16(float* d, const uint32_t* a, const uint32_t* b) {
    asm volatile("mma.sync.aligned.m16n8k16.row.col.f32.bf16.bf16.f32 "
        "{%0,%1,%2,%3}, {%4,%5,%6,%7}, {%8,%9}, {%0,%1,%2,%3};"
        : "+f"(d[0]), "+f"(d[1]), "+f"(d[2]), "+f"(d[3])
        : "r"(a[0]), "r"(a[1]), "r"(a[2]), "r"(a[3]), "r"(b[0]), "r"(b[1]));
}
__device__ __forceinline__ void cp16(uint32_t saddr, const void* g) {
    asm volatile("cp.async.cg.shared.global [%0], [%1], 16;" :: "r"(saddr), "l"(g));
}
#define CP_COMMIT() asm volatile("cp.async.commit_group;" ::: "memory")
#define CP_WAIT1()  asm volatile("cp.async.wait_group 1;" ::: "memory")

// =================== cp.async double-buffered HMMA GEMM ===================
// C[M,N] = A[M,K] @ Bt[N,K]^T + bias (+res).  hi/lo bf16 split, 3 MMAs.
// 128x128 CTA tile, 8 warps (4x2), BK=32, 3-stage cp.async pipeline.
#define MG_PAD   40
#define ST_T     (128 * MG_PAD)          // elems per array per stage
#define ST_T2    (ST_T * 2)              // bytes per array per stage
#define ST_ELEMS (4 * ST_T)              // elems per stage
#define ST_BYTES (ST_ELEMS * 2)          // 40960 B
#define NSTAGE   3
#define G_SMEM   (NSTAGE * ST_BYTES)     // 122880 B

__global__ __launch_bounds__(256, 1) void mma_gemm_kernel(
    const __nv_bfloat16* __restrict__ Ahi, const __nv_bfloat16* __restrict__ Alo,
    const __nv_bfloat16* __restrict__ Bhi, const __nv_bfloat16* __restrict__ Blo,
    const float* __restrict__ bias, const float* __restrict__ res,
    float* __restrict__ Cf, __nv_bfloat16* __restrict__ Cb,
    int M, int N, int K)
{
    extern __shared__ __nv_bfloat16 smem[];
    uint32_t sbase = smem_u32(smem);

    int tid = threadIdx.x, lane = tid & 31, wid = tid >> 5;
    int brow = blockIdx.y, bcol = blockIdx.x;
    int warp_m = (wid >> 1) * 32;
    int warp_n = (wid & 1) * 64;

    // per-thread load indices
    int l_row0 = tid >> 2;            // 0..63
    int l_ch   = tid & 3;             // 16B chunk
    const __nv_bfloat16* Aat = Ahi + (size_t)(brow * 128) * K;
    const __nv_bfloat16* Aal = Alo + (size_t)(brow * 128) * K;
    const __nv_bfloat16* Bbt = Bhi + (size_t)(bcol * 128) * K;
    const __nv_bfloat16* Bbl = Blo + (size_t)(bcol * 128) * K;

    float acc[2][8][4];
    #pragma unroll
    for (int t = 0; t < 2; t++)
        #pragma unroll
        for (int nt = 0; nt < 8; nt++)
            #pragma unroll
            for (int j = 0; j < 4; j++) acc[t][nt][j] = 0.0f;

    int nchunk = K >> 5;

    // prologue: stages 0,1
    #pragma unroll
    for (int p = 0; p < 2; p++) {
        uint32_t stb = sbase + p * ST_BYTES;
        #pragma unroll
        for (int it = 0; it < 2; it++) {
            int row = l_row0 + it * 64;
            uint32_t so = stb + (uint32_t)(row * MG_PAD + l_ch * 8) * 2;
            size_t go = (size_t)row * K + p * 32 + l_ch * 8;
            cp16(so + 0 * ST_T2, Aat + go);
            cp16(so + 1 * ST_T2, Aal + go);
            cp16(so + 2 * ST_T2, Bbt + go);
            cp16(so + 3 * ST_T2, Bbl + go);
        }
        CP_COMMIT();
    }

    int stage = 0;
    for (int c = 0; c < nchunk; c++) {
        CP_WAIT1();
        __syncthreads();

        // issue loads for c+2 into stage (c+2)%3
        if (c + 2 < nchunk) {
            int ns = stage + 2; if (ns >= 3) ns -= 3;
            uint32_t stb = sbase + ns * ST_BYTES;
            #pragma unroll
            for (int it = 0; it < 2; it++) {
                int row = l_row0 + it * 64;
                uint32_t so = stb + (uint32_t)(row * MG_PAD + l_ch * 8) * 2;
                size_t go = (size_t)row * K + (c + 2) * 32 + l_ch * 8;
                cp16(so + 0 * ST_T2, Aat + go);
                cp16(so + 1 * ST_T2, Aal + go);
                cp16(so + 2 * ST_T2, Bbt + go);
                cp16(so + 3 * ST_T2, Bbl + go);
            }
        }
        CP_COMMIT();

        // compute current stage
        uint32_t sa_h = sbase + stage * ST_BYTES;
        uint32_t sa_l = sa_h + ST_T2;
        uint32_t sb_h = sa_h + 2 * ST_T2;
        uint32_t sb_l = sa_h + 3 * ST_T2;

        #pragma unroll
        for (int ks = 0; ks < 2; ks++) {
            int kk = ks * 16;
            uint32_t ah[2][4], al[2][4];
            #pragma unroll
            for (int t = 0; t < 2; t++) {
                uint32_t off = (uint32_t)((warp_m + t * 16 + (lane & 15)) * MG_PAD
                             + kk + ((lane >> 4) << 3)) * 2;
                LDSM4(ah[t], sa_h + off);
                LDSM4(al[t], sa_l + off);
            }
            uint32_t bh[8][2], bl[8][2];
            #pragma unroll
            for (int p = 0; p < 4; p++) {
                uint32_t off = (uint32_t)((warp_n + p * 16 + ((lane >> 3) & 1) * 8 + (lane & 7)) * MG_PAD
                             + kk + ((lane >> 4) << 3)) * 2;
                uint32_t r[4];
                LDSM4(r, sb_h + off);
                bh[2*p][0] = r[0]; bh[2*p][1] = r[2];
                bh[2*p+1][0] = r[1]; bh[2*p+1][1] = r[3];
                LDSM4(r, sb_l + off);
                bl[2*p][0] = r[0]; bl[2*p][1] = r[2];
                bl[2*p+1][0] = r[1]; bl[2*p+1][1] = r[3];
            }
            #pragma unroll
            for (int t = 0; t < 2; t++)
                #pragma unroll
                for (int nt = 0; nt < 8; nt++) {
                    mma_bf16(acc[t][nt], ah[t], bh[nt]);
                    mma_bf16(acc[t][nt], ah[t], bl[nt]);
                    mma_bf16(acc[t][nt], al[t], bh[nt]);
                }
        }
        stage++; if (stage >= 3) stage = 0;
    }

    // epilogue
    int r0 = lane >> 2, c0 = (lane & 3) * 2;
    #pragma unroll
    for (int t = 0; t < 2; t++) {
        #pragma unroll
        for (int half = 0; half < 2; half++) {
            int grow = brow * 128 + warp_m + t * 16 + r0 + half * 8;
            #pragma unroll
            for (int nt = 0; nt < 8; nt++) {
                int gcol = bcol * 128 + warp_n + nt * 8 + c0;
                float ox = acc[t][nt][half * 2 + 0] + bias[gcol];
                float oy = acc[t][nt][half * 2 + 1] + bias[gcol + 1];
                if (Cb) {
                    *(__nv_bfloat162*)(Cb + (size_t)grow * N + gcol) =
                        __floats2bfloat162_rn(ox, oy);
                } else {
                    if (res) {
                        float2 rv = *(const float2*)(res + (size_t)grow * N + gcol);
                        ox += rv.x; oy += rv.y;
                    }
                    float2 o; o.x = ox; o.y = oy;
                    *(float2*)(Cf + (size_t)grow * N + gcol) = o;
                }
            }
        }
    }
}

// =================== HMMA flash attention (writes hi/lo split output) ===================
#define FB_BQ 64
#define FB_BK 64
#define FB_PAD 72

__global__ __launch_bounds__(128) void flash_mma_kernel(
    const __nv_bfloat16* __restrict__ Qb, const __nv_bfloat16* __restrict__ Vb,
    const float* __restrict__ AA,
    __nv_bfloat16* __restrict__ Ohi, __nv_bfloat16* __restrict__ Olo)
{
    __shared__ __nv_bfloat16 sQ[FB_BQ * FB_PAD];
    __shared__ __nv_bfloat16 sK[FB_BK * FB_PAD];
    __shared__ __nv_bfloat16 sV[FB_BK * FB_PAD];
    __shared__ float sAA[FB_BK];

    int b = blockIdx.z, h = blockIdx.y;
    int q0 = blockIdx.x * FB_BQ;
    int tid = threadIdx.x, lane = tid & 31, w = tid >> 5;

    uint32_t sq_a = smem_u32(sQ), sk_a = smem_u32(sK), sv_a = smem_u32(sV);

    #pragma unroll
    for (int i = 0; i < 4; i++) {
        int idx = tid + i * 128;
        int r = idx >> 3, c = idx & 7;
        size_t off = (size_t)(b * NSEQ + q0 + r) * DIM + h * DHEAD + c * 8;
        *(uint4*)&sQ[r * FB_PAD + c * 8] = *(const uint4*)(Qb + off);
    }
    __syncthreads();

    uint32_t qa[4][4];
    #pragma unroll
    for (int ks = 0; ks < 4; ks++) {
        uint32_t off = (uint32_t)((w * 16 + (lane & 15)) * FB_PAD + ks * 16 + ((lane >> 4) << 3)) * 2;
        LDSM4(qa[ks], sq_a + off);
    }

    float m0 = -1e30f, m1 = -1e30f, l0 = 0.0f, l1 = 0.0f;
    float o[8][4];
    #pragma unroll
    for (int t = 0; t < 8; t++)
        #pragma unroll
        for (int j = 0; j < 4; j++) o[t][j] = 0.0f;

    const float* aab = AA + ((size_t)(b * NHEAD + h)) * NSEQ;

    for (int kt = 0; kt < NSEQ; kt += FB_BK) {
        __syncthreads();
        #pragma unroll
        for (int i = 0; i < 4; i++) {
            int idx = tid + i * 128;
            int r = idx >> 3, c = idx & 7;
            size_t off = (size_t)(b * NSEQ + kt + r) * DIM + h * DHEAD + c * 8;
            *(uint4*)&sK[r * FB_PAD + c * 8] = *(const uint4*)(Qb + off);
            *(uint4*)&sV[r * FB_PAD + c * 8] = *(const uint4*)(Vb + off);
        }
        if (tid < FB_BK) sAA[tid] = aab[kt + tid];
        __syncthreads();

        float sc[8][4];
        #pragma unroll
        for (int t = 0; t < 8; t++)
            #pragma unroll
            for (int j = 0; j < 4; j++) sc[t][j] = 0.0f;

        #pragma unroll
        for (int ks = 0; ks < 4; ks++) {
            uint32_t kb[8][2];
            #pragma unroll
            for (int p = 0; p < 4; p++) {
                uint32_t off = (uint32_t)((p * 16 + ((lane >> 3) & 1) * 8 + (lane & 7)) * FB_PAD
                             + ks * 16 + ((lane >> 4) << 3)) * 2;
                uint32_t r[4];
                LDSM4(r, sk_a + off);
                kb[2*p][0] = r[0]; kb[2*p][1] = r[2];
                kb[2*p+1][0] = r[1]; kb[2*p+1][1] = r[3];
            }
            #pragma unroll
            for (int t = 0; t < 8; t++) mma_bf16(sc[t], qa[ks], kb[t]);
        }

        float mt0 = -1e30f, mt1 = -1e30f;
        #pragma unroll
        for (int t = 0; t < 8; t++) {
            float a0 = sAA[t * 8 + (lane & 3) * 2];
            float a1 = sAA[t * 8 + (lane & 3) * 2 + 1];
            sc[t][0] = 0.25f * sc[t][0] - 0.125f * a0;
            sc[t][1] = 0.25f * sc[t][1] - 0.125f * a1;
            sc[t][2] = 0.25f * sc[t][2] - 0.125f * a0;
            sc[t][3] = 0.25f * sc[t][3] - 0.125f * a1;
            mt0 = fmaxf(mt0, fmaxf(sc[t][0], sc[t][1]));
            mt1 = fmaxf(mt1, fmaxf(sc[t][2], sc[t][3]));
        }
        mt0 = fmaxf(mt0, __shfl_xor_sync(0xffffffffu, mt0, 1));
        mt0 = fmaxf(mt0, __shfl_xor_sync(0xffffffffu, mt0, 2));
        mt1 = fmaxf(mt1, __shfl_xor_sync(0xffffffffu, mt1, 1));
        mt1 = fmaxf(mt1, __shfl_xor_sync(0xffffffffu, mt1, 2));

        float mn0 = fmaxf(m0, mt0), mn1 = fmaxf(m1, mt1);
        float al0 = __expf(m0 - mn0), al1 = __expf(m1 - mn1);
        m0 = mn0; m1 = mn1;
        l0 *= al0; l1 *= al1;
        #pragma unroll
        for (int t = 0; t < 8; t++) {
            o[t][0] *= al0; o[t][1] *= al0;
            o[t][2] *= al1; o[t][3] *= al1;
        }

        #pragma unroll
        for (int t = 0; t < 8; t++) {
            sc[t][0] = __expf(sc[t][0] - m0);
            sc[t][1] = __expf(sc[t][1] - m0);
            sc[t][2] = __expf(sc[t][2] - m1);
            sc[t][3] = __expf(sc[t][3] - m1);
            l0 += sc[t][0] + sc[t][1];
            l1 += sc[t][2] + sc[t][3];
        }

        #pragma unroll
        for (int j = 0; j < 4; j++) {
            uint32_t pa[4];
            __nv_bfloat162 t2;
            t2 = __floats2bfloat162_rn(sc[2*j][0],   sc[2*j][1]);   pa[0] = *(uint32_t*)&t2;
            t2 = __floats2bfloat162_rn(sc[2*j][2],   sc[2*j][3]);   pa[1] = *(uint32_t*)&t2;
            t2 = __floats2bfloat162_rn(sc[2*j+1][0], sc[2*j+1][1]); pa[2] = *(uint32_t*)&t2;
            t2 = __floats2bfloat162_rn(sc[2*j+1][2], sc[2*j+1][3]); pa[3] = *(uint32_t*)&t2;

            uint32_t vb[8][2];
            #pragma unroll
            for (int dp = 0; dp < 4; dp++) {
                int g = lane >> 3, rr = lane & 7;
                uint32_t off = (uint32_t)((j * 16 + (g & 1) * 8 + rr) * FB_PAD
                             + dp * 16 + (g >> 1) * 8) * 2;
                uint32_t r[4];
                LDSM4T(r, sv_a + off);
                vb[2*dp][0]   = r[0]; vb[2*dp][1]   = r[1];
                vb[2*dp+1][0] = r[2]; vb[2*dp+1][1] = r[3];
            }
            #pragma unroll
            for (int t = 0; t < 8; t++) mma_bf16(o[t], pa, vb[t]);
        }
    }

    l0 += __shfl_xor_sync(0xffffffffu, l0, 1);
    l0 += __shfl_xor_sync(0xffffffffu, l0, 2);
    l1 += __shfl_xor_sync(0xffffffffu, l1, 1);
    l1 += __shfl_xor_sync(0xffffffffu, l1, 2);
    float inv0 = 1.0f / l0, inv1 = 1.0f / l1;

    int r0g = q0 + w * 16 + (lane >> 2);
    #pragma unroll
    for (int t = 0; t < 8; t++) {
        int c = h * DHEAD + t * 8 + (lane & 3) * 2;
        float o00 = o[t][0] * inv0, o01 = o[t][1] * inv0;
        float o10 = o[t][2] * inv1, o11 = o[t][3] * inv1;
        size_t off0 = (size_t)(b * NSEQ + r0g) * DIM + c;
        size_t off1 = (size_t)(b * NSEQ + r0g + 8) * DIM + c;
        __nv_bfloat162 h0 = __floats2bfloat162_rn(o00, o01);
        __nv_bfloat162 h1 = __floats2bfloat162_rn(o10, o11);
        *(__nv_bfloat162*)(Ohi + off0) = h0;
        *(__nv_bfloat162*)(Ohi + off1) = h1;
        *(__nv_bfloat162*)(Olo + off0) = __floats2bfloat162_rn(
            o00 - __bfloat162float(h0.x), o01 - __bfloat162float(h0.y));
        *(__nv_bfloat162*)(Olo + off1) = __floats2bfloat162_rn(
            o10 - __bfloat162float(h1.x), o11 - __bfloat162float(h1.y));
    }
}

// ---------------- fused LayerNorm + hi/lo split ----------------
__global__ __launch_bounds__(128) void ln_split_kernel(
    const float* __restrict__ X, const float* __restrict__ w,
    const float* __restrict__ bb, __nv_bfloat16* __restrict__ Hi,
    __nv_bfloat16* __restrict__ Lo)
{
    int row = blockIdx.x;
    int tid = threadIdx.x;
    const float* xp = X + (size_t)row * DIM;
    float4 v = *(const float4*)(xp + tid * 4);
    float s  = v.x + v.y + v.z + v.w;
    float sq = v.x*v.x + v.y*v.y + v.z*v.z + v.w*v.w;
    #pragma unroll
    for (int o = 16; o > 0; o >>= 1) {
        s  += __shfl_xor_sync(0xffffffffu, s,  o);
        sq += __shfl_xor_sync(0xffffffffu, sq, o);
    }
    __shared__ float reds[4], redq[4];
    int wid = tid >> 5, lane = tid & 31;
    if (lane == 0) { reds[wid] = s; redq[wid] = sq; }
    __syncthreads();
    s  = reds[0] + reds[1] + reds[2] + reds[3];
    sq = redq[0] + redq[1] + redq[2] + redq[3];
    float mu   = s * (1.0f / DIM);
    float var  = sq * (1.0f / DIM) - mu * mu;
    float rstd = rsqrtf(var + 1e-5f);
    float4 wv = *(const float4*)(w  + tid * 4);
    float4 bv = *(const float4*)(bb + tid * 4);
    float o0 = (v.x - mu) * rstd * wv.x + bv.x;
    float o1 = (v.y - mu) * rstd * wv.y + bv.y;
    float o2 = (v.z - mu) * rstd * wv.z + bv.z;
    float o3 = (v.w - mu) * rstd * wv.w + bv.w;
    __nv_bfloat162 h0 = __floats2bfloat162_rn(o0, o1);
    __nv_bfloat162 h1 = __floats2bfloat162_rn(o2, o3);
    __nv_bfloat162 l0 = __floats2bfloat162_rn(o0 - __bfloat162float(h0.x),
                                              o1 - __bfloat162float(h0.y));
    __nv_bfloat162 l1 = __floats2bfloat162_rn(o2 - __bfloat162float(h1.x),
                                              o3 - __bfloat162float(h1.y));
    size_t off = (size_t)row * DIM + tid * 4;
    *(__nv_bfloat162*)(Hi + off) = h0;
    *(__nv_bfloat162*)(Hi + off + 2) = h1;
    *(__nv_bfloat162*)(Lo + off) = l0;
    *(__nv_bfloat162*)(Lo + off + 2) = l1;
}

// ---------------- weight transpose+split ----------------
__global__ __launch_bounds__(256) void conv_wt_kernel(
    const float* __restrict__ W, __nv_bfloat16* __restrict__ Thi,
    __nv_bfloat16* __restrict__ Tlo, int K, int N)
{
    __shared__ __nv_bfloat16 shi[32][33];
    __shared__ __nv_bfloat16 slo[32][33];
    int tx = threadIdx.x & 31, ty = threadIdx.x >> 5;
    int n0 = blockIdx.x * 32, k0 = blockIdx.y * 32;
    #pragma unroll
    for (int j = 0; j < 4; j++) {
        int k = ty + j * 8;
        float v = W[(size_t)(k0 + k) * N + n0 + tx];
        __nv_bfloat16 h = __float2bfloat16_rn(v);
        shi[k][tx] = h;
        slo[k][tx] = __float2bfloat16_rn(v - __bfloat162float(h));
    }
    __syncthreads();
    #pragma unroll
    for (int j = 0; j < 4; j++) {
        int n = ty + j * 8;
        Thi[(size_t)(n0 + n) * K + k0 + tx] = shi[tx][n];
        Tlo[(size_t)(n0 + n) * K + k0 + tx] = slo[tx][n];
    }
}

// ---------------- AA_j = |q_j|^2 from bf16 q ----------------
__global__ void aa_kernel(const __nv_bfloat16* __restrict__ Qb, float* __restrict__ AA)
{
    int idx = blockIdx.x * blockDim.x + threadIdx.x;
    if (idx >= ROWS * NHEAD) return;
    int h = idx & 7;
    int row = idx >> 3;
    const uint4* qp = (const uint4*)(Qb + (size_t)row * DIM + h * DHEAD);
    float s = 0.0f;
    #pragma unroll
    for (int i = 0; i < 8; i++) {
        uint4 u = qp[i];
        const __nv_bfloat162* p = (const __nv_bfloat162*)&u;
        #pragma unroll
        for (int j = 0; j < 4; j++) {
            float2 f = __bfloat1622float2(p[j]);
            s += f.x * f.x + f.y * f.y;
        }
    }
    int b = row >> 11, n = row & 2047;
    AA[((size_t)(b * NHEAD + h)) * NSEQ + n] = s;
}

// ---------------- GEGLU + hi/lo split ----------------
__device__ __forceinline__ float gelu_exact(float x) {
    return 0.5f * x * (1.0f + erff(x * 0.70710678118654752f));
}
__global__ void geglu_split_kernel(const float* __restrict__ H,
                                   __nv_bfloat16* __restrict__ Hi,
                                   __nv_bfloat16* __restrict__ Lo)
{
    int idx = blockIdx.x * blockDim.x + threadIdx.x;
    if (idx >= ROWS * (IFF / 4)) return;
    int row = idx / (IFF / 4);
    int c4  = idx % (IFF / 4);
    const float* base = H + (size_t)row * (2 * IFF);
    float4 a  = *(const float4*)(base + c4 * 4);
    float4 gt = *(const float4*)(base + IFF + c4 * 4);
    float r0 = a.x * gelu_exact(gt.x);
    float r1 = a.y * gelu_exact(gt.y);
    float r2 = a.z * gelu_exact(gt.z);
    float r3 = a.w * gelu_exact(gt.w);
    __nv_bfloat162 h0 = __floats2bfloat162_rn(r0, r1);
    __nv_bfloat162 h1 = __floats2bfloat162_rn(r2, r3);
    __nv_bfloat162 l0 = __floats2bfloat162_rn(r0 - __bfloat162float(h0.x),
                                              r1 - __bfloat162float(h0.y));
    __nv_bfloat162 l1 = __floats2bfloat162_rn(r2 - __bfloat162float(h1.x),
                                              r3 - __bfloat162float(h1.y));
    size_t off = (size_t)row * IFF + c4 * 4;
    *(__nv_bfloat162*)(Hi + off) = h0;
    *(__nv_bfloat162*)(Hi + off + 2) = h1;
    *(__nv_bfloat162*)(Lo + off) = l0;
    *(__nv_bfloat162*)(Lo + off + 2) = l1;
}

// ---------------- host orchestration ----------------
struct Bufs {
    float *x1, *x2, *aa, *hh;
    __nv_bfloat16 *ahi, *alo, *whi, *wlo, *qb, *vb;
};

static void conv_wt(const float* W, __nv_bfloat16* hi, __nv_bfloat16* lo, int K, int N) {
    dim3 grid(N / 32, K / 32);
    conv_wt_kernel<<<grid, 256>>>(W, hi, lo, K, N);
}
static void tc_gemm_f32(const Bufs& B, const float* bias, const float* res,
                        float* C, int M, int N, int K) {
    dim3 grid(N / 128, M / 128);
    mma_gemm_kernel<<<grid, 256, G_SMEM>>>(B.ahi, B.alo, B.whi, B.wlo, bias, res,
                                           C, nullptr, M, N, K);
}
static void tc_gemm_bf16(const Bufs& B, const float* bias,
                         __nv_bfloat16* C, int M, int N, int K) {
    dim3 grid(N / 128, M / 128);
    mma_gemm_kernel<<<grid, 256, G_SMEM>>>(B.ahi, B.alo, B.whi, B.wlo, bias, nullptr,
                                           nullptr, C, M, N, K);
}
static void run_attention(const Bufs& B) {
    int aa_blocks = (ROWS * NHEAD + 255) / 256;
    aa_kernel<<<aa_blocks, 256>>>(B.qb, B.aa);
    dim3 fa_grid(NSEQ / FB_BQ, NHEAD, NBATCH);
    flash_mma_kernel<<<fa_grid, 128>>>(B.qb, B.vb, B.aa, B.ahi, B.alo);
}

extern "C" void kernel_launch(void* const* d_in, const int* in_sizes, int n_in,
                              void* d_out, int out_size)
{
    const float* x     = (const float*)d_in[0];
    const float* sa_w  = (const float*)d_in[1];
    const float* sa_b  = (const float*)d_in[2];
    const float* ca_w  = (const float*)d_in[3];
    const float* ca_b  = (const float*)d_in[4];
    const float* ff_nw = (const float*)d_in[5];
    const float* ff_nb = (const float*)d_in[6];
    const float* a1_wq = (const float*)d_in[7];
    const float* a1_bq = (const float*)d_in[8];
    const float* a1_wv = (const float*)d_in[9];
    const float* a1_bv = (const float*)d_in[10];
    const float* a1_wo = (const float*)d_in[11];
    const float* a1_bo = (const float*)d_in[12];
    const float* a2_wq = (const float*)d_in[13];
    const float* a2_bq = (const float*)d_in[14];
    const float* a2_wv = (const float*)d_in[15];
    const float* a2_bv = (const float*)d_in[16];
    const float* a2_wo = (const float*)d_in[17];
    const float* a2_bo = (const float*)d_in[18];
    const float* ff_w1 = (const float*)d_in[19];
    const float* ff_b1 = (const float*)d_in[20];
    const float* ff_w2 = (const float*)d_in[21];
    const float* ff_b2 = (const float*)d_in[22];
    float* out = (float*)d_out;

    Bufs B;
    cudaGetSymbolAddress((void**)&B.x1,  g_x1);
    cudaGetSymbolAddress((void**)&B.x2,  g_x2);
    cudaGetSymbolAddress((void**)&B.aa,  g_aa);
    cudaGetSymbolAddress((void**)&B.hh,  g_h);
    cudaGetSymbolAddress((void**)&B.ahi, g_ahi);
    cudaGetSymbolAddress((void**)&B.alo, g_alo);
    cudaGetSymbolAddress((void**)&B.whi, g_whi);
    cudaGetSymbolAddress((void**)&B.wlo, g_wlo);
    cudaGetSymbolAddress((void**)&B.qb,  g_qb);
    cudaGetSymbolAddress((void**)&B.vb,  g_vb);

    cudaFuncSetAttribute(mma_gemm_kernel,
                         cudaFuncAttributeMaxDynamicSharedMemorySize, G_SMEM);

    // ---- self-attention (attn1) ----
    ln_split_kernel<<<ROWS, 128>>>(x, sa_w, sa_b, B.ahi, B.alo);
    conv_wt(a1_wq, B.whi, B.wlo, DIM, DIM);
    tc_gemm_bf16(B, a1_bq, B.qb, ROWS, DIM, DIM);
    conv_wt(a1_wv, B.whi, B.wlo, DIM, DIM);
    tc_gemm_bf16(B, a1_bv, B.vb, ROWS, DIM, DIM);
    run_attention(B);   // writes split attn output into ahi/alo
    conv_wt(a1_wo, B.whi, B.wlo, DIM, DIM);
    tc_gemm_f32(B, a1_bo, x, B.x1, ROWS, DIM, DIM);

    // ---- attn2 (k=q, v from x) ----
    ln_split_kernel<<<ROWS, 128>>>(B.x1, ca_w, ca_b, B.ahi, B.alo);
    conv_wt(a2_wq, B.whi, B.wlo, DIM, DIM);
    tc_gemm_bf16(B, a2_bq, B.qb, ROWS, DIM, DIM);
    conv_wt(a2_wv, B.whi, B.wlo, DIM, DIM);
    tc_gemm_bf16(B, a2_bv, B.vb, ROWS, DIM, DIM);
    run_attention(B);
    conv_wt(a2_wo, B.whi, B.wlo, DIM, DIM);
    tc_gemm_f32(B, a2_bo, B.x1, B.x2, ROWS, DIM, DIM);

    // ---- GEGLU FFN ----
    ln_split_kernel<<<ROWS, 128>>>(B.x2, ff_nw, ff_nb, B.ahi, B.alo);
    conv_wt(ff_w1, B.whi, B.wlo, DIM, 2 * IFF);
    tc_gemm_f32(B, ff_b1, nullptr, B.hh, ROWS, 2 * IFF, DIM);
    int ge_blocks = (ROWS * (IFF / 4) + 255) / 256;
    geglu_split_kernel<<<ge_blocks, 256>>>(B.hh, B.ahi, B.alo);
    conv_wt(ff_w2, B.whi, B.wlo, IFF, DIM);
    tc_gemm_f32(B, ff_b2, B.x2, out, ROWS, DIM, IFF);
}

// round 11
// speedup vs baseline: 4.3342x; 1.0064x over previous
#include <cuda_runtime.h>
#include <cuda_bf16.h>
#include <cstdint>
#include <math.h>

#define ROWS 8192
#define DIM  512
#define NSEQ 2048
#define NBATCH 4
#define NHEAD 8
#define DHEAD 64
#define IFF  2048

// ---------------- scratch ----------------
__device__ float g_x1 [ROWS * DIM];
__device__ float g_x2 [ROWS * DIM];
__device__ float g_aa [NBATCH * NHEAD * NSEQ];
__device__ float g_h  [ROWS * 2 * IFF];
__device__ __nv_bfloat16 g_ahi[ROWS * IFF];
__device__ __nv_bfloat16 g_alo[ROWS * IFF];
__device__ __nv_bfloat16 g_whi[4096 * 512];
__device__ __nv_bfloat16 g_wlo[4096 * 512];
__device__ __nv_bfloat16 g_qb[ROWS * DIM];
__device__ __nv_bfloat16 g_vb[ROWS * DIM];

// =================== helpers ===================
__device__ __forceinline__ uint32_t smem_u32(const void* p) {
    uint32_t a;
    asm("{ .reg .u64 t; cvta.to.shared.u64 t, %1; cvt.u32.u64 %0, t; }" : "=r"(a) : "l"(p));
    return a;
}
#define LDSM4(r, addr) \
    asm volatile("ldmatrix.sync.aligned.m8n8.x4.shared.b16 {%0,%1,%2,%3}, [%4];" \
        : "=r"((r)[0]), "=r"((r)[1]), "=r"((r)[2]), "=r"((r)[3]) : "r"(addr))
#define LDSM4T(r, addr) \
    asm volatile("ldmatrix.sync.aligned.m8n8.x4.trans.shared.b16 {%0,%1,%2,%3}, [%4];" \
        : "=r"((r)[0]), "=r"((r)[1]), "=r"((r)[2]), "=r"((r)[3]) : "r"(addr))

__device__ __forceinline__ void mma_bf16(float* d, const uint32_t* a, const uint32_t* b) {
    asm volatile("mma.sync.aligned.m16n8k16.row.col.f32.bf16.bf16.f32 "
        "{%0,%1,%2,%3}, {%4,%5,%6,%7}, {%8,%9}, {%0,%1,%2,%3};"
        : "+f"(d[0]), "+f"(d[1]), "+f"(d[2]), "+f"(d[3])
        : "r"(a[0]), "r"(a[1]), "r"(a[2]), "r"(a[3]), "r"(b[0]), "r"(b[1]));
}
__device__ __forceinline__ void cp16(uint32_t saddr, const void* g) {
    asm volatile("cp.async.cg.shared.global [%0], [%1], 16;" :: "r"(saddr), "l"(g));
}
#define CP_COMMIT() asm volatile("cp.async.commit_group;" ::: "memory")
#define CP_WAIT1()  asm volatile("cp.async.wait_group 1;" ::: "memory")

// =================== cp.async HMMA GEMM, 128x64 tile, 2 CTAs/SM ===================
// C[M,N] = A[M,K] @ Bt[N,K]^T + bias (+res). hi/lo bf16 split (3 MMAs).
// 8 warps as 4(m32) x 2(n32). BK=32, 3-stage cp.async pipeline.
#define MG_PAD    40
#define SA_BYTES  (128 * MG_PAD * 2)        // 10240 B per A array
#define SB_BYTES  (64 * MG_PAD * 2)         // 5120 B per B array
#define OFF_AL    SA_BYTES
#define OFF_BH    (2 * SA_BYTES)
#define OFF_BL    (2 * SA_BYTES + SB_BYTES)
#define ST_BYTES  (2 * SA_BYTES + 2 * SB_BYTES)   // 30720 B per stage
#define NSTAGE    3
#define G_SMEM    (NSTAGE * ST_BYTES)             // 92160 B

__global__ __launch_bounds__(256, 2) void mma_gemm_kernel(
    const __nv_bfloat16* __restrict__ Ahi, const __nv_bfloat16* __restrict__ Alo,
    const __nv_bfloat16* __restrict__ Bhi, const __nv_bfloat16* __restrict__ Blo,
    const float* __restrict__ bias, const float* __restrict__ bias2,
    const float* __restrict__ res,
    float* __restrict__ Cf, __nv_bfloat16* __restrict__ Cb,
    __nv_bfloat16* __restrict__ Cb2,
    int M, int N, int K, int Nh)
{
    extern __shared__ __nv_bfloat16 smem[];
    uint32_t sbase = smem_u32(smem);

    int tid = threadIdx.x, lane = tid & 31, wid = tid >> 5;
    int brow = blockIdx.y, bcol = blockIdx.x;
    int warp_m = (wid >> 1) * 32;
    int warp_n = (wid & 1) * 32;

    // load indices
    int a_row = tid >> 2;            // 0..63 (+64 second iter)
    int l_ch  = tid & 3;
    int b_row = tid >> 2;            // 0..63
    const __nv_bfloat16* Aat = Ahi + (size_t)(brow * 128) * K;
    const __nv_bfloat16* Aal = Alo + (size_t)(brow * 128) * K;
    const __nv_bfloat16* Bbt = Bhi + (size_t)(bcol * 64) * K;
    const __nv_bfloat16* Bbl = Blo + (size_t)(bcol * 64) * K;

    float acc[2][4][4];
    #pragma unroll
    for (int t = 0; t < 2; t++)
        #pragma unroll
        for (int nt = 0; nt < 4; nt++)
            #pragma unroll
            for (int j = 0; j < 4; j++) acc[t][nt][j] = 0.0f;

    int nchunk = K >> 5;

    // prologue: stages 0,1
    #pragma unroll
    for (int p = 0; p < 2; p++) {
        uint32_t stb = sbase + p * ST_BYTES;
        #pragma unroll
        for (int it = 0; it < 2; it++) {
            int row = a_row + it * 64;
            uint32_t so = stb + (uint32_t)(row * MG_PAD + l_ch * 8) * 2;
            size_t go = (size_t)row * K + p * 32 + l_ch * 8;
            cp16(so, Aat + go);
            cp16(so + OFF_AL, Aal + go);
        }
        {
            uint32_t so = stb + (uint32_t)(b_row * MG_PAD + l_ch * 8) * 2;
            size_t go = (size_t)b_row * K + p * 32 + l_ch * 8;
            cp16(so + OFF_BH, Bbt + go);
            cp16(so + OFF_BL, Bbl + go);
        }
        CP_COMMIT();
    }

    int stage = 0;
    for (int c = 0; c < nchunk; c++) {
        CP_WAIT1();
        __syncthreads();

        if (c + 2 < nchunk) {
            int ns = stage + 2; if (ns >= 3) ns -= 3;
            uint32_t stb = sbase + ns * ST_BYTES;
            #pragma unroll
            for (int it = 0; it < 2; it++) {
                int row = a_row + it * 64;
                uint32_t so = stb + (uint32_t)(row * MG_PAD + l_ch * 8) * 2;
                size_t go = (size_t)row * K + (c + 2) * 32 + l_ch * 8;
                cp16(so, Aat + go);
                cp16(so + OFF_AL, Aal + go);
            }
            {
                uint32_t so = stb + (uint32_t)(b_row * MG_PAD + l_ch * 8) * 2;
                size_t go = (size_t)b_row * K + (c + 2) * 32 + l_ch * 8;
                cp16(so + OFF_BH, Bbt + go);
                cp16(so + OFF_BL, Bbl + go);
            }
        }
        CP_COMMIT();

        uint32_t sa_h = sbase + stage * ST_BYTES;
        uint32_t sa_l = sa_h + OFF_AL;
        uint32_t sb_h = sa_h + OFF_BH;
        uint32_t sb_l = sa_h + OFF_BL;

        #pragma unroll
        for (int ks = 0; ks < 2; ks++) {
            int kk = ks * 16;
            uint32_t ah[2][4], al[2][4];
            #pragma unroll
            for (int t = 0; t < 2; t++) {
                uint32_t off = (uint32_t)((warp_m + t * 16 + (lane & 15)) * MG_PAD
                             + kk + ((lane >> 4) << 3)) * 2;
                LDSM4(ah[t], sa_h + off);
                LDSM4(al[t], sa_l + off);
            }
            uint32_t bh[4][2], bl[4][2];
            #pragma unroll
            for (int p = 0; p < 2; p++) {
                uint32_t off = (uint32_t)((warp_n + p * 16 + ((lane >> 3) & 1) * 8 + (lane & 7)) * MG_PAD
                             + kk + ((lane >> 4) << 3)) * 2;
                uint32_t r[4];
                LDSM4(r, sb_h + off);
                bh[2*p][0] = r[0]; bh[2*p][1] = r[2];
                bh[2*p+1][0] = r[1]; bh[2*p+1][1] = r[3];
                LDSM4(r, sb_l + off);
                bl[2*p][0] = r[0]; bl[2*p][1] = r[2];
                bl[2*p+1][0] = r[1]; bl[2*p+1][1] = r[3];
            }
            #pragma unroll
            for (int t = 0; t < 2; t++)
                #pragma unroll
                for (int nt = 0; nt < 4; nt++) {
                    mma_bf16(acc[t][nt], ah[t], bh[nt]);
                    mma_bf16(acc[t][nt], ah[t], bl[nt]);
                    mma_bf16(acc[t][nt], al[t], bh[nt]);
                }
        }
        stage++; if (stage >= 3) stage = 0;
    }

    // epilogue
    int r0 = lane >> 2, c0 = (lane & 3) * 2;
    #pragma unroll
    for (int t = 0; t < 2; t++) {
        #pragma unroll
        for (int half = 0; half < 2; half++) {
            int grow = brow * 128 + warp_m + t * 16 + r0 + half * 8;
            #pragma unroll
            for (int nt = 0; nt < 4; nt++) {
                int gcol = bcol * 64 + warp_n + nt * 8 + c0;
                float ox = acc[t][nt][half * 2 + 0];
                float oy = acc[t][nt][half * 2 + 1];
                if (Cb2) {
                    // pair mode: cols [0,Nh) -> Cb/bias, [Nh,2Nh) -> Cb2/bias2
                    __nv_bfloat16* dst; const float* bs; int cc;
                    if (gcol < Nh) { dst = Cb; bs = bias; cc = gcol; }
                    else           { dst = Cb2; bs = bias2; cc = gcol - Nh; }
                    ox += bs[cc]; oy += bs[cc + 1];
                    *(__nv_bfloat162*)(dst + (size_t)grow * Nh + cc) =
                        __floats2bfloat162_rn(ox, oy);
                } else if (Cb) {
                    ox += bias[gcol]; oy += bias[gcol + 1];
                    *(__nv_bfloat162*)(Cb + (size_t)grow * N + gcol) =
                        __floats2bfloat162_rn(ox, oy);
                } else {
                    ox += bias[gcol]; oy += bias[gcol + 1];
                    if (res) {
                        float2 rv = *(const float2*)(res + (size_t)grow * N + gcol);
                        ox += rv.x; oy += rv.y;
                    }
                    float2 o; o.x = ox; o.y = oy;
                    *(float2*)(Cf + (size_t)grow * N + gcol) = o;
                }
            }
        }
    }
}

// =================== HMMA flash attention (writes hi/lo split output) ===================
#define FB_BQ 64
#define FB_BK 64
#define FB_PAD 72

__global__ __launch_bounds__(128) void flash_mma_kernel(
    const __nv_bfloat16* __restrict__ Qb, const __nv_bfloat16* __restrict__ Vb,
    const float* __restrict__ AA,
    __nv_bfloat16* __restrict__ Ohi, __nv_bfloat16* __restrict__ Olo)
{
    __shared__ __nv_bfloat16 sQ[FB_BQ * FB_PAD];
    __shared__ __nv_bfloat16 sK[FB_BK * FB_PAD];
    __shared__ __nv_bfloat16 sV[FB_BK * FB_PAD];
    __shared__ float sAA[FB_BK];

    int b = blockIdx.z, h = blockIdx.y;
    int q0 = blockIdx.x * FB_BQ;
    int tid = threadIdx.x, lane = tid & 31, w = tid >> 5;

    uint32_t sq_a = smem_u32(sQ), sk_a = smem_u32(sK), sv_a = smem_u32(sV);

    #pragma unroll
    for (int i = 0; i < 4; i++) {
        int idx = tid + i * 128;
        int r = idx >> 3, c = idx & 7;
        size_t off = (size_t)(b * NSEQ + q0 + r) * DIM + h * DHEAD + c * 8;
        *(uint4*)&sQ[r * FB_PAD + c * 8] = *(const uint4*)(Qb + off);
    }
    __syncthreads();

    uint32_t qa[4][4];
    #pragma unroll
    for (int ks = 0; ks < 4; ks++) {
        uint32_t off = (uint32_t)((w * 16 + (lane & 15)) * FB_PAD + ks * 16 + ((lane >> 4) << 3)) * 2;
        LDSM4(qa[ks], sq_a + off);
    }

    float m0 = -1e30f, m1 = -1e30f, l0 = 0.0f, l1 = 0.0f;
    float o[8][4];
    #pragma unroll
    for (int t = 0; t < 8; t++)
        #pragma unroll
        for (int j = 0; j < 4; j++) o[t][j] = 0.0f;

    const float* aab = AA + ((size_t)(b * NHEAD + h)) * NSEQ;

    for (int kt = 0; kt < NSEQ; kt += FB_BK) {
        __syncthreads();
        #pragma unroll
        for (int i = 0; i < 4; i++) {
            int idx = tid + i * 128;
            int r = idx >> 3, c = idx & 7;
            size_t off = (size_t)(b * NSEQ + kt + r) * DIM + h * DHEAD + c * 8;
            *(uint4*)&sK[r * FB_PAD + c * 8] = *(const uint4*)(Qb + off);
            *(uint4*)&sV[r * FB_PAD + c * 8] = *(const uint4*)(Vb + off);
        }
        if (tid < FB_BK) sAA[tid] = aab[kt + tid];
        __syncthreads();

        float sc[8][4];
        #pragma unroll
        for (int t = 0; t < 8; t++)
            #pragma unroll
            for (int j = 0; j < 4; j++) sc[t][j] = 0.0f;

        #pragma unroll
        for (int ks = 0; ks < 4; ks++) {
            uint32_t kb[8][2];
            #pragma unroll
            for (int p = 0; p < 4; p++) {
                uint32_t off = (uint32_t)((p * 16 + ((lane >> 3) & 1) * 8 + (lane & 7)) * FB_PAD
                             + ks * 16 + ((lane >> 4) << 3)) * 2;
                uint32_t r[4];
                LDSM4(r, sk_a + off);
                kb[2*p][0] = r[0]; kb[2*p][1] = r[2];
                kb[2*p+1][0] = r[1]; kb[2*p+1][1] = r[3];
            }
            #pragma unroll
            for (int t = 0; t < 8; t++) mma_bf16(sc[t], qa[ks], kb[t]);
        }

        float mt0 = -1e30f, mt1 = -1e30f;
        #pragma unroll
        for (int t = 0; t < 8; t++) {
            float a0 = sAA[t * 8 + (lane & 3) * 2];
            float a1 = sAA[t * 8 + (lane & 3) * 2 + 1];
            sc[t][0] = 0.25f * sc[t][0] - 0.125f * a0;
            sc[t][1] = 0.25f * sc[t][1] - 0.125f * a1;
            sc[t][2] = 0.25f * sc[t][2] - 0.125f * a0;
            sc[t][3] = 0.25f * sc[t][3] - 0.125f * a1;
            mt0 = fmaxf(mt0, fmaxf(sc[t][0], sc[t][1]));
            mt1 = fmaxf(mt1, fmaxf(sc[t][2], sc[t][3]));
        }
        mt0 = fmaxf(mt0, __shfl_xor_sync(0xffffffffu, mt0, 1));
        mt0 = fmaxf(mt0, __shfl_xor_sync(0xffffffffu, mt0, 2));
        mt1 = fmaxf(mt1, __shfl_xor_sync(0xffffffffu, mt1, 1));
        mt1 = fmaxf(mt1, __shfl_xor_sync(0xffffffffu, mt1, 2));

        float mn0 = fmaxf(m0, mt0), mn1 = fmaxf(m1, mt1);
        float al0 = __expf(m0 - mn0), al1 = __expf(m1 - mn1);
        m0 = mn0; m1 = mn1;
        l0 *= al0; l1 *= al1;
        #pragma unroll
        for (int t = 0; t < 8; t++) {
            o[t][0] *= al0; o[t][1] *= al0;
            o[t][2] *= al1; o[t][3] *= al1;
        }

        #pragma unroll
        for (int t = 0; t < 8; t++) {
            sc[t][0] = __expf(sc[t][0] - m0);
            sc[t][1] = __expf(sc[t][1] - m0);
            sc[t][2] = __expf(sc[t][2] - m1);
            sc[t][3] = __expf(sc[t][3] - m1);
            l0 += sc[t][0] + sc[t][1];
            l1 += sc[t][2] + sc[t][3];
        }

        #pragma unroll
        for (int j = 0; j < 4; j++) {
            uint32_t pa[4];
            __nv_bfloat162 t2;
            t2 = __floats2bfloat162_rn(sc[2*j][0],   sc[2*j][1]);   pa[0] = *(uint32_t*)&t2;
            t2 = __floats2bfloat162_rn(sc[2*j][2],   sc[2*j][3]);   pa[1] = *(uint32_t*)&t2;
            t2 = __floats2bfloat162_rn(sc[2*j+1][0], sc[2*j+1][1]); pa[2] = *(uint32_t*)&t2;
            t2 = __floats2bfloat162_rn(sc[2*j+1][2], sc[2*j+1][3]); pa[3] = *(uint32_t*)&t2;

            uint32_t vb[8][2];
            #pragma unroll
            for (int dp = 0; dp < 4; dp++) {
                int g = lane >> 3, rr = lane & 7;
                uint32_t off = (uint32_t)((j * 16 + (g & 1) * 8 + rr) * FB_PAD
                             + dp * 16 + (g >> 1) * 8) * 2;
                uint32_t r[4];
                LDSM4T(r, sv_a + off);
                vb[2*dp][0]   = r[0]; vb[2*dp][1]   = r[1];
                vb[2*dp+1][0] = r[2]; vb[2*dp+1][1] = r[3];
            }
            #pragma unroll
            for (int t = 0; t < 8; t++) mma_bf16(o[t], pa, vb[t]);
        }
    }

    l0 += __shfl_xor_sync(0xffffffffu, l0, 1);
    l0 += __shfl_xor_sync(0xffffffffu, l0, 2);
    l1 += __shfl_xor_sync(0xffffffffu, l1, 1);
    l1 += __shfl_xor_sync(0xffffffffu, l1, 2);
    float inv0 = 1.0f / l0, inv1 = 1.0f / l1;

    int r0g = q0 + w * 16 + (lane >> 2);
    #pragma unroll
    for (int t = 0; t < 8; t++) {
        int c = h * DHEAD + t * 8 + (lane & 3) * 2;
        float o00 = o[t][0] * inv0, o01 = o[t][1] * inv0;
        float o10 = o[t][2] * inv1, o11 = o[t][3] * inv1;
        size_t off0 = (size_t)(b * NSEQ + r0g) * DIM + c;
        size_t off1 = (size_t)(b * NSEQ + r0g + 8) * DIM + c;
        __nv_bfloat162 h0 = __floats2bfloat162_rn(o00, o01);
        __nv_bfloat162 h1 = __floats2bfloat162_rn(o10, o11);
        *(__nv_bfloat162*)(Ohi + off0) = h0;
        *(__nv_bfloat162*)(Ohi + off1) = h1;
        *(__nv_bfloat162*)(Olo + off0) = __floats2bfloat162_rn(
            o00 - __bfloat162float(h0.x), o01 - __bfloat162float(h0.y));
        *(__nv_bfloat162*)(Olo + off1) = __floats2bfloat162_rn(
            o10 - __bfloat162float(h1.x), o11 - __bfloat162float(h1.y));
    }
}

// ---------------- fused LayerNorm + hi/lo split ----------------
__global__ __launch_bounds__(128) void ln_split_kernel(
    const float* __restrict__ X, const float* __restrict__ w,
    const float* __restrict__ bb, __nv_bfloat16* __restrict__ Hi,
    __nv_bfloat16* __restrict__ Lo)
{
    int row = blockIdx.x;
    int tid = threadIdx.x;
    const float* xp = X + (size_t)row * DIM;
    float4 v = *(const float4*)(xp + tid * 4);
    float s  = v.x + v.y + v.z + v.w;
    float sq = v.x*v.x + v.y*v.y + v.z*v.z + v.w*v.w;
    #pragma unroll
    for (int o = 16; o > 0; o >>= 1) {
        s  += __shfl_xor_sync(0xffffffffu, s,  o);
        sq += __shfl_xor_sync(0xffffffffu, sq, o);
    }
    __shared__ float reds[4], redq[4];
    int wid = tid >> 5, lane = tid & 31;
    if (lane == 0) { reds[wid] = s; redq[wid] = sq; }
    __syncthreads();
    s  = reds[0] + reds[1] + reds[2] + reds[3];
    sq = redq[0] + redq[1] + redq[2] + redq[3];
    float mu   = s * (1.0f / DIM);
    float var  = sq * (1.0f / DIM) - mu * mu;
    float rstd = rsqrtf(var + 1e-5f);
    float4 wv = *(const float4*)(w  + tid * 4);
    float4 bv = *(const float4*)(bb + tid * 4);
    float o0 = (v.x - mu) * rstd * wv.x + bv.x;
    float o1 = (v.y - mu) * rstd * wv.y + bv.y;
    float o2 = (v.z - mu) * rstd * wv.z + bv.z;
    float o3 = (v.w - mu) * rstd * wv.w + bv.w;
    __nv_bfloat162 h0 = __floats2bfloat162_rn(o0, o1);
    __nv_bfloat162 h1 = __floats2bfloat162_rn(o2, o3);
    __nv_bfloat162 l0 = __floats2bfloat162_rn(o0 - __bfloat162float(h0.x),
                                              o1 - __bfloat162float(h0.y));
    __nv_bfloat162 l1 = __floats2bfloat162_rn(o2 - __bfloat162float(h1.x),
                                              o3 - __bfloat162float(h1.y));
    size_t off = (size_t)row * DIM + tid * 4;
    *(__nv_bfloat162*)(Hi + off) = h0;
    *(__nv_bfloat162*)(Hi + off + 2) = h1;
    *(__nv_bfloat162*)(Lo + off) = l0;
    *(__nv_bfloat162*)(Lo + off + 2) = l1;
}

// ---------------- weight transpose+split ----------------
__global__ __launch_bounds__(256) void conv_wt_kernel(
    const float* __restrict__ W, __nv_bfloat16* __restrict__ Thi,
    __nv_bfloat16* __restrict__ Tlo, int K, int N)
{
    __shared__ __nv_bfloat16 shi[32][33];
    __shared__ __nv_bfloat16 slo[32][33];
    int tx = threadIdx.x & 31, ty = threadIdx.x >> 5;
    int n0 = blockIdx.x * 32, k0 = blockIdx.y * 32;
    #pragma unroll
    for (int j = 0; j < 4; j++) {
        int k = ty + j * 8;
        float v = W[(size_t)(k0 + k) * N + n0 + tx];
        __nv_bfloat16 h = __float2bfloat16_rn(v);
        shi[k][tx] = h;
        slo[k][tx] = __float2bfloat16_rn(v - __bfloat162float(h));
    }
    __syncthreads();
    #pragma unroll
    for (int j = 0; j < 4; j++) {
        int n = ty + j * 8;
        Thi[(size_t)(n0 + n) * K + k0 + tx] = shi[tx][n];
        Tlo[(size_t)(n0 + n) * K + k0 + tx] = slo[tx][n];
    }
}

// ---------------- AA_j = |q_j|^2 from bf16 q ----------------
__global__ void aa_kernel(const __nv_bfloat16* __restrict__ Qb, float* __restrict__ AA)
{
    int idx = blockIdx.x * blockDim.x + threadIdx.x;
    if (idx >= ROWS * NHEAD) return;
    int h = idx & 7;
    int row = idx >> 3;
    const uint4* qp = (const uint4*)(Qb + (size_t)row * DIM + h * DHEAD);
    float s = 0.0f;
    #pragma unroll
    for (int i = 0; i < 8; i++) {
        uint4 u = qp[i];
        const __nv_bfloat162* p = (const __nv_bfloat162*)&u;
        #pragma unroll
        for (int j = 0; j < 4; j++) {
            float2 f = __bfloat1622float2(p[j]);
            s += f.x * f.x + f.y * f.y;
        }
    }
    int b = row >> 11, n = row & 2047;
    AA[((size_t)(b * NHEAD + h)) * NSEQ + n] = s;
}

// ---------------- GEGLU + hi/lo split ----------------
__device__ __forceinline__ float gelu_exact(float x) {
    return 0.5f * x * (1.0f + erff(x * 0.70710678118654752f));
}
__global__ void geglu_split_kernel(const float* __restrict__ H,
                                   __nv_bfloat16* __restrict__ Hi,
                                   __nv_bfloat16* __restrict__ Lo)
{
    int idx = blockIdx.x * blockDim.x + threadIdx.x;
    if (idx >= ROWS * (IFF / 4)) return;
    int row = idx / (IFF / 4);
    int c4  = idx % (IFF / 4);
    const float* base = H + (size_t)row * (2 * IFF);
    float4 a  = *(const float4*)(base + c4 * 4);
    float4 gt = *(const float4*)(base + IFF + c4 * 4);
    float r0 = a.x * gelu_exact(gt.x);
    float r1 = a.y * gelu_exact(gt.y);
    float r2 = a.z * gelu_exact(gt.z);
    float r3 = a.w * gelu_exact(gt.w);
    __nv_bfloat162 h0 = __floats2bfloat162_rn(r0, r1);
    __nv_bfloat162 h1 = __floats2bfloat162_rn(r2, r3);
    __nv_bfloat162 l0 = __floats2bfloat162_rn(r0 - __bfloat162float(h0.x),
                                              r1 - __bfloat162float(h0.y));
    __nv_bfloat162 l1 = __floats2bfloat162_rn(r2 - __bfloat162float(h1.x),
                                              r3 - __bfloat162float(h1.y));
    size_t off = (size_t)row * IFF + c4 * 4;
    *(__nv_bfloat162*)(Hi + off) = h0;
    *(__nv_bfloat162*)(Hi + off + 2) = h1;
    *(__nv_bfloat162*)(Lo + off) = l0;
    *(__nv_bfloat162*)(Lo + off + 2) = l1;
}

// ---------------- host orchestration ----------------
struct Bufs {
    float *x1, *x2, *aa, *hh;
    __nv_bfloat16 *ahi, *alo, *whi, *wlo, *qb, *vb;
};

static void conv_wt(const float* W, __nv_bfloat16* hi, __nv_bfloat16* lo, int K, int N) {
    dim3 grid(N / 32, K / 32);
    conv_wt_kernel<<<grid, 256>>>(W, hi, lo, K, N);
}
static void tc_gemm_f32(const Bufs& B, const float* bias, const float* res,
                        float* C, int M, int N, int K) {
    dim3 grid(N / 64, M / 128);
    mma_gemm_kernel<<<grid, 256, G_SMEM>>>(B.ahi, B.alo, B.whi, B.wlo, bias, nullptr,
                                           res, C, nullptr, nullptr, M, N, K, 0);
}
static void tc_gemm_qv(const Bufs& B, const float* bq, const float* bv,
                       int M, int K) {
    // N = 1024 stacked (q rows then v rows in whi/wlo); pair epilogue
    dim3 grid(1024 / 64, M / 128);
    mma_gemm_kernel<<<grid, 256, G_SMEM>>>(B.ahi, B.alo, B.whi, B.wlo, bq, bv,
                                           nullptr, nullptr, B.qb, B.vb,
                                           M, 1024, K, 512);
}
static void run_attention(const Bufs& B) {
    int aa_blocks = (ROWS * NHEAD + 255) / 256;
    aa_kernel<<<aa_blocks, 256>>>(B.qb, B.aa);
    dim3 fa_grid(NSEQ / FB_BQ, NHEAD, NBATCH);
    flash_mma_kernel<<<fa_grid, 128>>>(B.qb, B.vb, B.aa, B.ahi, B.alo);
}

extern "C" void kernel_launch(void* const* d_in, const int* in_sizes, int n_in,
                              void* d_out, int out_size)
{
    const float* x     = (const float*)d_in[0];
    const float* sa_w  = (const float*)d_in[1];
    const float* sa_b  = (const float*)d_in[2];
    const float* ca_w  = (const float*)d_in[3];
    const float* ca_b  = (const float*)d_in[4];
    const float* ff_nw = (const float*)d_in[5];
    const float* ff_nb = (const float*)d_in[6];
    const float* a1_wq = (const float*)d_in[7];
    const float* a1_bq = (const float*)d_in[8];
    const float* a1_wv = (const float*)d_in[9];
    const float* a1_bv = (const float*)d_in[10];
    const float* a1_wo = (const float*)d_in[11];
    const float* a1_bo = (const float*)d_in[12];
    const float* a2_wq = (const float*)d_in[13];
    const float* a2_bq = (const float*)d_in[14];
    const float* a2_wv = (const float*)d_in[15];
    const float* a2_bv = (const float*)d_in[16];
    const float* a2_wo = (const float*)d_in[17];
    const float* a2_bo = (const float*)d_in[18];
    const float* ff_w1 = (const float*)d_in[19];
    const float* ff_b1 = (const float*)d_in[20];
    const float* ff_w2 = (const float*)d_in[21];
    const float* ff_b2 = (const float*)d_in[22];
    float* out = (float*)d_out;

    Bufs B;
    cudaGetSymbolAddress((void**)&B.x1,  g_x1);
    cudaGetSymbolAddress((void**)&B.x2,  g_x2);
    cudaGetSymbolAddress((void**)&B.aa,  g_aa);
    cudaGetSymbolAddress((void**)&B.hh,  g_h);
    cudaGetSymbolAddress((void**)&B.ahi, g_ahi);
    cudaGetSymbolAddress((void**)&B.alo, g_alo);
    cudaGetSymbolAddress((void**)&B.whi, g_whi);
    cudaGetSymbolAddress((void**)&B.wlo, g_wlo);
    cudaGetSymbolAddress((void**)&B.qb,  g_qb);
    cudaGetSymbolAddress((void**)&B.vb,  g_vb);

    cudaFuncSetAttribute(mma_gemm_kernel,
                         cudaFuncAttributeMaxDynamicSharedMemorySize, G_SMEM);

    // ---- self-attention (attn1) ----
    ln_split_kernel<<<ROWS, 128>>>(x, sa_w, sa_b, B.ahi, B.alo);
    conv_wt(a1_wq, B.whi, B.wlo, DIM, DIM);                       // rows 0..511
    conv_wt(a1_wv, B.whi + DIM * DIM, B.wlo + DIM * DIM, DIM, DIM); // rows 512..1023
    tc_gemm_qv(B, a1_bq, a1_bv, ROWS, DIM);
    run_attention(B);   // writes split attn output into ahi/alo
    conv_wt(a1_wo, B.whi, B.wlo, DIM, DIM);
    tc_gemm_f32(B, a1_bo, x, B.x1, ROWS, DIM, DIM);

    // ---- attn2 (k=q, v from x) ----
    ln_split_kernel<<<ROWS, 128>>>(B.x1, ca_w, ca_b, B.ahi, B.alo);
    conv_wt(a2_wq, B.whi, B.wlo, DIM, DIM);
    conv_wt(a2_wv, B.whi + DIM * DIM, B.wlo + DIM * DIM, DIM, DIM);
    tc_gemm_qv(B, a2_bq, a2_bv, ROWS, DIM);
    run_attention(B);
    conv_wt(a2_wo, B.whi, B.wlo, DIM, DIM);
    tc_gemm_f32(B, a2_bo, B.x1, B.x2, ROWS, DIM, DIM);

    // ---- GEGLU FFN ----
    ln_split_kernel<<<ROWS, 128>>>(B.x2, ff_nw, ff_nb, B.ahi, B.alo);
    conv_wt(ff_w1, B.whi, B.wlo, DIM, 2 * IFF);
    tc_gemm_f32(B, ff_b1, nullptr, B.hh, ROWS, 2 * IFF, DIM);
    int ge_blocks = (ROWS * (IFF / 4) + 255) / 256;
    geglu_split_kernel<<<ge_blocks, 256>>>(B.hh, B.ahi, B.alo);
    conv_wt(ff_w2, B.whi, B.wlo, IFF, DIM);
    tc_gemm_f32(B, ff_b2, B.x2, out, ROWS, DIM, IFF);
}

// round 12
// speedup vs baseline: 5.7349x; 1.3232x over previous
#include <cuda_runtime.h>
#include <cuda_bf16.h>
#include <cstdint>
#include <math.h>

#define ROWS 8192
#define DIM  512
#define NSEQ 2048
#define NBATCH 4
#define NHEAD 8
#define DHEAD 64
#define IFF  2048

// ---------------- scratch ----------------
__device__ float g_x1 [ROWS * DIM];
__device__ float g_x2 [ROWS * DIM];
__device__ float g_aa [NBATCH * NHEAD * NSEQ];
__device__ float g_h  [ROWS * 2 * IFF];
__device__ __nv_bfloat16 g_ahi[ROWS * IFF];
__device__ __nv_bfloat16 g_alo[ROWS * IFF];
__device__ __nv_bfloat16 g_whi[4096 * 512];
__device__ __nv_bfloat16 g_wlo[4096 * 512];
__device__ __nv_bfloat16 g_qb[ROWS * DIM];
__device__ __nv_bfloat16 g_vb[ROWS * DIM];

// =================== helpers ===================
__device__ __forceinline__ uint32_t smem_u32(const void* p) {
    uint32_t a;
    asm("{ .reg .u64 t; cvta.to.shared.u64 t, %1; cvt.u32.u64 %0, t; }" : "=r"(a) : "l"(p));
    return a;
}
#define LDSM4(r, addr) \
    asm volatile("ldmatrix.sync.aligned.m8n8.x4.shared.b16 {%0,%1,%2,%3}, [%4];" \
        : "=r"((r)[0]), "=r"((r)[1]), "=r"((r)[2]), "=r"((r)[3]) : "r"(addr))
#define LDSM4T(r, addr) \
    asm volatile("ldmatrix.sync.aligned.m8n8.x4.trans.shared.b16 {%0,%1,%2,%3}, [%4];" \
        : "=r"((r)[0]), "=r"((r)[1]), "=r"((r)[2]), "=r"((r)[3]) : "r"(addr))

__device__ __forceinline__ void mma_bf16(float* d, const uint32_t* a, const uint32_t* b) {
    asm volatile("mma.sync.aligned.m16n8k16.row.col.f32.bf16.bf16.f32 "
        "{%0,%1,%2,%3}, {%4,%5,%6,%7}, {%8,%9}, {%0,%1,%2,%3};"
        : "+f"(d[0]), "+f"(d[1]), "+f"(d[2]), "+f"(d[3])
        : "r"(a[0]), "r"(a[1]), "r"(a[2]), "r"(a[3]), "r"(b[0]), "r"(b[1]));
}
__device__ __forceinline__ void cp16(uint32_t saddr, const void* g) {
    asm volatile("cp.async.cg.shared.global [%0], [%1], 16;" :: "r"(saddr), "l"(g));
}
#define CP_COMMIT() asm volatile("cp.async.commit_group;" ::: "memory")
#define CP_WAIT1()  asm volatile("cp.async.wait_group 1;" ::: "memory")

// =================== cp.async HMMA GEMM, 128x64 tile, 2 CTAs/SM ===================
// C[M,N] = A[M,K] @ Bt[N,K]^T + bias (+res).
// LO=true: hi/lo bf16 split (3 MMAs). LO=false: single bf16 (1 MMA, half traffic).
#define MG_PAD    40
#define SA_BYTES  (128 * MG_PAD * 2)
#define SB_BYTES  (64 * MG_PAD * 2)
#define OFF_AL    SA_BYTES
#define OFF_BH    (2 * SA_BYTES)
#define OFF_BL    (2 * SA_BYTES + SB_BYTES)
#define ST_BYTES  (2 * SA_BYTES + 2 * SB_BYTES)   // 30720 B per stage
#define NSTAGE    3
#define G_SMEM    (NSTAGE * ST_BYTES)             // 92160 B

template<bool LO>
__global__ __launch_bounds__(256, 2) void mma_gemm_kernel(
    const __nv_bfloat16* __restrict__ Ahi, const __nv_bfloat16* __restrict__ Alo,
    const __nv_bfloat16* __restrict__ Bhi, const __nv_bfloat16* __restrict__ Blo,
    const float* __restrict__ bias, const float* __restrict__ bias2,
    const float* __restrict__ res,
    float* __restrict__ Cf, __nv_bfloat16* __restrict__ Cb,
    __nv_bfloat16* __restrict__ Cb2,
    int M, int N, int K, int Nh)
{
    extern __shared__ __nv_bfloat16 smem[];
    uint32_t sbase = smem_u32(smem);

    int tid = threadIdx.x, lane = tid & 31, wid = tid >> 5;
    int brow = blockIdx.y, bcol = blockIdx.x;
    int warp_m = (wid >> 1) * 32;
    int warp_n = (wid & 1) * 32;

    int a_row = tid >> 2;
    int l_ch  = tid & 3;
    int b_row = tid >> 2;
    const __nv_bfloat16* Aat = Ahi + (size_t)(brow * 128) * K;
    const __nv_bfloat16* Aal = Alo + (size_t)(brow * 128) * K;
    const __nv_bfloat16* Bbt = Bhi + (size_t)(bcol * 64) * K;
    const __nv_bfloat16* Bbl = Blo + (size_t)(bcol * 64) * K;

    float acc[2][4][4];
    #pragma unroll
    for (int t = 0; t < 2; t++)
        #pragma unroll
        for (int nt = 0; nt < 4; nt++)
            #pragma unroll
            for (int j = 0; j < 4; j++) acc[t][nt][j] = 0.0f;

    int nchunk = K >> 5;

    #pragma unroll
    for (int p = 0; p < 2; p++) {
        uint32_t stb = sbase + p * ST_BYTES;
        #pragma unroll
        for (int it = 0; it < 2; it++) {
            int row = a_row + it * 64;
            uint32_t so = stb + (uint32_t)(row * MG_PAD + l_ch * 8) * 2;
            size_t go = (size_t)row * K + p * 32 + l_ch * 8;
            cp16(so, Aat + go);
            if (LO) cp16(so + OFF_AL, Aal + go);
        }
        {
            uint32_t so = stb + (uint32_t)(b_row * MG_PAD + l_ch * 8) * 2;
            size_t go = (size_t)b_row * K + p * 32 + l_ch * 8;
            cp16(so + OFF_BH, Bbt + go);
            if (LO) cp16(so + OFF_BL, Bbl + go);
        }
        CP_COMMIT();
    }

    int stage = 0;
    for (int c = 0; c < nchunk; c++) {
        CP_WAIT1();
        __syncthreads();

        if (c + 2 < nchunk) {
            int ns = stage + 2; if (ns >= 3) ns -= 3;
            uint32_t stb = sbase + ns * ST_BYTES;
            #pragma unroll
            for (int it = 0; it < 2; it++) {
                int row = a_row + it * 64;
                uint32_t so = stb + (uint32_t)(row * MG_PAD + l_ch * 8) * 2;
                size_t go = (size_t)row * K + (c + 2) * 32 + l_ch * 8;
                cp16(so, Aat + go);
                if (LO) cp16(so + OFF_AL, Aal + go);
            }
            {
                uint32_t so = stb + (uint32_t)(b_row * MG_PAD + l_ch * 8) * 2;
                size_t go = (size_t)b_row * K + (c + 2) * 32 + l_ch * 8;
                cp16(so + OFF_BH, Bbt + go);
                if (LO) cp16(so + OFF_BL, Bbl + go);
            }
        }
        CP_COMMIT();

        uint32_t sa_h = sbase + stage * ST_BYTES;
        uint32_t sa_l = sa_h + OFF_AL;
        uint32_t sb_h = sa_h + OFF_BH;
        uint32_t sb_l = sa_h + OFF_BL;

        #pragma unroll
        for (int ks = 0; ks < 2; ks++) {
            int kk = ks * 16;
            uint32_t ah[2][4], al[2][4];
            #pragma unroll
            for (int t = 0; t < 2; t++) {
                uint32_t off = (uint32_t)((warp_m + t * 16 + (lane & 15)) * MG_PAD
                             + kk + ((lane >> 4) << 3)) * 2;
                LDSM4(ah[t], sa_h + off);
                if (LO) LDSM4(al[t], sa_l + off);
            }
            uint32_t bh[4][2], bl[4][2];
            #pragma unroll
            for (int p = 0; p < 2; p++) {
                uint32_t off = (uint32_t)((warp_n + p * 16 + ((lane >> 3) & 1) * 8 + (lane & 7)) * MG_PAD
                             + kk + ((lane >> 4) << 3)) * 2;
                uint32_t r[4];
                LDSM4(r, sb_h + off);
                bh[2*p][0] = r[0]; bh[2*p][1] = r[2];
                bh[2*p+1][0] = r[1]; bh[2*p+1][1] = r[3];
                if (LO) {
                    LDSM4(r, sb_l + off);
                    bl[2*p][0] = r[0]; bl[2*p][1] = r[2];
                    bl[2*p+1][0] = r[1]; bl[2*p+1][1] = r[3];
                }
            }
            #pragma unroll
            for (int t = 0; t < 2; t++)
                #pragma unroll
                for (int nt = 0; nt < 4; nt++) {
                    mma_bf16(acc[t][nt], ah[t], bh[nt]);
                    if (LO) {
                        mma_bf16(acc[t][nt], ah[t], bl[nt]);
                        mma_bf16(acc[t][nt], al[t], bh[nt]);
                    }
                }
        }
        stage++; if (stage >= 3) stage = 0;
    }

    int r0 = lane >> 2, c0 = (lane & 3) * 2;
    #pragma unroll
    for (int t = 0; t < 2; t++) {
        #pragma unroll
        for (int half = 0; half < 2; half++) {
            int grow = brow * 128 + warp_m + t * 16 + r0 + half * 8;
            #pragma unroll
            for (int nt = 0; nt < 4; nt++) {
                int gcol = bcol * 64 + warp_n + nt * 8 + c0;
                float ox = acc[t][nt][half * 2 + 0];
                float oy = acc[t][nt][half * 2 + 1];
                if (Cb2) {
                    __nv_bfloat16* dst; const float* bs; int cc;
                    if (gcol < Nh) { dst = Cb; bs = bias; cc = gcol; }
                    else           { dst = Cb2; bs = bias2; cc = gcol - Nh; }
                    ox += bs[cc]; oy += bs[cc + 1];
                    *(__nv_bfloat162*)(dst + (size_t)grow * Nh + cc) =
                        __floats2bfloat162_rn(ox, oy);
                } else if (Cb) {
                    ox += bias[gcol]; oy += bias[gcol + 1];
                    *(__nv_bfloat162*)(Cb + (size_t)grow * N + gcol) =
                        __floats2bfloat162_rn(ox, oy);
                } else {
                    ox += bias[gcol]; oy += bias[gcol + 1];
                    if (res) {
                        float2 rv = *(const float2*)(res + (size_t)grow * N + gcol);
                        ox += rv.x; oy += rv.y;
                    }
                    float2 o; o.x = ox; o.y = oy;
                    *(float2*)(Cf + (size_t)grow * N + gcol) = o;
                }
            }
        }
    }
}

// =================== HMMA flash attention (writes hi/lo split output) ===================
#define FB_BQ 64
#define FB_BK 64
#define FB_PAD 72

__global__ __launch_bounds__(128) void flash_mma_kernel(
    const __nv_bfloat16* __restrict__ Qb, const __nv_bfloat16* __restrict__ Vb,
    const float* __restrict__ AA,
    __nv_bfloat16* __restrict__ Ohi, __nv_bfloat16* __restrict__ Olo)
{
    __shared__ __nv_bfloat16 sQ[FB_BQ * FB_PAD];
    __shared__ __nv_bfloat16 sK[FB_BK * FB_PAD];
    __shared__ __nv_bfloat16 sV[FB_BK * FB_PAD];
    __shared__ float sAA[FB_BK];

    int b = blockIdx.z, h = blockIdx.y;
    int q0 = blockIdx.x * FB_BQ;
    int tid = threadIdx.x, lane = tid & 31, w = tid >> 5;

    uint32_t sq_a = smem_u32(sQ), sk_a = smem_u32(sK), sv_a = smem_u32(sV);

    #pragma unroll
    for (int i = 0; i < 4; i++) {
        int idx = tid + i * 128;
        int r = idx >> 3, c = idx & 7;
        size_t off = (size_t)(b * NSEQ + q0 + r) * DIM + h * DHEAD + c * 8;
        *(uint4*)&sQ[r * FB_PAD + c * 8] = *(const uint4*)(Qb + off);
    }
    __syncthreads();

    uint32_t qa[4][4];
    #pragma unroll
    for (int ks = 0; ks < 4; ks++) {
        uint32_t off = (uint32_t)((w * 16 + (lane & 15)) * FB_PAD + ks * 16 + ((lane >> 4) << 3)) * 2;
        LDSM4(qa[ks], sq_a + off);
    }

    float m0 = -1e30f, m1 = -1e30f, l0 = 0.0f, l1 = 0.0f;
    float o[8][4];
    #pragma unroll
    for (int t = 0; t < 8; t++)
        #pragma unroll
        for (int j = 0; j < 4; j++) o[t][j] = 0.0f;

    const float* aab = AA + ((size_t)(b * NHEAD + h)) * NSEQ;

    for (int kt = 0; kt < NSEQ; kt += FB_BK) {
        __syncthreads();
        #pragma unroll
        for (int i = 0; i < 4; i++) {
            int idx = tid + i * 128;
            int r = idx >> 3, c = idx & 7;
            size_t off = (size_t)(b * NSEQ + kt + r) * DIM + h * DHEAD + c * 8;
            *(uint4*)&sK[r * FB_PAD + c * 8] = *(const uint4*)(Qb + off);
            *(uint4*)&sV[r * FB_PAD + c * 8] = *(const uint4*)(Vb + off);
        }
        if (tid < FB_BK) sAA[tid] = aab[kt + tid];
        __syncthreads();

        float sc[8][4];
        #pragma unroll
        for (int t = 0; t < 8; t++)
            #pragma unroll
            for (int j = 0; j < 4; j++) sc[t][j] = 0.0f;

        #pragma unroll
        for (int ks = 0; ks < 4; ks++) {
            uint32_t kb[8][2];
            #pragma unroll
            for (int p = 0; p < 4; p++) {
                uint32_t off = (uint32_t)((p * 16 + ((lane >> 3) & 1) * 8 + (lane & 7)) * FB_PAD
                             + ks * 16 + ((lane >> 4) << 3)) * 2;
                uint32_t r[4];
                LDSM4(r, sk_a + off);
                kb[2*p][0] = r[0]; kb[2*p][1] = r[2];
                kb[2*p+1][0] = r[1]; kb[2*p+1][1] = r[3];
            }
            #pragma unroll
            for (int t = 0; t < 8; t++) mma_bf16(sc[t], qa[ks], kb[t]);
        }

        float mt0 = -1e30f, mt1 = -1e30f;
        #pragma unroll
        for (int t = 0; t < 8; t++) {
            float a0 = sAA[t * 8 + (lane & 3) * 2];
            float a1 = sAA[t * 8 + (lane & 3) * 2 + 1];
            sc[t][0] = 0.25f * sc[t][0] - 0.125f * a0;
            sc[t][1] = 0.25f * sc[t][1] - 0.125f * a1;
            sc[t][2] = 0.25f * sc[t][2] - 0.125f * a0;
            sc[t][3] = 0.25f * sc[t][3] - 0.125f * a1;
            mt0 = fmaxf(mt0, fmaxf(sc[t][0], sc[t][1]));
            mt1 = fmaxf(mt1, fmaxf(sc[t][2], sc[t][3]));
        }
        mt0 = fmaxf(mt0, __shfl_xor_sync(0xffffffffu, mt0, 1));
        mt0 = fmaxf(mt0, __shfl_xor_sync(0xffffffffu, mt0, 2));
        mt1 = fmaxf(mt1, __shfl_xor_sync(0xffffffffu, mt1, 1));
        mt1 = fmaxf(mt1, __shfl_xor_sync(0xffffffffu, mt1, 2));

        float mn0 = fmaxf(m0, mt0), mn1 = fmaxf(m1, mt1);
        float al0 = __expf(m0 - mn0), al1 = __expf(m1 - mn1);
        m0 = mn0; m1 = mn1;
        l0 *= al0; l1 *= al1;
        #pragma unroll
        for (int t = 0; t < 8; t++) {
            o[t][0] *= al0; o[t][1] *= al0;
            o[t][2] *= al1; o[t][3] *= al1;
        }

        #pragma unroll
        for (int t = 0; t < 8; t++) {
            sc[t][0] = __expf(sc[t][0] - m0);
            sc[t][1] = __expf(sc[t][1] - m0);
            sc[t][2] = __expf(sc[t][2] - m1);
            sc[t][3] = __expf(sc[t][3] - m1);
            l0 += sc[t][0] + sc[t][1];
            l1 += sc[t][2] + sc[t][3];
        }

        #pragma unroll
        for (int j = 0; j < 4; j++) {
            uint32_t pa[4];
            __nv_bfloat162 t2;
            t2 = __floats2bfloat162_rn(sc[2*j][0],   sc[2*j][1]);   pa[0] = *(uint32_t*)&t2;
            t2 = __floats2bfloat162_rn(sc[2*j][2],   sc[2*j][3]);   pa[1] = *(uint32_t*)&t2;
            t2 = __floats2bfloat162_rn(sc[2*j+1][0], sc[2*j+1][1]); pa[2] = *(uint32_t*)&t2;
            t2 = __floats2bfloat162_rn(sc[2*j+1][2], sc[2*j+1][3]); pa[3] = *(uint32_t*)&t2;

            uint32_t vb[8][2];
            #pragma unroll
            for (int dp = 0; dp < 4; dp++) {
                int g = lane >> 3, rr = lane & 7;
                uint32_t off = (uint32_t)((j * 16 + (g & 1) * 8 + rr) * FB_PAD
                             + dp * 16 + (g >> 1) * 8) * 2;
                uint32_t r[4];
                LDSM4T(r, sv_a + off);
                vb[2*dp][0]   = r[0]; vb[2*dp][1]   = r[1];
                vb[2*dp+1][0] = r[2]; vb[2*dp+1][1] = r[3];
            }
            #pragma unroll
            for (int t = 0; t < 8; t++) mma_bf16(o[t], pa, vb[t]);
        }
    }

    l0 += __shfl_xor_sync(0xffffffffu, l0, 1);
    l0 += __shfl_xor_sync(0xffffffffu, l0, 2);
    l1 += __shfl_xor_sync(0xffffffffu, l1, 1);
    l1 += __shfl_xor_sync(0xffffffffu, l1, 2);
    float inv0 = 1.0f / l0, inv1 = 1.0f / l1;

    int r0g = q0 + w * 16 + (lane >> 2);
    #pragma unroll
    for (int t = 0; t < 8; t++) {
        int c = h * DHEAD + t * 8 + (lane & 3) * 2;
        float o00 = o[t][0] * inv0, o01 = o[t][1] * inv0;
        float o10 = o[t][2] * inv1, o11 = o[t][3] * inv1;
        size_t off0 = (size_t)(b * NSEQ + r0g) * DIM + c;
        size_t off1 = (size_t)(b * NSEQ + r0g + 8) * DIM + c;
        __nv_bfloat162 h0 = __floats2bfloat162_rn(o00, o01);
        __nv_bfloat162 h1 = __floats2bfloat162_rn(o10, o11);
        *(__nv_bfloat162*)(Ohi + off0) = h0;
        *(__nv_bfloat162*)(Ohi + off1) = h1;
        *(__nv_bfloat162*)(Olo + off0) = __floats2bfloat162_rn(
            o00 - __bfloat162float(h0.x), o01 - __bfloat162float(h0.y));
        *(__nv_bfloat162*)(Olo + off1) = __floats2bfloat162_rn(
            o10 - __bfloat162float(h1.x), o11 - __bfloat162float(h1.y));
    }
}

// ---------------- fused LayerNorm + hi/lo split ----------------
__global__ __launch_bounds__(128) void ln_split_kernel(
    const float* __restrict__ X, const float* __restrict__ w,
    const float* __restrict__ bb, __nv_bfloat16* __restrict__ Hi,
    __nv_bfloat16* __restrict__ Lo)
{
    int row = blockIdx.x;
    int tid = threadIdx.x;
    const float* xp = X + (size_t)row * DIM;
    float4 v = *(const float4*)(xp + tid * 4);
    float s  = v.x + v.y + v.z + v.w;
    float sq = v.x*v.x + v.y*v.y + v.z*v.z + v.w*v.w;
    #pragma unroll
    for (int o = 16; o > 0; o >>= 1) {
        s  += __shfl_xor_sync(0xffffffffu, s,  o);
        sq += __shfl_xor_sync(0xffffffffu, sq, o);
    }
    __shared__ float reds[4], redq[4];
    int wid = tid >> 5, lane = tid & 31;
    if (lane == 0) { reds[wid] = s; redq[wid] = sq; }
    __syncthreads();
    s  = reds[0] + reds[1] + reds[2] + reds[3];
    sq = redq[0] + redq[1] + redq[2] + redq[3];
    float mu   = s * (1.0f / DIM);
    float var  = sq * (1.0f / DIM) - mu * mu;
    float rstd = rsqrtf(var + 1e-5f);
    float4 wv = *(const float4*)(w  + tid * 4);
    float4 bv = *(const float4*)(bb + tid * 4);
    float o0 = (v.x - mu) * rstd * wv.x + bv.x;
    float o1 = (v.y - mu) * rstd * wv.y + bv.y;
    float o2 = (v.z - mu) * rstd * wv.z + bv.z;
    float o3 = (v.w - mu) * rstd * wv.w + bv.w;
    __nv_bfloat162 h0 = __floats2bfloat162_rn(o0, o1);
    __nv_bfloat162 h1 = __floats2bfloat162_rn(o2, o3);
    __nv_bfloat162 l0 = __floats2bfloat162_rn(o0 - __bfloat162float(h0.x),
                                              o1 - __bfloat162float(h0.y));
    __nv_bfloat162 l1 = __floats2bfloat162_rn(o2 - __bfloat162float(h1.x),
                                              o3 - __bfloat162float(h1.y));
    size_t off = (size_t)row * DIM + tid * 4;
    *(__nv_bfloat162*)(Hi + off) = h0;
    *(__nv_bfloat162*)(Hi + off + 2) = h1;
    *(__nv_bfloat162*)(Lo + off) = l0;
    *(__nv_bfloat162*)(Lo + off + 2) = l1;
}

// ---------------- weight transpose+split ----------------
__global__ __launch_bounds__(256) void conv_wt_kernel(
    const float* __restrict__ W, __nv_bfloat16* __restrict__ Thi,
    __nv_bfloat16* __restrict__ Tlo, int K, int N)
{
    __shared__ __nv_bfloat16 shi[32][33];
    __shared__ __nv_bfloat16 slo[32][33];
    int tx = threadIdx.x & 31, ty = threadIdx.x >> 5;
    int n0 = blockIdx.x * 32, k0 = blockIdx.y * 32;
    #pragma unroll
    for (int j = 0; j < 4; j++) {
        int k = ty + j * 8;
        float v = W[(size_t)(k0 + k) * N + n0 + tx];
        __nv_bfloat16 h = __float2bfloat16_rn(v);
        shi[k][tx] = h;
        slo[k][tx] = __float2bfloat16_rn(v - __bfloat162float(h));
    }
    __syncthreads();
    #pragma unroll
    for (int j = 0; j < 4; j++) {
        int n = ty + j * 8;
        Thi[(size_t)(n0 + n) * K + k0 + tx] = shi[tx][n];
        Tlo[(size_t)(n0 + n) * K + k0 + tx] = slo[tx][n];
    }
}

// ---------------- AA_j = |q_j|^2 from bf16 q ----------------
__global__ void aa_kernel(const __nv_bfloat16* __restrict__ Qb, float* __restrict__ AA)
{
    int idx = blockIdx.x * blockDim.x + threadIdx.x;
    if (idx >= ROWS * NHEAD) return;
    int h = idx & 7;
    int row = idx >> 3;
    const uint4* qp = (const uint4*)(Qb + (size_t)row * DIM + h * DHEAD);
    float s = 0.0f;
    #pragma unroll
    for (int i = 0; i < 8; i++) {
        uint4 u = qp[i];
        const __nv_bfloat162* p = (const __nv_bfloat162*)&u;
        #pragma unroll
        for (int j = 0; j < 4; j++) {
            float2 f = __bfloat1622float2(p[j]);
            s += f.x * f.x + f.y * f.y;
        }
    }
    int b = row >> 11, n = row & 2047;
    AA[((size_t)(b * NHEAD + h)) * NSEQ + n] = s;
}

// ---------------- GEGLU + hi/lo split ----------------
__device__ __forceinline__ float gelu_exact(float x) {
    return 0.5f * x * (1.0f + erff(x * 0.70710678118654752f));
}
__global__ void geglu_split_kernel(const float* __restrict__ H,
                                   __nv_bfloat16* __restrict__ Hi,
                                   __nv_bfloat16* __restrict__ Lo)
{
    int idx = blockIdx.x * blockDim.x + threadIdx.x;
    if (idx >= ROWS * (IFF / 4)) return;
    int row = idx / (IFF / 4);
    int c4  = idx % (IFF / 4);
    const float* base = H + (size_t)row * (2 * IFF);
    float4 a  = *(const float4*)(base + c4 * 4);
    float4 gt = *(const float4*)(base + IFF + c4 * 4);
    float r0 = a.x * gelu_exact(gt.x);
    float r1 = a.y * gelu_exact(gt.y);
    float r2 = a.z * gelu_exact(gt.z);
    float r3 = a.w * gelu_exact(gt.w);
    __nv_bfloat162 h0 = __floats2bfloat162_rn(r0, r1);
    __nv_bfloat162 h1 = __floats2bfloat162_rn(r2, r3);
    __nv_bfloat162 l0 = __floats2bfloat162_rn(r0 - __bfloat162float(h0.x),
                                              r1 - __bfloat162float(h0.y));
    __nv_bfloat162 l1 = __floats2bfloat162_rn(r2 - __bfloat162float(h1.x),
                                              r3 - __bfloat162float(h1.y));
    size_t off = (size_t)row * IFF + c4 * 4;
    *(__nv_bfloat162*)(Hi + off) = h0;
    *(__nv_bfloat162*)(Hi + off + 2) = h1;
    *(__nv_bfloat162*)(Lo + off) = l0;
    *(__nv_bfloat162*)(Lo + off + 2) = l1;
}

// ---------------- host orchestration ----------------
struct Bufs {
    float *x1, *x2, *aa, *hh;
    __nv_bfloat16 *ahi, *alo, *whi, *wlo, *qb, *vb;
};

static void conv_wt(const float* W, __nv_bfloat16* hi, __nv_bfloat16* lo, int K, int N) {
    dim3 grid(N / 32, K / 32);
    conv_wt_kernel<<<grid, 256>>>(W, hi, lo, K, N);
}
// hi/lo 3-MMA GEMM (residual-stream writers)
static void tc_gemm_f32_lo(const Bufs& B, const float* bias, const float* res,
                           float* C, int M, int N, int K) {
    dim3 grid(N / 64, M / 128);
    mma_gemm_kernel<true><<<grid, 256, G_SMEM>>>(B.ahi, B.alo, B.whi, B.wlo, bias, nullptr,
                                                 res, C, nullptr, nullptr, M, N, K, 0);
}
// single-bf16 GEMM (diluted paths)
static void tc_gemm_f32_1x(const Bufs& B, const float* bias, const float* res,
                           float* C, int M, int N, int K) {
    dim3 grid(N / 64, M / 128);
    mma_gemm_kernel<false><<<grid, 256, G_SMEM>>>(B.ahi, B.alo, B.whi, B.wlo, bias, nullptr,
                                                  res, C, nullptr, nullptr, M, N, K, 0);
}
static void tc_gemm_qv(const Bufs& B, const float* bq, const float* bv,
                       int M, int K) {
    dim3 grid(1024 / 64, M / 128);
    mma_gemm_kernel<false><<<grid, 256, G_SMEM>>>(B.ahi, B.alo, B.whi, B.wlo, bq, bv,
                                                  nullptr, nullptr, B.qb, B.vb,
                                                  M, 1024, K, 512);
}
static void run_attention(const Bufs& B) {
    int aa_blocks = (ROWS * NHEAD + 255) / 256;
    aa_kernel<<<aa_blocks, 256>>>(B.qb, B.aa);
    dim3 fa_grid(NSEQ / FB_BQ, NHEAD, NBATCH);
    flash_mma_kernel<<<fa_grid, 128>>>(B.qb, B.vb, B.aa, B.ahi, B.alo);
}

extern "C" void kernel_launch(void* const* d_in, const int* in_sizes, int n_in,
                              void* d_out, int out_size)
{
    const float* x     = (const float*)d_in[0];
    const float* sa_w  = (const float*)d_in[1];
    const float* sa_b  = (const float*)d_in[2];
    const float* ca_w  = (const float*)d_in[3];
    const float* ca_b  = (const float*)d_in[4];
    const float* ff_nw = (const float*)d_in[5];
    const float* ff_nb = (const float*)d_in[6];
    const float* a1_wq = (const float*)d_in[7];
    const float* a1_bq = (const float*)d_in[8];
    const float* a1_wv = (const float*)d_in[9];
    const float* a1_bv = (const float*)d_in[10];
    const float* a1_wo = (const float*)d_in[11];
    const float* a1_bo = (const float*)d_in[12];
    const float* a2_wq = (const float*)d_in[13];
    const float* a2_bq = (const float*)d_in[14];
    const float* a2_wv = (const float*)d_in[15];
    const float* a2_bv = (const float*)d_in[16];
    const float* a2_wo = (const float*)d_in[17];
    const float* a2_bo = (const float*)d_in[18];
    const float* ff_w1 = (const float*)d_in[19];
    const float* ff_b1 = (const float*)d_in[20];
    const float* ff_w2 = (const float*)d_in[21];
    const float* ff_b2 = (const float*)d_in[22];
    float* out = (float*)d_out;

    Bufs B;
    cudaGetSymbolAddress((void**)&B.x1,  g_x1);
    cudaGetSymbolAddress((void**)&B.x2,  g_x2);
    cudaGetSymbolAddress((void**)&B.aa,  g_aa);
    cudaGetSymbolAddress((void**)&B.hh,  g_h);
    cudaGetSymbolAddress((void**)&B.ahi, g_ahi);
    cudaGetSymbolAddress((void**)&B.alo, g_alo);
    cudaGetSymbolAddress((void**)&B.whi, g_whi);
    cudaGetSymbolAddress((void**)&B.wlo, g_wlo);
    cudaGetSymbolAddress((void**)&B.qb,  g_qb);
    cudaGetSymbolAddress((void**)&B.vb,  g_vb);

    cudaFuncSetAttribute(mma_gemm_kernel<true>,
                         cudaFuncAttributeMaxDynamicSharedMemorySize, G_SMEM);
    cudaFuncSetAttribute(mma_gemm_kernel<false>,
                         cudaFuncAttributeMaxDynamicSharedMemorySize, G_SMEM);

    // ---- self-attention (attn1) ----
    ln_split_kernel<<<ROWS, 128>>>(x, sa_w, sa_b, B.ahi, B.alo);
    conv_wt(a1_wq, B.whi, B.wlo, DIM, DIM);
    conv_wt(a1_wv, B.whi + DIM * DIM, B.wlo + DIM * DIM, DIM, DIM);
    tc_gemm_qv(B, a1_bq, a1_bv, ROWS, DIM);            // single bf16
    run_attention(B);
    conv_wt(a1_wo, B.whi, B.wlo, DIM, DIM);
    tc_gemm_f32_lo(B, a1_bo, x, B.x1, ROWS, DIM, DIM); // hi/lo

    // ---- attn2 (k=q, v from x) ----
    ln_split_kernel<<<ROWS, 128>>>(B.x1, ca_w, ca_b, B.ahi, B.alo);
    conv_wt(a2_wq, B.whi, B.wlo, DIM, DIM);
    conv_wt(a2_wv, B.whi + DIM * DIM, B.wlo + DIM * DIM, DIM, DIM);
    tc_gemm_qv(B, a2_bq, a2_bv, ROWS, DIM);            // single bf16
    run_attention(B);
    conv_wt(a2_wo, B.whi, B.wlo, DIM, DIM);
    tc_gemm_f32_lo(B, a2_bo, B.x1, B.x2, ROWS, DIM, DIM); // hi/lo

    // ---- GEGLU FFN ----
    ln_split_kernel<<<ROWS, 128>>>(B.x2, ff_nw, ff_nb, B.ahi, B.alo);
    conv_wt(ff_w1, B.whi, B.wlo, DIM, 2 * IFF);
    tc_gemm_f32_1x(B, ff_b1, nullptr, B.hh, ROWS, 2 * IFF, DIM);  // single bf16
    int ge_blocks = (ROWS * (IFF / 4) + 255) / 256;
    geglu_split_kernel<<<ge_blocks, 256>>>(B.hh, B.ahi, B.alo);
    conv_wt(ff_w2, B.whi, B.wlo, IFF, DIM);
    tc_gemm_f32_lo(B, ff_b2, B.x2, out, ROWS, DIM, IFF);          // hi/lo
}

// round 13
// speedup vs baseline: 6.2905x; 1.0969x over previous
#include <cuda_runtime.h>
#include <cuda_bf16.h>
#include <cstdint>
#include <math.h>

#define ROWS 8192
#define DIM  512
#define NSEQ 2048
#define NBATCH 4
#define NHEAD 8
#define DHEAD 64
#define IFF  2048

// ---------------- scratch ----------------
__device__ float g_x1 [ROWS * DIM];
__device__ float g_x2 [ROWS * DIM];
__device__ float g_aa [NBATCH * NHEAD * NSEQ];
__device__ float g_h  [ROWS * 2 * IFF];        // FF1 out; reused as bf16 buffer
__device__ __nv_bfloat16 g_ahi[ROWS * IFF];
__device__ __nv_bfloat16 g_alo[ROWS * IFF];
__device__ __nv_bfloat16 g_whi[4096 * 512];
__device__ __nv_bfloat16 g_wlo[4096 * 512];
__device__ __nv_bfloat16 g_qb[ROWS * DIM];
__device__ __nv_bfloat16 g_vb[ROWS * DIM];

// =================== helpers ===================
__device__ __forceinline__ uint32_t smem_u32(const void* p) {
    uint32_t a;
    asm("{ .reg .u64 t; cvta.to.shared.u64 t, %1; cvt.u32.u64 %0, t; }" : "=r"(a) : "l"(p));
    return a;
}
#define LDSM4(r, addr) \
    asm volatile("ldmatrix.sync.aligned.m8n8.x4.shared.b16 {%0,%1,%2,%3}, [%4];" \
        : "=r"((r)[0]), "=r"((r)[1]), "=r"((r)[2]), "=r"((r)[3]) : "r"(addr))
#define LDSM4T(r, addr) \
    asm volatile("ldmatrix.sync.aligned.m8n8.x4.trans.shared.b16 {%0,%1,%2,%3}, [%4];" \
        : "=r"((r)[0]), "=r"((r)[1]), "=r"((r)[2]), "=r"((r)[3]) : "r"(addr))

__device__ __forceinline__ void mma_bf16(float* d, const uint32_t* a, const uint32_t* b) {
    asm volatile("mma.sync.aligned.m16n8k16.row.col.f32.bf16.bf16.f32 "
        "{%0,%1,%2,%3}, {%4,%5,%6,%7}, {%8,%9}, {%0,%1,%2,%3};"
        : "+f"(d[0]), "+f"(d[1]), "+f"(d[2]), "+f"(d[3])
        : "r"(a[0]), "r"(a[1]), "r"(a[2]), "r"(a[3]), "r"(b[0]), "r"(b[1]));
}
__device__ __forceinline__ void cp16(uint32_t saddr, const void* g) {
    asm volatile("cp.async.cg.shared.global [%0], [%1], 16;" :: "r"(saddr), "l"(g));
}
#define CP_COMMIT() asm volatile("cp.async.commit_group;" ::: "memory")
#define CP_WAIT1()  asm volatile("cp.async.wait_group 1;" ::: "memory")

// =================== cp.async HMMA GEMM, 128x64 tile, 2 CTAs/SM ===================
#define MG_PAD    40
#define SA_BYTES  (128 * MG_PAD * 2)
#define SB_BYTES  (64 * MG_PAD * 2)
#define OFF_AL    SA_BYTES
#define OFF_BH    (2 * SA_BYTES)
#define OFF_BL    (2 * SA_BYTES + SB_BYTES)
#define ST_BYTES  (2 * SA_BYTES + 2 * SB_BYTES)
#define NSTAGE    3
#define G_SMEM    (NSTAGE * ST_BYTES)

template<bool LO>
__global__ __launch_bounds__(256, 2) void mma_gemm_kernel(
    const __nv_bfloat16* __restrict__ Ahi, const __nv_bfloat16* __restrict__ Alo,
    const __nv_bfloat16* __restrict__ Bhi, const __nv_bfloat16* __restrict__ Blo,
    const float* __restrict__ bias, const float* __restrict__ bias2,
    const float* __restrict__ res,
    float* __restrict__ Cf, __nv_bfloat16* __restrict__ Cb,
    __nv_bfloat16* __restrict__ Cb2,
    int M, int N, int K, int Nh)
{
    extern __shared__ __nv_bfloat16 smem[];
    uint32_t sbase = smem_u32(smem);

    int tid = threadIdx.x, lane = tid & 31, wid = tid >> 5;
    int brow = blockIdx.y, bcol = blockIdx.x;
    int warp_m = (wid >> 1) * 32;
    int warp_n = (wid & 1) * 32;

    int a_row = tid >> 2;
    int l_ch  = tid & 3;
    int b_row = tid >> 2;
    const __nv_bfloat16* Aat = Ahi + (size_t)(brow * 128) * K;
    const __nv_bfloat16* Aal = Alo + (size_t)(brow * 128) * K;
    const __nv_bfloat16* Bbt = Bhi + (size_t)(bcol * 64) * K;
    const __nv_bfloat16* Bbl = Blo + (size_t)(bcol * 64) * K;

    float acc[2][4][4];
    #pragma unroll
    for (int t = 0; t < 2; t++)
        #pragma unroll
        for (int nt = 0; nt < 4; nt++)
            #pragma unroll
            for (int j = 0; j < 4; j++) acc[t][nt][j] = 0.0f;

    int nchunk = K >> 5;

    #pragma unroll
    for (int p = 0; p < 2; p++) {
        uint32_t stb = sbase + p * ST_BYTES;
        #pragma unroll
        for (int it = 0; it < 2; it++) {
            int row = a_row + it * 64;
            uint32_t so = stb + (uint32_t)(row * MG_PAD + l_ch * 8) * 2;
            size_t go = (size_t)row * K + p * 32 + l_ch * 8;
            cp16(so, Aat + go);
            if (LO) cp16(so + OFF_AL, Aal + go);
        }
        {
            uint32_t so = stb + (uint32_t)(b_row * MG_PAD + l_ch * 8) * 2;
            size_t go = (size_t)b_row * K + p * 32 + l_ch * 8;
            cp16(so + OFF_BH, Bbt + go);
            if (LO) cp16(so + OFF_BL, Bbl + go);
        }
        CP_COMMIT();
    }

    int stage = 0;
    for (int c = 0; c < nchunk; c++) {
        CP_WAIT1();
        __syncthreads();

        if (c + 2 < nchunk) {
            int ns = stage + 2; if (ns >= 3) ns -= 3;
            uint32_t stb = sbase + ns * ST_BYTES;
            #pragma unroll
            for (int it = 0; it < 2; it++) {
                int row = a_row + it * 64;
                uint32_t so = stb + (uint32_t)(row * MG_PAD + l_ch * 8) * 2;
                size_t go = (size_t)row * K + (c + 2) * 32 + l_ch * 8;
                cp16(so, Aat + go);
                if (LO) cp16(so + OFF_AL, Aal + go);
            }
            {
                uint32_t so = stb + (uint32_t)(b_row * MG_PAD + l_ch * 8) * 2;
                size_t go = (size_t)b_row * K + (c + 2) * 32 + l_ch * 8;
                cp16(so + OFF_BH, Bbt + go);
                if (LO) cp16(so + OFF_BL, Bbl + go);
            }
        }
        CP_COMMIT();

        uint32_t sa_h = sbase + stage * ST_BYTES;
        uint32_t sa_l = sa_h + OFF_AL;
        uint32_t sb_h = sa_h + OFF_BH;
        uint32_t sb_l = sa_h + OFF_BL;

        #pragma unroll
        for (int ks = 0; ks < 2; ks++) {
            int kk = ks * 16;
            uint32_t ah[2][4], al[2][4];
            #pragma unroll
            for (int t = 0; t < 2; t++) {
                uint32_t off = (uint32_t)((warp_m + t * 16 + (lane & 15)) * MG_PAD
                             + kk + ((lane >> 4) << 3)) * 2;
                LDSM4(ah[t], sa_h + off);
                if (LO) LDSM4(al[t], sa_l + off);
            }
            uint32_t bh[4][2], bl[4][2];
            #pragma unroll
            for (int p = 0; p < 2; p++) {
                uint32_t off = (uint32_t)((warp_n + p * 16 + ((lane >> 3) & 1) * 8 + (lane & 7)) * MG_PAD
                             + kk + ((lane >> 4) << 3)) * 2;
                uint32_t r[4];
                LDSM4(r, sb_h + off);
                bh[2*p][0] = r[0]; bh[2*p][1] = r[2];
                bh[2*p+1][0] = r[1]; bh[2*p+1][1] = r[3];
                if (LO) {
                    LDSM4(r, sb_l + off);
                    bl[2*p][0] = r[0]; bl[2*p][1] = r[2];
                    bl[2*p+1][0] = r[1]; bl[2*p+1][1] = r[3];
                }
            }
            #pragma unroll
            for (int t = 0; t < 2; t++)
                #pragma unroll
                for (int nt = 0; nt < 4; nt++) {
                    mma_bf16(acc[t][nt], ah[t], bh[nt]);
                    if (LO) {
                        mma_bf16(acc[t][nt], ah[t], bl[nt]);
                        mma_bf16(acc[t][nt], al[t], bh[nt]);
                    }
                }
        }
        stage++; if (stage >= 3) stage = 0;
    }

    int r0 = lane >> 2, c0 = (lane & 3) * 2;
    #pragma unroll
    for (int t = 0; t < 2; t++) {
        #pragma unroll
        for (int half = 0; half < 2; half++) {
            int grow = brow * 128 + warp_m + t * 16 + r0 + half * 8;
            #pragma unroll
            for (int nt = 0; nt < 4; nt++) {
                int gcol = bcol * 64 + warp_n + nt * 8 + c0;
                float ox = acc[t][nt][half * 2 + 0];
                float oy = acc[t][nt][half * 2 + 1];
                if (Cb2) {
                    __nv_bfloat16* dst; const float* bs; int cc;
                    if (gcol < Nh) { dst = Cb; bs = bias; cc = gcol; }
                    else           { dst = Cb2; bs = bias2; cc = gcol - Nh; }
                    ox += bs[cc]; oy += bs[cc + 1];
                    *(__nv_bfloat162*)(dst + (size_t)grow * Nh + cc) =
                        __floats2bfloat162_rn(ox, oy);
                } else if (Cb) {
                    ox += bias[gcol]; oy += bias[gcol + 1];
                    *(__nv_bfloat162*)(Cb + (size_t)grow * N + gcol) =
                        __floats2bfloat162_rn(ox, oy);
                } else {
                    ox += bias[gcol]; oy += bias[gcol + 1];
                    if (res) {
                        float2 rv = *(const float2*)(res + (size_t)grow * N + gcol);
                        ox += rv.x; oy += rv.y;
                    }
                    float2 o; o.x = ox; o.y = oy;
                    *(float2*)(Cf + (size_t)grow * N + gcol) = o;
                }
            }
        }
    }
}

// =================== HMMA flash attention, cp.async double-buffered K/V ===================
#define FB_BQ 64
#define FB_BK 64
#define FB_PAD 72
#define FB_KV_BYTES (FB_BK * FB_PAD * 2)   // 9216 B per tile per array

__global__ __launch_bounds__(128) void flash_mma_kernel(
    const __nv_bfloat16* __restrict__ Qb, const __nv_bfloat16* __restrict__ Vb,
    const float* __restrict__ AA,
    __nv_bfloat16* __restrict__ Ohi, __nv_bfloat16* __restrict__ Olo)
{
    __shared__ __nv_bfloat16 sQ[FB_BQ * FB_PAD];
    __shared__ __nv_bfloat16 sK[2][FB_BK * FB_PAD];
    __shared__ __nv_bfloat16 sV[2][FB_BK * FB_PAD];
    __shared__ float sAA[2][FB_BK];

    int b = blockIdx.z, h = blockIdx.y;
    int q0 = blockIdx.x * FB_BQ;
    int tid = threadIdx.x, lane = tid & 31, w = tid >> 5;

    uint32_t sq_a = smem_u32(sQ);
    uint32_t sk_a = smem_u32(sK);
    uint32_t sv_a = smem_u32(sV);

    // prefetch K/V tile 0 via cp.async
    #pragma unroll
    for (int i = 0; i < 4; i++) {
        int idx = tid + i * 128;
        int r = idx >> 3, c = idx & 7;
        size_t off = (size_t)(b * NSEQ + r) * DIM + h * DHEAD + c * 8;
        uint32_t so = (uint32_t)(r * FB_PAD + c * 8) * 2;
        cp16(sk_a + so, Qb + off);
        cp16(sv_a + so, Vb + off);
    }
    CP_COMMIT();

    // load Q tile (regular) + fragments
    #pragma unroll
    for (int i = 0; i < 4; i++) {
        int idx = tid + i * 128;
        int r = idx >> 3, c = idx & 7;
        size_t off = (size_t)(b * NSEQ + q0 + r) * DIM + h * DHEAD + c * 8;
        *(uint4*)&sQ[r * FB_PAD + c * 8] = *(const uint4*)(Qb + off);
    }
    __syncthreads();

    uint32_t qa[4][4];
    #pragma unroll
    for (int ks = 0; ks < 4; ks++) {
        uint32_t off = (uint32_t)((w * 16 + (lane & 15)) * FB_PAD + ks * 16 + ((lane >> 4) << 3)) * 2;
        LDSM4(qa[ks], sq_a + off);
    }

    float m0 = -1e30f, m1 = -1e30f, l0 = 0.0f, l1 = 0.0f;
    float o[8][4];
    #pragma unroll
    for (int t = 0; t < 8; t++)
        #pragma unroll
        for (int j = 0; j < 4; j++) o[t][j] = 0.0f;

    const float* aab = AA + ((size_t)(b * NHEAD + h)) * NSEQ;
    const int ntiles = NSEQ / FB_BK;

    for (int it = 0; it < ntiles; it++) {
        int buf = it & 1;
        __syncthreads();   // previous compute (on buf^1) finished

        // prefetch tile it+1 into buf^1
        if (it + 1 < ntiles) {
            uint32_t dst_k = sk_a + (buf ^ 1) * FB_KV_BYTES;
            uint32_t dst_v = sv_a + (buf ^ 1) * FB_KV_BYTES;
            #pragma unroll
            for (int i = 0; i < 4; i++) {
                int idx = tid + i * 128;
                int r = idx >> 3, c = idx & 7;
                size_t off = (size_t)(b * NSEQ + (it + 1) * FB_BK + r) * DIM + h * DHEAD + c * 8;
                uint32_t so = (uint32_t)(r * FB_PAD + c * 8) * 2;
                cp16(dst_k + so, Qb + off);
                cp16(dst_v + so, Vb + off);
            }
        }
        CP_COMMIT();
        if (tid < FB_BK) sAA[buf][tid] = aab[it * FB_BK + tid];
        CP_WAIT1();        // current tile ready
        __syncthreads();

        uint32_t skb = sk_a + buf * FB_KV_BYTES;
        uint32_t svb = sv_a + buf * FB_KV_BYTES;

        float sc[8][4];
        #pragma unroll
        for (int t = 0; t < 8; t++)
            #pragma unroll
            for (int j = 0; j < 4; j++) sc[t][j] = 0.0f;

        #pragma unroll
        for (int ks = 0; ks < 4; ks++) {
            uint32_t kb[8][2];
            #pragma unroll
            for (int p = 0; p < 4; p++) {
                uint32_t off = (uint32_t)((p * 16 + ((lane >> 3) & 1) * 8 + (lane & 7)) * FB_PAD
                             + ks * 16 + ((lane >> 4) << 3)) * 2;
                uint32_t r[4];
                LDSM4(r, skb + off);
                kb[2*p][0] = r[0]; kb[2*p][1] = r[2];
                kb[2*p+1][0] = r[1]; kb[2*p+1][1] = r[3];
            }
            #pragma unroll
            for (int t = 0; t < 8; t++) mma_bf16(sc[t], qa[ks], kb[t]);
        }

        float mt0 = -1e30f, mt1 = -1e30f;
        #pragma unroll
        for (int t = 0; t < 8; t++) {
            float a0 = sAA[buf][t * 8 + (lane & 3) * 2];
            float a1 = sAA[buf][t * 8 + (lane & 3) * 2 + 1];
            sc[t][0] = 0.25f * sc[t][0] - 0.125f * a0;
            sc[t][1] = 0.25f * sc[t][1] - 0.125f * a1;
            sc[t][2] = 0.25f * sc[t][2] - 0.125f * a0;
            sc[t][3] = 0.25f * sc[t][3] - 0.125f * a1;
            mt0 = fmaxf(mt0, fmaxf(sc[t][0], sc[t][1]));
            mt1 = fmaxf(mt1, fmaxf(sc[t][2], sc[t][3]));
        }
        mt0 = fmaxf(mt0, __shfl_xor_sync(0xffffffffu, mt0, 1));
        mt0 = fmaxf(mt0, __shfl_xor_sync(0xffffffffu, mt0, 2));
        mt1 = fmaxf(mt1, __shfl_xor_sync(0xffffffffu, mt1, 1));
        mt1 = fmaxf(mt1, __shfl_xor_sync(0xffffffffu, mt1, 2));

        float mn0 = fmaxf(m0, mt0), mn1 = fmaxf(m1, mt1);
        float al0 = __expf(m0 - mn0), al1 = __expf(m1 - mn1);
        m0 = mn0; m1 = mn1;
        l0 *= al0; l1 *= al1;
        #pragma unroll
        for (int t = 0; t < 8; t++) {
            o[t][0] *= al0; o[t][1] *= al0;
            o[t][2] *= al1; o[t][3] *= al1;
        }

        #pragma unroll
        for (int t = 0; t < 8; t++) {
            sc[t][0] = __expf(sc[t][0] - m0);
            sc[t][1] = __expf(sc[t][1] - m0);
            sc[t][2] = __expf(sc[t][2] - m1);
            sc[t][3] = __expf(sc[t][3] - m1);
            l0 += sc[t][0] + sc[t][1];
            l1 += sc[t][2] + sc[t][3];
        }

        #pragma unroll
        for (int j = 0; j < 4; j++) {
            uint32_t pa[4];
            __nv_bfloat162 t2;
            t2 = __floats2bfloat162_rn(sc[2*j][0],   sc[2*j][1]);   pa[0] = *(uint32_t*)&t2;
            t2 = __floats2bfloat162_rn(sc[2*j][2],   sc[2*j][3]);   pa[1] = *(uint32_t*)&t2;
            t2 = __floats2bfloat162_rn(sc[2*j+1][0], sc[2*j+1][1]); pa[2] = *(uint32_t*)&t2;
            t2 = __floats2bfloat162_rn(sc[2*j+1][2], sc[2*j+1][3]); pa[3] = *(uint32_t*)&t2;

            uint32_t vb[8][2];
            #pragma unroll
            for (int dp = 0; dp < 4; dp++) {
                int g = lane >> 3, rr = lane & 7;
                uint32_t off = (uint32_t)((j * 16 + (g & 1) * 8 + rr) * FB_PAD
                             + dp * 16 + (g >> 1) * 8) * 2;
                uint32_t r[4];
                LDSM4T(r, svb + off);
                vb[2*dp][0]   = r[0]; vb[2*dp][1]   = r[1];
                vb[2*dp+1][0] = r[2]; vb[2*dp+1][1] = r[3];
            }
            #pragma unroll
            for (int t = 0; t < 8; t++) mma_bf16(o[t], pa, vb[t]);
        }
    }

    l0 += __shfl_xor_sync(0xffffffffu, l0, 1);
    l0 += __shfl_xor_sync(0xffffffffu, l0, 2);
    l1 += __shfl_xor_sync(0xffffffffu, l1, 1);
    l1 += __shfl_xor_sync(0xffffffffu, l1, 2);
    float inv0 = 1.0f / l0, inv1 = 1.0f / l1;

    int r0g = q0 + w * 16 + (lane >> 2);
    #pragma unroll
    for (int t = 0; t < 8; t++) {
        int c = h * DHEAD + t * 8 + (lane & 3) * 2;
        float o00 = o[t][0] * inv0, o01 = o[t][1] * inv0;
        float o10 = o[t][2] * inv1, o11 = o[t][3] * inv1;
        size_t off0 = (size_t)(b * NSEQ + r0g) * DIM + c;
        size_t off1 = (size_t)(b * NSEQ + r0g + 8) * DIM + c;
        __nv_bfloat162 h0 = __floats2bfloat162_rn(o00, o01);
        __nv_bfloat162 h1 = __floats2bfloat162_rn(o10, o11);
        *(__nv_bfloat162*)(Ohi + off0) = h0;
        *(__nv_bfloat162*)(Ohi + off1) = h1;
        *(__nv_bfloat162*)(Olo + off0) = __floats2bfloat162_rn(
            o00 - __bfloat162float(h0.x), o01 - __bfloat162float(h0.y));
        *(__nv_bfloat162*)(Olo + off1) = __floats2bfloat162_rn(
            o10 - __bfloat162float(h1.x), o11 - __bfloat162float(h1.y));
    }
}

// ---------------- fused LayerNorm + hi/lo split ----------------
__global__ __launch_bounds__(128) void ln_split_kernel(
    const float* __restrict__ X, const float* __restrict__ w,
    const float* __restrict__ bb, __nv_bfloat16* __restrict__ Hi,
    __nv_bfloat16* __restrict__ Lo)
{
    int row = blockIdx.x;
    int tid = threadIdx.x;
    const float* xp = X + (size_t)row * DIM;
    float4 v = *(const float4*)(xp + tid * 4);
    float s  = v.x + v.y + v.z + v.w;
    float sq = v.x*v.x + v.y*v.y + v.z*v.z + v.w*v.w;
    #pragma unroll
    for (int o = 16; o > 0; o >>= 1) {
        s  += __shfl_xor_sync(0xffffffffu, s,  o);
        sq += __shfl_xor_sync(0xffffffffu, sq, o);
    }
    __shared__ float reds[4], redq[4];
    int wid = tid >> 5, lane = tid & 31;
    if (lane == 0) { reds[wid] = s; redq[wid] = sq; }
    __syncthreads();
    s  = reds[0] + reds[1] + reds[2] + reds[3];
    sq = redq[0] + redq[1] + redq[2] + redq[3];
    float mu   = s * (1.0f / DIM);
    float var  = sq * (1.0f / DIM) - mu * mu;
    float rstd = rsqrtf(var + 1e-5f);
    float4 wv = *(const float4*)(w  + tid * 4);
    float4 bv = *(const float4*)(bb + tid * 4);
    float o0 = (v.x - mu) * rstd * wv.x + bv.x;
    float o1 = (v.y - mu) * rstd * wv.y + bv.y;
    float o2 = (v.z - mu) * rstd * wv.z + bv.z;
    float o3 = (v.w - mu) * rstd * wv.w + bv.w;
    __nv_bfloat162 h0 = __floats2bfloat162_rn(o0, o1);
    __nv_bfloat162 h1 = __floats2bfloat162_rn(o2, o3);
    __nv_bfloat162 l0 = __floats2bfloat162_rn(o0 - __bfloat162float(h0.x),
                                              o1 - __bfloat162float(h0.y));
    __nv_bfloat162 l1 = __floats2bfloat162_rn(o2 - __bfloat162float(h1.x),
                                              o3 - __bfloat162float(h1.y));
    size_t off = (size_t)row * DIM + tid * 4;
    *(__nv_bfloat162*)(Hi + off) = h0;
    *(__nv_bfloat162*)(Hi + off + 2) = h1;
    *(__nv_bfloat162*)(Lo + off) = l0;
    *(__nv_bfloat162*)(Lo + off + 2) = l1;
}

// ---------------- weight transpose+split ----------------
__global__ __launch_bounds__(256) void conv_wt_kernel(
    const float* __restrict__ W, __nv_bfloat16* __restrict__ Thi,
    __nv_bfloat16* __restrict__ Tlo, int K, int N)
{
    __shared__ __nv_bfloat16 shi[32][33];
    __shared__ __nv_bfloat16 slo[32][33];
    int tx = threadIdx.x & 31, ty = threadIdx.x >> 5;
    int n0 = blockIdx.x * 32, k0 = blockIdx.y * 32;
    #pragma unroll
    for (int j = 0; j < 4; j++) {
        int k = ty + j * 8;
        float v = W[(size_t)(k0 + k) * N + n0 + tx];
        __nv_bfloat16 h = __float2bfloat16_rn(v);
        shi[k][tx] = h;
        slo[k][tx] = __float2bfloat16_rn(v - __bfloat162float(h));
    }
    __syncthreads();
    #pragma unroll
    for (int j = 0; j < 4; j++) {
        int n = ty + j * 8;
        Thi[(size_t)(n0 + n) * K + k0 + tx] = shi[tx][n];
        Tlo[(size_t)(n0 + n) * K + k0 + tx] = slo[tx][n];
    }
}

// ---------------- AA_j = |q_j|^2 from bf16 q ----------------
__global__ void aa_kernel(const __nv_bfloat16* __restrict__ Qb, float* __restrict__ AA)
{
    int idx = blockIdx.x * blockDim.x + threadIdx.x;
    if (idx >= ROWS * NHEAD) return;
    int h = idx & 7;
    int row = idx >> 3;
    const uint4* qp = (const uint4*)(Qb + (size_t)row * DIM + h * DHEAD);
    float s = 0.0f;
    #pragma unroll
    for (int i = 0; i < 8; i++) {
        uint4 u = qp[i];
        const __nv_bfloat162* p = (const __nv_bfloat162*)&u;
        #pragma unroll
        for (int j = 0; j < 4; j++) {
            float2 f = __bfloat1622float2(p[j]);
            s += f.x * f.x + f.y * f.y;
        }
    }
    int b = row >> 11, n = row & 2047;
    AA[((size_t)(b * NHEAD + h)) * NSEQ + n] = s;
}

// ---------------- GEGLU (bf16 input) + hi/lo split ----------------
__device__ __forceinline__ float gelu_exact(float x) {
    return 0.5f * x * (1.0f + erff(x * 0.70710678118654752f));
}
__global__ void geglu_split_kernel(const __nv_bfloat16* __restrict__ H,
                                   __nv_bfloat16* __restrict__ Hi,
                                   __nv_bfloat16* __restrict__ Lo)
{
    int idx = blockIdx.x * blockDim.x + threadIdx.x;   // 8 elems per thread
    if (idx >= ROWS * (IFF / 8)) return;
    int row = idx / (IFF / 8);
    int c8  = idx % (IFF / 8);
    const __nv_bfloat16* base = H + (size_t)row * (2 * IFF);
    uint4 au = *(const uint4*)(base + c8 * 8);
    uint4 gu = *(const uint4*)(base + IFF + c8 * 8);
    const __nv_bfloat162* ap = (const __nv_bfloat162*)&au;
    const __nv_bfloat162* gp = (const __nv_bfloat162*)&gu;
    uint4 ho, lo;
    uint32_t* hop = (uint32_t*)&ho;
    uint32_t* lop = (uint32_t*)&lo;
    #pragma unroll
    for (int j = 0; j < 4; j++) {
        float2 af = __bfloat1622float2(ap[j]);
        float2 gf = __bfloat1622float2(gp[j]);
        float r0 = af.x * gelu_exact(gf.x);
        float r1 = af.y * gelu_exact(gf.y);
        __nv_bfloat162 hb = __floats2bfloat162_rn(r0, r1);
        __nv_bfloat162 lb = __floats2bfloat162_rn(r0 - __bfloat162float(hb.x),
                                                  r1 - __bfloat162float(hb.y));
        hop[j] = *(uint32_t*)&hb;
        lop[j] = *(uint32_t*)&lb;
    }
    size_t off = (size_t)row * IFF + c8 * 8;
    *(uint4*)(Hi + off) = ho;
    *(uint4*)(Lo + off) = lo;
}

// ---------------- host orchestration ----------------
struct Bufs {
    float *x1, *x2, *aa;
    __nv_bfloat16 *hb;
    __nv_bfloat16 *ahi, *alo, *whi, *wlo, *qb, *vb;
};

static void conv_wt(const float* W, __nv_bfloat16* hi, __nv_bfloat16* lo, int K, int N) {
    dim3 grid(N / 32, K / 32);
    conv_wt_kernel<<<grid, 256>>>(W, hi, lo, K, N);
}
static void tc_gemm_f32_lo(const Bufs& B, const float* bias, const float* res,
                           float* C, int M, int N, int K) {
    dim3 grid(N / 64, M / 128);
    mma_gemm_kernel<true><<<grid, 256, G_SMEM>>>(B.ahi, B.alo, B.whi, B.wlo, bias, nullptr,
                                                 res, C, nullptr, nullptr, M, N, K, 0);
}
static void tc_gemm_bf16_1x(const Bufs& B, const float* bias,
                            __nv_bfloat16* C, int M, int N, int K) {
    dim3 grid(N / 64, M / 128);
    mma_gemm_kernel<false><<<grid, 256, G_SMEM>>>(B.ahi, B.alo, B.whi, B.wlo, bias, nullptr,
                                                  nullptr, nullptr, C, nullptr, M, N, K, 0);
}
static void tc_gemm_qv(const Bufs& B, const float* bq, const float* bv,
                       int M, int K) {
    dim3 grid(1024 / 64, M / 128);
    mma_gemm_kernel<false><<<grid, 256, G_SMEM>>>(B.ahi, B.alo, B.whi, B.wlo, bq, bv,
                                                  nullptr, nullptr, B.qb, B.vb,
                                                  M, 1024, K, 512);
}
static void run_attention(const Bufs& B) {
    int aa_blocks = (ROWS * NHEAD + 255) / 256;
    aa_kernel<<<aa_blocks, 256>>>(B.qb, B.aa);
    dim3 fa_grid(NSEQ / FB_BQ, NHEAD, NBATCH);
    flash_mma_kernel<<<fa_grid, 128>>>(B.qb, B.vb, B.aa, B.ahi, B.alo);
}

extern "C" void kernel_launch(void* const* d_in, const int* in_sizes, int n_in,
                              void* d_out, int out_size)
{
    const float* x     = (const float*)d_in[0];
    const float* sa_w  = (const float*)d_in[1];
    const float* sa_b  = (const float*)d_in[2];
    const float* ca_w  = (const float*)d_in[3];
    const float* ca_b  = (const float*)d_in[4];
    const float* ff_nw = (const float*)d_in[5];
    const float* ff_nb = (const float*)d_in[6];
    const float* a1_wq = (const float*)d_in[7];
    const float* a1_bq = (const float*)d_in[8];
    const float* a1_wv = (const float*)d_in[9];
    const float* a1_bv = (const float*)d_in[10];
    const float* a1_wo = (const float*)d_in[11];
    const float* a1_bo = (const float*)d_in[12];
    const float* a2_wq = (const float*)d_in[13];
    const float* a2_bq = (const float*)d_in[14];
    const float* a2_wv = (const float*)d_in[15];
    const float* a2_bv = (const float*)d_in[16];
    const float* a2_wo = (const float*)d_in[17];
    const float* a2_bo = (const float*)d_in[18];
    const float* ff_w1 = (const float*)d_in[19];
    const float* ff_b1 = (const float*)d_in[20];
    const float* ff_w2 = (const float*)d_in[21];
    const float* ff_b2 = (const float*)d_in[22];
    float* out = (float*)d_out;

    Bufs B;
    cudaGetSymbolAddress((void**)&B.x1,  g_x1);
    cudaGetSymbolAddress((void**)&B.x2,  g_x2);
    cudaGetSymbolAddress((void**)&B.aa,  g_aa);
    cudaGetSymbolAddress((void**)&B.hb,  g_h);   // reuse fp32 buffer as bf16
    cudaGetSymbolAddress((void**)&B.ahi, g_ahi);
    cudaGetSymbolAddress((void**)&B.alo, g_alo);
    cudaGetSymbolAddress((void**)&B.whi, g_whi);
    cudaGetSymbolAddress((void**)&B.wlo, g_wlo);
    cudaGetSymbolAddress((void**)&B.qb,  g_qb);
    cudaGetSymbolAddress((void**)&B.vb,  g_vb);

    cudaFuncSetAttribute(mma_gemm_kernel<true>,
                         cudaFuncAttributeMaxDynamicSharedMemorySize, G_SMEM);
    cudaFuncSetAttribute(mma_gemm_kernel<false>,
                         cudaFuncAttributeMaxDynamicSharedMemorySize, G_SMEM);

    // ---- self-attention (attn1) ----
    ln_split_kernel<<<ROWS, 128>>>(x, sa_w, sa_b, B.ahi, B.alo);
    conv_wt(a1_wq, B.whi, B.wlo, DIM, DIM);
    conv_wt(a1_wv, B.whi + DIM * DIM, B.wlo + DIM * DIM, DIM, DIM);
    tc_gemm_qv(B, a1_bq, a1_bv, ROWS, DIM);
    run_attention(B);
    conv_wt(a1_wo, B.whi, B.wlo, DIM, DIM);
    tc_gemm_f32_lo(B, a1_bo, x, B.x1, ROWS, DIM, DIM);

    // ---- attn2 (k=q, v from x) ----
    ln_split_kernel<<<ROWS, 128>>>(B.x1, ca_w, ca_b, B.ahi, B.alo);
    conv_wt(a2_wq, B.whi, B.wlo, DIM, DIM);
    conv_wt(a2_wv, B.whi + DIM * DIM, B.wlo + DIM * DIM, DIM, DIM);
    tc_gemm_qv(B, a2_bq, a2_bv, ROWS, DIM);
    run_attention(B);
    conv_wt(a2_wo, B.whi, B.wlo, DIM, DIM);
    tc_gemm_f32_lo(B, a2_bo, B.x1, B.x2, ROWS, DIM, DIM);

    // ---- GEGLU FFN ----
    ln_split_kernel<<<ROWS, 128>>>(B.x2, ff_nw, ff_nb, B.ahi, B.alo);
    conv_wt(ff_w1, B.whi, B.wlo, DIM, 2 * IFF);
    tc_gemm_bf16_1x(B, ff_b1, B.hb, ROWS, 2 * IFF, DIM);   // FF1 -> bf16
    int ge_blocks = (ROWS * (IFF / 8) + 255) / 256;
    geglu_split_kernel<<<ge_blocks, 256>>>(B.hb, B.ahi, B.alo);
    conv_wt(ff_w2, B.whi, B.wlo, IFF, DIM);
    tc_gemm_f32_lo(B, ff_b2, B.x2, out, ROWS, DIM, IFF);
}

// round 15
// speedup vs baseline: 6.4828x; 1.0306x over previous
#include <cuda_runtime.h>
#include <cuda_bf16.h>
#include <cstdint>
#include <math.h>

#define ROWS 8192
#define DIM  512
#define NSEQ 2048
#define NBATCH 4
#define NHEAD 8
#define DHEAD 64
#define IFF  2048

// ---------------- scratch ----------------
__device__ float g_x1 [ROWS * DIM];
__device__ float g_x2 [ROWS * DIM];
__device__ float g_aa [NBATCH * NHEAD * NSEQ];
__device__ float g_h  [ROWS * 2 * IFF];        // FF1 out (bf16 reuse)
__device__ __nv_bfloat16 g_ahi[ROWS * IFF];
__device__ __nv_bfloat16 g_alo[ROWS * IFF];
__device__ __nv_bfloat16 g_whi[4096 * 512];
__device__ __nv_bfloat16 g_wlo[4096 * 512];
__device__ __nv_bfloat16 g_qb[ROWS * DIM];
__device__ __nv_bfloat16 g_vb[ROWS * DIM];

// =================== helpers ===================
__device__ __forceinline__ uint32_t smem_u32(const void* p) {
    uint32_t a;
    asm("{ .reg .u64 t; cvta.to.shared.u64 t, %1; cvt.u32.u64 %0, t; }" : "=r"(a) : "l"(p));
    return a;
}
#define LDSM4(r, addr) \
    asm volatile("ldmatrix.sync.aligned.m8n8.x4.shared.b16 {%0,%1,%2,%3}, [%4];" \
        : "=r"((r)[0]), "=r"((r)[1]), "=r"((r)[2]), "=r"((r)[3]) : "r"(addr))
#define LDSM4T(r, addr) \
    asm volatile("ldmatrix.sync.aligned.m8n8.x4.trans.shared.b16 {%0,%1,%2,%3}, [%4];" \
        : "=r"((r)[0]), "=r"((r)[1]), "=r"((r)[2]), "=r"((r)[3]) : "r"(addr))

__device__ __forceinline__ void mma_bf16(float* d, const uint32_t* a, const uint32_t* b) {
    asm volatile("mma.sync.aligned.m16n8k16.row.col.f32.bf16.bf16.f32 "
        "{%0,%1,%2,%3}, {%4,%5,%6,%7}, {%8,%9}, {%0,%1,%2,%3};"
        : "+f"(d[0]), "+f"(d[1]), "+f"(d[2]), "+f"(d[3])
        : "r"(a[0]), "r"(a[1]), "r"(a[2]), "r"(a[3]), "r"(b[0]), "r"(b[1]));
}
__device__ __forceinline__ void cp16(uint32_t saddr, const void* g) {
    asm volatile("cp.async.cg.shared.global [%0], [%1], 16;" :: "r"(saddr), "l"(g));
}
#define CP_COMMIT() asm volatile("cp.async.commit_group;" ::: "memory")
#define CP_WAIT1()  asm volatile("cp.async.wait_group 1;" ::: "memory")

// =================== cp.async HMMA GEMM, 128x64 tile, BK=64, 2 CTAs/SM ===================
// LO=true : hi/lo split (3 MMAs), 2-stage pipeline (221KB/SM total)
// LO=false: single bf16 (1 MMA),  3-stage pipeline (166KB/SM total)
#define MG_PAD    72
#define SA_BYTES  (128 * MG_PAD * 2)   // 18432
#define SB_BYTES  (64 * MG_PAD * 2)    // 9216

template<bool LO>
struct GCfg {
    static constexpr int OFF_AL = SA_BYTES;                       // only if LO
    static constexpr int OFF_BH = LO ? 2 * SA_BYTES : SA_BYTES;
    static constexpr int OFF_BL = LO ? 2 * SA_BYTES + SB_BYTES : 0;
    static constexpr int ST     = LO ? (2 * SA_BYTES + 2 * SB_BYTES)
                                     : (SA_BYTES + SB_BYTES);     // 55296 / 27648
    static constexpr int NST    = LO ? 2 : 3;
    static constexpr int SMEM   = ST * NST;                       // 110592 / 82944
};

template<bool LO>
__global__ __launch_bounds__(256, 2) void mma_gemm_kernel(
    const __nv_bfloat16* __restrict__ Ahi, const __nv_bfloat16* __restrict__ Alo,
    const __nv_bfloat16* __restrict__ Bhi, const __nv_bfloat16* __restrict__ Blo,
    const float* __restrict__ bias, const float* __restrict__ bias2,
    const float* __restrict__ res,
    float* __restrict__ Cf, __nv_bfloat16* __restrict__ Cb,
    __nv_bfloat16* __restrict__ Cb2,
    int M, int N, int K, int Nh)
{
    using C = GCfg<LO>;
    extern __shared__ __nv_bfloat16 smem[];
    uint32_t sbase = smem_u32(smem);

    int tid = threadIdx.x, lane = tid & 31, wid = tid >> 5;
    int brow = blockIdx.y, bcol = blockIdx.x;
    int warp_m = (wid >> 1) * 32;
    int warp_n = (wid & 1) * 32;

    const __nv_bfloat16* Aat = Ahi + (size_t)(brow * 128) * K;
    const __nv_bfloat16* Aal = Alo + (size_t)(brow * 128) * K;
    const __nv_bfloat16* Bbt = Bhi + (size_t)(bcol * 64) * K;
    const __nv_bfloat16* Bbl = Blo + (size_t)(bcol * 64) * K;

    float acc[2][4][4];
    #pragma unroll
    for (int t = 0; t < 2; t++)
        #pragma unroll
        for (int nt = 0; nt < 4; nt++)
            #pragma unroll
            for (int j = 0; j < 4; j++) acc[t][nt][j] = 0.0f;

    int nchunk = K >> 6;   // BK=64

    // chunk loader: 64 K-cols; A 128 rows (4 cp16/array), B 64 rows (2 cp16/array)
    auto load_chunk = [&](int c, int st) {
        uint32_t stb = sbase + st * C::ST;
        #pragma unroll
        for (int i = 0; i < 4; i++) {
            int idx = tid + i * 256;
            int row = idx >> 3, ch = idx & 7;
            uint32_t so = stb + (uint32_t)(row * MG_PAD + ch * 8) * 2;
            size_t go = (size_t)row * K + c * 64 + ch * 8;
            cp16(so, Aat + go);
            if (LO) cp16(so + C::OFF_AL, Aal + go);
        }
        #pragma unroll
        for (int i = 0; i < 2; i++) {
            int idx = tid + i * 256;
            int row = idx >> 3, ch = idx & 7;
            uint32_t so = stb + (uint32_t)(row * MG_PAD + ch * 8) * 2;
            size_t go = (size_t)row * K + c * 64 + ch * 8;
            cp16(so + C::OFF_BH, Bbt + go);
            if (LO) cp16(so + C::OFF_BL, Bbl + go);
        }
        CP_COMMIT();
    };

    // prologue: NST-1 stages
    #pragma unroll
    for (int p = 0; p < C::NST - 1; p++) load_chunk(p, p);

    for (int c = 0; c < nchunk; c++) {
        int stage = c % C::NST;
        if (C::NST == 2) {
            __syncthreads();                       // prior compute done before overwrite
            if (c + 1 < nchunk) load_chunk(c + 1, (c + 1) % C::NST);
            else CP_COMMIT();
            CP_WAIT1();
            __syncthreads();
        } else {
            CP_WAIT1();
            __syncthreads();
            if (c + 2 < nchunk) load_chunk(c + 2, (c + 2) % C::NST);
            else CP_COMMIT();
        }

        uint32_t sa_h = sbase + stage * C::ST;
        uint32_t sa_l = sa_h + C::OFF_AL;
        uint32_t sb_h = sa_h + C::OFF_BH;
        uint32_t sb_l = sa_h + C::OFF_BL;

        #pragma unroll
        for (int ks = 0; ks < 4; ks++) {
            int kk = ks * 16;
            uint32_t ah[2][4], al[2][4];
            #pragma unroll
            for (int t = 0; t < 2; t++) {
                uint32_t off = (uint32_t)((warp_m + t * 16 + (lane & 15)) * MG_PAD
                             + kk + ((lane >> 4) << 3)) * 2;
                LDSM4(ah[t], sa_h + off);
                if (LO) LDSM4(al[t], sa_l + off);
            }
            uint32_t bh[4][2], bl[4][2];
            #pragma unroll
            for (int p = 0; p < 2; p++) {
                uint32_t off = (uint32_t)((warp_n + p * 16 + ((lane >> 3) & 1) * 8 + (lane & 7)) * MG_PAD
                             + kk + ((lane >> 4) << 3)) * 2;
                uint32_t r[4];
                LDSM4(r, sb_h + off);
                bh[2*p][0] = r[0]; bh[2*p][1] = r[2];
                bh[2*p+1][0] = r[1]; bh[2*p+1][1] = r[3];
                if (LO) {
                    LDSM4(r, sb_l + off);
                    bl[2*p][0] = r[0]; bl[2*p][1] = r[2];
                    bl[2*p+1][0] = r[1]; bl[2*p+1][1] = r[3];
                }
            }
            #pragma unroll
            for (int t = 0; t < 2; t++)
                #pragma unroll
                for (int nt = 0; nt < 4; nt++) {
                    mma_bf16(acc[t][nt], ah[t], bh[nt]);
                    if (LO) {
                        mma_bf16(acc[t][nt], ah[t], bl[nt]);
                        mma_bf16(acc[t][nt], al[t], bh[nt]);
                    }
                }
        }
    }

    int r0 = lane >> 2, c0 = (lane & 3) * 2;
    #pragma unroll
    for (int t = 0; t < 2; t++) {
        #pragma unroll
        for (int half = 0; half < 2; half++) {
            int grow = brow * 128 + warp_m + t * 16 + r0 + half * 8;
            #pragma unroll
            for (int nt = 0; nt < 4; nt++) {
                int gcol = bcol * 64 + warp_n + nt * 8 + c0;
                float ox = acc[t][nt][half * 2 + 0];
                float oy = acc[t][nt][half * 2 + 1];
                if (Cb2) {
                    __nv_bfloat16* dst; const float* bs; int cc;
                    if (gcol < Nh) { dst = Cb; bs = bias; cc = gcol; }
                    else           { dst = Cb2; bs = bias2; cc = gcol - Nh; }
                    ox += bs[cc]; oy += bs[cc + 1];
                    *(__nv_bfloat162*)(dst + (size_t)grow * Nh + cc) =
                        __floats2bfloat162_rn(ox, oy);
                } else if (Cb) {
                    ox += bias[gcol]; oy += bias[gcol + 1];
                    *(__nv_bfloat162*)(Cb + (size_t)grow * N + gcol) =
                        __floats2bfloat162_rn(ox, oy);
                } else {
                    ox += bias[gcol]; oy += bias[gcol + 1];
                    if (res) {
                        float2 rv = *(const float2*)(res + (size_t)grow * N + gcol);
                        ox += rv.x; oy += rv.y;
                    }
                    float2 o; o.x = ox; o.y = oy;
                    *(float2*)(Cf + (size_t)grow * N + gcol) = o;
                }
            }
        }
    }
}

// =================== HMMA flash attention, cp.async double-buffered K/V ===================
#define FB_BQ 64
#define FB_BK 64
#define FB_PAD 72
#define FB_KV_BYTES (FB_BK * FB_PAD * 2)

__global__ __launch_bounds__(128) void flash_mma_kernel(
    const __nv_bfloat16* __restrict__ Qb, const __nv_bfloat16* __restrict__ Vb,
    const float* __restrict__ AA,
    __nv_bfloat16* __restrict__ Ohi, __nv_bfloat16* __restrict__ Olo)
{
    __shared__ __nv_bfloat16 sQ[FB_BQ * FB_PAD];
    __shared__ __nv_bfloat16 sK[2][FB_BK * FB_PAD];
    __shared__ __nv_bfloat16 sV[2][FB_BK * FB_PAD];
    __shared__ float sAA[2][FB_BK];

    int b = blockIdx.z, h = blockIdx.y;
    int q0 = blockIdx.x * FB_BQ;
    int tid = threadIdx.x, lane = tid & 31, w = tid >> 5;

    uint32_t sq_a = smem_u32(sQ);
    uint32_t sk_a = smem_u32(sK);
    uint32_t sv_a = smem_u32(sV);

    #pragma unroll
    for (int i = 0; i < 4; i++) {
        int idx = tid + i * 128;
        int r = idx >> 3, c = idx & 7;
        size_t off = (size_t)(b * NSEQ + r) * DIM + h * DHEAD + c * 8;
        uint32_t so = (uint32_t)(r * FB_PAD + c * 8) * 2;
        cp16(sk_a + so, Qb + off);
        cp16(sv_a + so, Vb + off);
    }
    CP_COMMIT();

    #pragma unroll
    for (int i = 0; i < 4; i++) {
        int idx = tid + i * 128;
        int r = idx >> 3, c = idx & 7;
        size_t off = (size_t)(b * NSEQ + q0 + r) * DIM + h * DHEAD + c * 8;
        *(uint4*)&sQ[r * FB_PAD + c * 8] = *(const uint4*)(Qb + off);
    }
    __syncthreads();

    uint32_t qa[4][4];
    #pragma unroll
    for (int ks = 0; ks < 4; ks++) {
        uint32_t off = (uint32_t)((w * 16 + (lane & 15)) * FB_PAD + ks * 16 + ((lane >> 4) << 3)) * 2;
        LDSM4(qa[ks], sq_a + off);
    }

    float m0 = -1e30f, m1 = -1e30f, l0 = 0.0f, l1 = 0.0f;
    float o[8][4];
    #pragma unroll
    for (int t = 0; t < 8; t++)
        #pragma unroll
        for (int j = 0; j < 4; j++) o[t][j] = 0.0f;

    const float* aab = AA + ((size_t)(b * NHEAD + h)) * NSEQ;
    const int ntiles = NSEQ / FB_BK;

    for (int it = 0; it < ntiles; it++) {
        int buf = it & 1;
        __syncthreads();

        if (it + 1 < ntiles) {
            uint32_t dst_k = sk_a + (buf ^ 1) * FB_KV_BYTES;
            uint32_t dst_v = sv_a + (buf ^ 1) * FB_KV_BYTES;
            #pragma unroll
            for (int i = 0; i < 4; i++) {
                int idx = tid + i * 128;
                int r = idx >> 3, c = idx & 7;
                size_t off = (size_t)(b * NSEQ + (it + 1) * FB_BK + r) * DIM + h * DHEAD + c * 8;
                uint32_t so = (uint32_t)(r * FB_PAD + c * 8) * 2;
                cp16(dst_k + so, Qb + off);
                cp16(dst_v + so, Vb + off);
            }
        }
        CP_COMMIT();
        if (tid < FB_BK) sAA[buf][tid] = aab[it * FB_BK + tid];
        CP_WAIT1();
        __syncthreads();

        uint32_t skb = sk_a + buf * FB_KV_BYTES;
        uint32_t svb = sv_a + buf * FB_KV_BYTES;

        float sc[8][4];
        #pragma unroll
        for (int t = 0; t < 8; t++)
            #pragma unroll
            for (int j = 0; j < 4; j++) sc[t][j] = 0.0f;

        #pragma unroll
        for (int ks = 0; ks < 4; ks++) {
            uint32_t kb[8][2];
            #pragma unroll
            for (int p = 0; p < 4; p++) {
                uint32_t off = (uint32_t)((p * 16 + ((lane >> 3) & 1) * 8 + (lane & 7)) * FB_PAD
                             + ks * 16 + ((lane >> 4) << 3)) * 2;
                uint32_t r[4];
                LDSM4(r, skb + off);
                kb[2*p][0] = r[0]; kb[2*p][1] = r[2];
                kb[2*p+1][0] = r[1]; kb[2*p+1][1] = r[3];
            }
            #pragma unroll
            for (int t = 0; t < 8; t++) mma_bf16(sc[t], qa[ks], kb[t]);
        }

        float mt0 = -1e30f, mt1 = -1e30f;
        #pragma unroll
        for (int t = 0; t < 8; t++) {
            float a0 = sAA[buf][t * 8 + (lane & 3) * 2];
            float a1 = sAA[buf][t * 8 + (lane & 3) * 2 + 1];
            sc[t][0] = 0.25f * sc[t][0] - 0.125f * a0;
            sc[t][1] = 0.25f * sc[t][1] - 0.125f * a1;
            sc[t][2] = 0.25f * sc[t][2] - 0.125f * a0;
            sc[t][3] = 0.25f * sc[t][3] - 0.125f * a1;
            mt0 = fmaxf(mt0, fmaxf(sc[t][0], sc[t][1]));
            mt1 = fmaxf(mt1, fmaxf(sc[t][2], sc[t][3]));
        }
        mt0 = fmaxf(mt0, __shfl_xor_sync(0xffffffffu, mt0, 1));
        mt0 = fmaxf(mt0, __shfl_xor_sync(0xffffffffu, mt0, 2));
        mt1 = fmaxf(mt1, __shfl_xor_sync(0xffffffffu, mt1, 1));
        mt1 = fmaxf(mt1, __shfl_xor_sync(0xffffffffu, mt1, 2));

        float mn0 = fmaxf(m0, mt0), mn1 = fmaxf(m1, mt1);
        float al0 = __expf(m0 - mn0), al1 = __expf(m1 - mn1);
        m0 = mn0; m1 = mn1;
        l0 *= al0; l1 *= al1;
        #pragma unroll
        for (int t = 0; t < 8; t++) {
            o[t][0] *= al0; o[t][1] *= al0;
            o[t][2] *= al1; o[t][3] *= al1;
        }

        #pragma unroll
        for (int t = 0; t < 8; t++) {
            sc[t][0] = __expf(sc[t][0] - m0);
            sc[t][1] = __expf(sc[t][1] - m0);
            sc[t][2] = __expf(sc[t][2] - m1);
            sc[t][3] = __expf(sc[t][3] - m1);
            l0 += sc[t][0] + sc[t][1];
            l1 += sc[t][2] + sc[t][3];
        }

        #pragma unroll
        for (int j = 0; j < 4; j++) {
            uint32_t pa[4];
            __nv_bfloat162 t2;
            t2 = __floats2bfloat162_rn(sc[2*j][0],   sc[2*j][1]);   pa[0] = *(uint32_t*)&t2;
            t2 = __floats2bfloat162_rn(sc[2*j][2],   sc[2*j][3]);   pa[1] = *(uint32_t*)&t2;
            t2 = __floats2bfloat162_rn(sc[2*j+1][0], sc[2*j+1][1]); pa[2] = *(uint32_t*)&t2;
            t2 = __floats2bfloat162_rn(sc[2*j+1][2], sc[2*j+1][3]); pa[3] = *(uint32_t*)&t2;

            uint32_t vb[8][2];
            #pragma unroll
            for (int dp = 0; dp < 4; dp++) {
                int g = lane >> 3, rr = lane & 7;
                uint32_t off = (uint32_t)((j * 16 + (g & 1) * 8 + rr) * FB_PAD
                             + dp * 16 + (g >> 1) * 8) * 2;
                uint32_t r[4];
                LDSM4T(r, svb + off);
                vb[2*dp][0]   = r[0]; vb[2*dp][1]   = r[1];
                vb[2*dp+1][0] = r[2]; vb[2*dp+1][1] = r[3];
            }
            #pragma unroll
            for (int t = 0; t < 8; t++) mma_bf16(o[t], pa, vb[t]);
        }
    }

    l0 += __shfl_xor_sync(0xffffffffu, l0, 1);
    l0 += __shfl_xor_sync(0xffffffffu, l0, 2);
    l1 += __shfl_xor_sync(0xffffffffu, l1, 1);
    l1 += __shfl_xor_sync(0xffffffffu, l1, 2);
    float inv0 = 1.0f / l0, inv1 = 1.0f / l1;

    int r0g = q0 + w * 16 + (lane >> 2);
    #pragma unroll
    for (int t = 0; t < 8; t++) {
        int c = h * DHEAD + t * 8 + (lane & 3) * 2;
        float o00 = o[t][0] * inv0, o01 = o[t][1] * inv0;
        float o10 = o[t][2] * inv1, o11 = o[t][3] * inv1;
        size_t off0 = (size_t)(b * NSEQ + r0g) * DIM + c;
        size_t off1 = (size_t)(b * NSEQ + r0g + 8) * DIM + c;
        __nv_bfloat162 h0 = __floats2bfloat162_rn(o00, o01);
        __nv_bfloat162 h1 = __floats2bfloat162_rn(o10, o11);
        *(__nv_bfloat162*)(Ohi + off0) = h0;
        *(__nv_bfloat162*)(Ohi + off1) = h1;
        *(__nv_bfloat162*)(Olo + off0) = __floats2bfloat162_rn(
            o00 - __bfloat162float(h0.x), o01 - __bfloat162float(h0.y));
        *(__nv_bfloat162*)(Olo + off1) = __floats2bfloat162_rn(
            o10 - __bfloat162float(h1.x), o11 - __bfloat162float(h1.y));
    }
}

// ---------------- fused LayerNorm + hi/lo split ----------------
__global__ __launch_bounds__(128) void ln_split_kernel(
    const float* __restrict__ X, const float* __restrict__ w,
    const float* __restrict__ bb, __nv_bfloat16* __restrict__ Hi,
    __nv_bfloat16* __restrict__ Lo)
{
    int row = blockIdx.x;
    int tid = threadIdx.x;
    const float* xp = X + (size_t)row * DIM;
    float4 v = *(const float4*)(xp + tid * 4);
    float s  = v.x + v.y + v.z + v.w;
    float sq = v.x*v.x + v.y*v.y + v.z*v.z + v.w*v.w;
    #pragma unroll
    for (int o = 16; o > 0; o >>= 1) {
        s  += __shfl_xor_sync(0xffffffffu, s,  o);
        sq += __shfl_xor_sync(0xffffffffu, sq, o);
    }
    __shared__ float reds[4], redq[4];
    int wid = tid >> 5, lane = tid & 31;
    if (lane == 0) { reds[wid] = s; redq[wid] = sq; }
    __syncthreads();
    s  = reds[0] + reds[1] + reds[2] + reds[3];
    sq = redq[0] + redq[1] + redq[2] + redq[3];
    float mu   = s * (1.0f / DIM);
    float var  = sq * (1.0f / DIM) - mu * mu;
    float rstd = rsqrtf(var + 1e-5f);
    float4 wv = *(const float4*)(w  + tid * 4);
    float4 bv = *(const float4*)(bb + tid * 4);
    float o0 = (v.x - mu) * rstd * wv.x + bv.x;
    float o1 = (v.y - mu) * rstd * wv.y + bv.y;
    float o2 = (v.z - mu) * rstd * wv.z + bv.z;
    float o3 = (v.w - mu) * rstd * wv.w + bv.w;
    __nv_bfloat162 h0 = __floats2bfloat162_rn(o0, o1);
    __nv_bfloat162 h1 = __floats2bfloat162_rn(o2, o3);
    __nv_bfloat162 l0 = __floats2bfloat162_rn(o0 - __bfloat162float(h0.x),
                                              o1 - __bfloat162float(h0.y));
    __nv_bfloat162 l1 = __floats2bfloat162_rn(o2 - __bfloat162float(h1.x),
                                              o3 - __bfloat162float(h1.y));
    size_t off = (size_t)row * DIM + tid * 4;
    *(__nv_bfloat162*)(Hi + off) = h0;
    *(__nv_bfloat162*)(Hi + off + 2) = h1;
    *(__nv_bfloat162*)(Lo + off) = l0;
    *(__nv_bfloat162*)(Lo + off + 2) = l1;
}

// ---------------- weight transpose+split (vectorized: 32K x 128N tiles) ----------------
__global__ __launch_bounds__(256) void conv_wt_kernel(
    const float* __restrict__ W, __nv_bfloat16* __restrict__ Thi,
    __nv_bfloat16* __restrict__ Tlo, int K, int N)
{
    __shared__ __nv_bfloat16 shi[32][132];
    __shared__ __nv_bfloat16 slo[32][132];
    int tid = threadIdx.x;
    int tx = tid & 31;      // n-group (4 cols each)
    int ty = tid >> 5;      // 0..7
    int n0 = blockIdx.x * 128, k0 = blockIdx.y * 32;

    #pragma unroll
    for (int j = 0; j < 4; j++) {
        int k = ty + j * 8;
        float4 wv = *(const float4*)(W + (size_t)(k0 + k) * N + n0 + tx * 4);
        float f[4] = {wv.x, wv.y, wv.z, wv.w};
        #pragma unroll
        for (int i = 0; i < 4; i++) {
            __nv_bfloat16 hb = __float2bfloat16_rn(f[i]);
            shi[k][tx * 4 + i] = hb;
            slo[k][tx * 4 + i] = __float2bfloat16_rn(f[i] - __bfloat162float(hb));
        }
    }
    __syncthreads();

    int n  = tid >> 1;            // 0..127
    int kh = (tid & 1) * 16;      // 0 or 16
    uint4 uh, ul;
    uint32_t* uhp = (uint32_t*)&uh;
    uint32_t* ulp = (uint32_t*)&ul;
    #pragma unroll
    for (int half = 0; half < 2; half++) {
        #pragma unroll
        for (int p = 0; p < 4; p++) {
            int k = kh + half * 8 + p * 2;
            uhp[p] = (uint32_t)*(uint16_t*)&shi[k][n] |
                     ((uint32_t)*(uint16_t*)&shi[k + 1][n] << 16);
            ulp[p] = (uint32_t)*(uint16_t*)&slo[k][n] |
                     ((uint32_t)*(uint16_t*)&slo[k + 1][n] << 16);
        }
        size_t off = (size_t)(n0 + n) * K + k0 + kh + half * 8;
        *(uint4*)(Thi + off) = uh;
        *(uint4*)(Tlo + off) = ul;
    }
}

// ---------------- AA_j = |q_j|^2 from bf16 q ----------------
__global__ void aa_kernel(const __nv_bfloat16* __restrict__ Qb, float* __restrict__ AA)
{
    int idx = blockIdx.x * blockDim.x + threadIdx.x;
    if (idx >= ROWS * NHEAD) return;
    int h = idx & 7;
    int row = idx >> 3;
    const uint4* qp = (const uint4*)(Qb + (size_t)row * DIM + h * DHEAD);
    float s = 0.0f;
    #pragma unroll
    for (int i = 0; i < 8; i++) {
        uint4 u = qp[i];
        const __nv_bfloat162* p = (const __nv_bfloat162*)&u;
        #pragma unroll
        for (int j = 0; j < 4; j++) {
            float2 f = __bfloat1622float2(p[j]);
            s += f.x * f.x + f.y * f.y;
        }
    }
    int b = row >> 11, n = row & 2047;
    AA[((size_t)(b * NHEAD + h)) * NSEQ + n] = s;
}

// ---------------- GEGLU (bf16 input) + hi/lo split ----------------
__device__ __forceinline__ float gelu_exact(float x) {
    return 0.5f * x * (1.0f + erff(x * 0.70710678118654752f));
}
__global__ void geglu_split_kernel(const __nv_bfloat16* __restrict__ H,
                                   __nv_bfloat16* __restrict__ Hi,
                                   __nv_bfloat16* __restrict__ Lo)
{
    int idx = blockIdx.x * blockDim.x + threadIdx.x;
    if (idx >= ROWS * (IFF / 8)) return;
    int row = idx / (IFF / 8);
    int c8  = idx % (IFF / 8);
    const __nv_bfloat16* base = H + (size_t)row * (2 * IFF);
    uint4 au = *(const uint4*)(base + c8 * 8);
    uint4 gu = *(const uint4*)(base + IFF + c8 * 8);
    const __nv_bfloat162* ap = (const __nv_bfloat162*)&au;
    const __nv_bfloat162* gp = (const __nv_bfloat162*)&gu;
    uint4 ho, lo;
    uint32_t* hop = (uint32_t*)&ho;
    uint32_t* lop = (uint32_t*)&lo;
    #pragma unroll
    for (int j = 0; j < 4; j++) {
        float2 af = __bfloat1622float2(ap[j]);
        float2 gf = __bfloat1622float2(gp[j]);
        float r0 = af.x * gelu_exact(gf.x);
        float r1 = af.y * gelu_exact(gf.y);
        __nv_bfloat162 hb = __floats2bfloat162_rn(r0, r1);
        __nv_bfloat162 lb = __floats2bfloat162_rn(r0 - __bfloat162float(hb.x),
                                                  r1 - __bfloat162float(hb.y));
        hop[j] = *(uint32_t*)&hb;
        lop[j] = *(uint32_t*)&lb;
    }
    size_t off = (size_t)row * IFF + c8 * 8;
    *(uint4*)(Hi + off) = ho;
    *(uint4*)(Lo + off) = lo;
}

// ---------------- host orchestration ----------------
struct Bufs {
    float *x1, *x2, *aa;
    __nv_bfloat16 *hb;
    __nv_bfloat16 *ahi, *alo, *whi, *wlo, *qb, *vb;
};

static void conv_wt(const float* W, __nv_bfloat16* hi, __nv_bfloat16* lo, int K, int N) {
    dim3 grid(N / 128, K / 32);
    conv_wt_kernel<<<grid, 256>>>(W, hi, lo, K, N);
}
static void tc_gemm_f32_lo(const Bufs& B, const float* bias, const float* res,
                           float* C, int M, int N, int K) {
    dim3 grid(N / 64, M / 128);
    mma_gemm_kernel<true><<<grid, 256, GCfg<true>::SMEM>>>(
        B.ahi, B.alo, B.whi, B.wlo, bias, nullptr, res, C, nullptr, nullptr, M, N, K, 0);
}
static void tc_gemm_bf16_1x(const Bufs& B, const float* bias,
                            __nv_bfloat16* C, int M, int N, int K) {
    dim3 grid(N / 64, M / 128);
    mma_gemm_kernel<false><<<grid, 256, GCfg<false>::SMEM>>>(
        B.ahi, B.alo, B.whi, B.wlo, bias, nullptr, nullptr, nullptr, C, nullptr, M, N, K, 0);
}
static void tc_gemm_qv(const Bufs& B, const float* bq, const float* bv,
                       int M, int K) {
    dim3 grid(1024 / 64, M / 128);
    mma_gemm_kernel<false><<<grid, 256, GCfg<false>::SMEM>>>(
        B.ahi, B.alo, B.whi, B.wlo, bq, bv, nullptr, nullptr, B.qb, B.vb, M, 1024, K, 512);
}
static void run_attention(const Bufs& B) {
    int aa_blocks = (ROWS * NHEAD + 255) / 256;
    aa_kernel<<<aa_blocks, 256>>>(B.qb, B.aa);
    dim3 fa_grid(NSEQ / FB_BQ, NHEAD, NBATCH);
    flash_mma_kernel<<<fa_grid, 128>>>(B.qb, B.vb, B.aa, B.ahi, B.alo);
}

extern "C" void kernel_launch(void* const* d_in, const int* in_sizes, int n_in,
                              void* d_out, int out_size)
{
    const float* x     = (const float*)d_in[0];
    const float* sa_w  = (const float*)d_in[1];
    const float* sa_b  = (const float*)d_in[2];
    const float* ca_w  = (const float*)d_in[3];
    const float* ca_b  = (const float*)d_in[4];
    const float* ff_nw = (const float*)d_in[5];
    const float* ff_nb = (const float*)d_in[6];
    const float* a1_wq = (const float*)d_in[7];
    const float* a1_bq = (const float*)d_in[8];
    const float* a1_wv = (const float*)d_in[9];
    const float* a1_bv = (const float*)d_in[10];
    const float* a1_wo = (const float*)d_in[11];
    const float* a1_bo = (const float*)d_in[12];
    const float* a2_wq = (const float*)d_in[13];
    const float* a2_bq = (const float*)d_in[14];
    const float* a2_wv = (const float*)d_in[15];
    const float* a2_bv = (const float*)d_in[16];
    const float* a2_wo = (const float*)d_in[17];
    const float* a2_bo = (const float*)d_in[18];
    const float* ff_w1 = (const float*)d_in[19];
    const float* ff_b1 = (const float*)d_in[20];
    const float* ff_w2 = (const float*)d_in[21];
    const float* ff_b2 = (const float*)d_in[22];
    float* out = (float*)d_out;

    Bufs B;
    cudaGetSymbolAddress((void**)&B.x1,  g_x1);
    cudaGetSymbolAddress((void**)&B.x2,  g_x2);
    cudaGetSymbolAddress((void**)&B.aa,  g_aa);
    cudaGetSymbolAddress((void**)&B.hb,  g_h);
    cudaGetSymbolAddress((void**)&B.ahi, g_ahi);
    cudaGetSymbolAddress((void**)&B.alo, g_alo);
    cudaGetSymbolAddress((void**)&B.whi, g_whi);
    cudaGetSymbolAddress((void**)&B.wlo, g_wlo);
    cudaGetSymbolAddress((void**)&B.qb,  g_qb);
    cudaGetSymbolAddress((void**)&B.vb,  g_vb);

    cudaFuncSetAttribute(mma_gemm_kernel<true>,
                         cudaFuncAttributeMaxDynamicSharedMemorySize, GCfg<true>::SMEM);
    cudaFuncSetAttribute(mma_gemm_kernel<false>,
                         cudaFuncAttributeMaxDynamicSharedMemorySize, GCfg<false>::SMEM);

    // ---- self-attention (attn1) ----
    ln_split_kernel<<<ROWS, 128>>>(x, sa_w, sa_b, B.ahi, B.alo);
    conv_wt(a1_wq, B.whi, B.wlo, DIM, DIM);
    conv_wt(a1_wv, B.whi + DIM * DIM, B.wlo + DIM * DIM, DIM, DIM);
    tc_gemm_qv(B, a1_bq, a1_bv, ROWS, DIM);
    run_attention(B);
    conv_wt(a1_wo, B.whi, B.wlo, DIM, DIM);
    tc_gemm_f32_lo(B, a1_bo, x, B.x1, ROWS, DIM, DIM);

    // ---- attn2 (k=q, v from x) ----
    ln_split_kernel<<<ROWS, 128>>>(B.x1, ca_w, ca_b, B.ahi, B.alo);
    conv_wt(a2_wq, B.whi, B.wlo, DIM, DIM);
    conv_wt(a2_wv, B.whi + DIM * DIM, B.wlo + DIM * DIM, DIM, DIM);
    tc_gemm_qv(B, a2_bq, a2_bv, ROWS, DIM);
    run_attention(B);
    conv_wt(a2_wo, B.whi, B.wlo, DIM, DIM);
    tc_gemm_f32_lo(B, a2_bo, B.x1, B.x2, ROWS, DIM, DIM);

    // ---- GEGLU FFN ----
    ln_split_kernel<<<ROWS, 128>>>(B.x2, ff_nw, ff_nb, B.ahi, B.alo);
    conv_wt(ff_w1, B.whi, B.wlo, DIM, 2 * IFF);
    tc_gemm_bf16_1x(B, ff_b1, B.hb, ROWS, 2 * IFF, DIM);
    int ge_blocks = (ROWS * (IFF / 8) + 255) / 256;
    geglu_split_kernel<<<ge_blocks, 256>>>(B.hb, B.ahi, B.alo);
    conv_wt(ff_w2, B.whi, B.wlo, IFF, DIM);
    tc_gemm_f32_lo(B, ff_b2, B.x2, out, ROWS, DIM, IFF);
}

// round 16
// speedup vs baseline: 6.5981x; 1.0178x over previous
#include <cuda_runtime.h>
#include <cuda_bf16.h>
#include <cstdint>
#include <math.h>

#define ROWS 8192
#define DIM  512
#define NSEQ 2048
#define NBATCH 4
#define NHEAD 8
#define DHEAD 64
#define IFF  2048

// ---------------- scratch ----------------
__device__ float g_x1 [ROWS * DIM];
__device__ float g_x2 [ROWS * DIM];
__device__ float g_aa [NBATCH * NHEAD * NSEQ];
__device__ float g_h  [ROWS * 2 * IFF];        // FF1 out (bf16 reuse)
__device__ __nv_bfloat16 g_ahi[ROWS * IFF];
__device__ __nv_bfloat16 g_alo[ROWS * IFF];
__device__ __nv_bfloat16 g_whi[4096 * 512];
__device__ __nv_bfloat16 g_wlo[4096 * 512];
__device__ __nv_bfloat16 g_qb[ROWS * DIM];
__device__ __nv_bfloat16 g_vb[ROWS * DIM];

// =================== helpers ===================
__device__ __forceinline__ uint32_t smem_u32(const void* p) {
    uint32_t a;
    asm("{ .reg .u64 t; cvta.to.shared.u64 t, %1; cvt.u32.u64 %0, t; }" : "=r"(a) : "l"(p));
    return a;
}
#define LDSM4(r, addr) \
    asm volatile("ldmatrix.sync.aligned.m8n8.x4.shared.b16 {%0,%1,%2,%3}, [%4];" \
        : "=r"((r)[0]), "=r"((r)[1]), "=r"((r)[2]), "=r"((r)[3]) : "r"(addr))
#define LDSM4T(r, addr) \
    asm volatile("ldmatrix.sync.aligned.m8n8.x4.trans.shared.b16 {%0,%1,%2,%3}, [%4];" \
        : "=r"((r)[0]), "=r"((r)[1]), "=r"((r)[2]), "=r"((r)[3]) : "r"(addr))

__device__ __forceinline__ void mma_bf16(float* d, const uint32_t* a, const uint32_t* b) {
    asm volatile("mma.sync.aligned.m16n8k16.row.col.f32.bf16.bf16.f32 "
        "{%0,%1,%2,%3}, {%4,%5,%6,%7}, {%8,%9}, {%0,%1,%2,%3};"
        : "+f"(d[0]), "+f"(d[1]), "+f"(d[2]), "+f"(d[3])
        : "r"(a[0]), "r"(a[1]), "r"(a[2]), "r"(a[3]), "r"(b[0]), "r"(b[1]));
}
__device__ __forceinline__ void cp16(uint32_t saddr, const void* g) {
    asm volatile("cp.async.cg.shared.global [%0], [%1], 16;" :: "r"(saddr), "l"(g));
}
#define CP_COMMIT() asm volatile("cp.async.commit_group;" ::: "memory")
#define CP_WAIT1()  asm volatile("cp.async.wait_group 1;" ::: "memory")

#define MG_PAD    72
#define SA_BYTES  (128 * MG_PAD * 2)   // 18432
#define SB_BYTES  (64 * MG_PAD * 2)    // 9216

// =================== LO (hi/lo 3-MMA) GEMM: 128x64 tile, BK=64, 2-stage ===================
#define LO_OFF_AL SA_BYTES
#define LO_OFF_BH (2 * SA_BYTES)
#define LO_OFF_BL (2 * SA_BYTES + SB_BYTES)
#define LO_ST     (2 * SA_BYTES + 2 * SB_BYTES)   // 55296
#define LO_SMEM   (2 * LO_ST)                      // 110592

__global__ __launch_bounds__(256, 2) void mma_gemm_lo_kernel(
    const __nv_bfloat16* __restrict__ Ahi, const __nv_bfloat16* __restrict__ Alo,
    const __nv_bfloat16* __restrict__ Bhi, const __nv_bfloat16* __restrict__ Blo,
    const float* __restrict__ bias, const float* __restrict__ res,
    float* __restrict__ Cf, int M, int N, int K)
{
    extern __shared__ __nv_bfloat16 smem[];
    uint32_t sbase = smem_u32(smem);

    int tid = threadIdx.x, lane = tid & 31, wid = tid >> 5;
    int brow = blockIdx.y, bcol = blockIdx.x;
    int warp_m = (wid >> 1) * 32;
    int warp_n = (wid & 1) * 32;

    const __nv_bfloat16* Aat = Ahi + (size_t)(brow * 128) * K;
    const __nv_bfloat16* Aal = Alo + (size_t)(brow * 128) * K;
    const __nv_bfloat16* Bbt = Bhi + (size_t)(bcol * 64) * K;
    const __nv_bfloat16* Bbl = Blo + (size_t)(bcol * 64) * K;

    float acc[2][4][4];
    #pragma unroll
    for (int t = 0; t < 2; t++)
        #pragma unroll
        for (int nt = 0; nt < 4; nt++)
            #pragma unroll
            for (int j = 0; j < 4; j++) acc[t][nt][j] = 0.0f;

    int nchunk = K >> 6;

    auto load_chunk = [&](int c, int st) {
        uint32_t stb = sbase + st * LO_ST;
        #pragma unroll
        for (int i = 0; i < 4; i++) {
            int idx = tid + i * 256;
            int row = idx >> 3, ch = idx & 7;
            uint32_t so = stb + (uint32_t)(row * MG_PAD + ch * 8) * 2;
            size_t go = (size_t)row * K + c * 64 + ch * 8;
            cp16(so, Aat + go);
            cp16(so + LO_OFF_AL, Aal + go);
        }
        #pragma unroll
        for (int i = 0; i < 2; i++) {
            int idx = tid + i * 256;
            int row = idx >> 3, ch = idx & 7;
            uint32_t so = stb + (uint32_t)(row * MG_PAD + ch * 8) * 2;
            size_t go = (size_t)row * K + c * 64 + ch * 8;
            cp16(so + LO_OFF_BH, Bbt + go);
            cp16(so + LO_OFF_BL, Bbl + go);
        }
        CP_COMMIT();
    };

    load_chunk(0, 0);

    for (int c = 0; c < nchunk; c++) {
        int stage = c & 1;
        __syncthreads();
        if (c + 1 < nchunk) load_chunk(c + 1, (c + 1) & 1);
        else CP_COMMIT();
        CP_WAIT1();
        __syncthreads();

        uint32_t sa_h = sbase + stage * LO_ST;
        uint32_t sa_l = sa_h + LO_OFF_AL;
        uint32_t sb_h = sa_h + LO_OFF_BH;
        uint32_t sb_l = sa_h + LO_OFF_BL;

        #pragma unroll
        for (int ks = 0; ks < 4; ks++) {
            int kk = ks * 16;
            uint32_t ah[2][4], al[2][4];
            #pragma unroll
            for (int t = 0; t < 2; t++) {
                uint32_t off = (uint32_t)((warp_m + t * 16 + (lane & 15)) * MG_PAD
                             + kk + ((lane >> 4) << 3)) * 2;
                LDSM4(ah[t], sa_h + off);
                LDSM4(al[t], sa_l + off);
            }
            uint32_t bh[4][2], bl[4][2];
            #pragma unroll
            for (int p = 0; p < 2; p++) {
                uint32_t off = (uint32_t)((warp_n + p * 16 + ((lane >> 3) & 1) * 8 + (lane & 7)) * MG_PAD
                             + kk + ((lane >> 4) << 3)) * 2;
                uint32_t r[4];
                LDSM4(r, sb_h + off);
                bh[2*p][0] = r[0]; bh[2*p][1] = r[2];
                bh[2*p+1][0] = r[1]; bh[2*p+1][1] = r[3];
                LDSM4(r, sb_l + off);
                bl[2*p][0] = r[0]; bl[2*p][1] = r[2];
                bl[2*p+1][0] = r[1]; bl[2*p+1][1] = r[3];
            }
            #pragma unroll
            for (int t = 0; t < 2; t++)
                #pragma unroll
                for (int nt = 0; nt < 4; nt++) {
                    mma_bf16(acc[t][nt], ah[t], bh[nt]);
                    mma_bf16(acc[t][nt], ah[t], bl[nt]);
                    mma_bf16(acc[t][nt], al[t], bh[nt]);
                }
        }
    }

    int r0 = lane >> 2, c0 = (lane & 3) * 2;
    #pragma unroll
    for (int t = 0; t < 2; t++) {
        #pragma unroll
        for (int half = 0; half < 2; half++) {
            int grow = brow * 128 + warp_m + t * 16 + r0 + half * 8;
            #pragma unroll
            for (int nt = 0; nt < 4; nt++) {
                int gcol = bcol * 64 + warp_n + nt * 8 + c0;
                float ox = acc[t][nt][half * 2 + 0] + bias[gcol];
                float oy = acc[t][nt][half * 2 + 1] + bias[gcol + 1];
                if (res) {
                    float2 rv = *(const float2*)(res + (size_t)grow * N + gcol);
                    ox += rv.x; oy += rv.y;
                }
                float2 o; o.x = ox; o.y = oy;
                *(float2*)(Cf + (size_t)grow * N + gcol) = o;
            }
        }
    }
}

// =================== 1x (single-bf16) GEMM: 128x128 tile, warp 32x64, BK=64, 3-stage ===================
#define X1_OFF_B  SA_BYTES
#define X1_ST     (2 * SA_BYTES)     // A 128 rows + B 128 rows = 36864
#define X1_SMEM   (3 * X1_ST)        // 110592

__global__ __launch_bounds__(256, 2) void mma_gemm1x_kernel(
    const __nv_bfloat16* __restrict__ Ahi,
    const __nv_bfloat16* __restrict__ Bhi,
    const float* __restrict__ bias, const float* __restrict__ bias2,
    __nv_bfloat16* __restrict__ Cb, __nv_bfloat16* __restrict__ Cb2,
    int M, int N, int K, int Nh)
{
    extern __shared__ __nv_bfloat16 smem[];
    uint32_t sbase = smem_u32(smem);

    int tid = threadIdx.x, lane = tid & 31, wid = tid >> 5;
    int brow = blockIdx.y, bcol = blockIdx.x;
    int warp_m = (wid >> 1) * 32;
    int warp_n = (wid & 1) * 64;

    const __nv_bfloat16* Aat = Ahi + (size_t)(brow * 128) * K;
    const __nv_bfloat16* Bbt = Bhi + (size_t)(bcol * 128) * K;

    float acc[2][8][4];
    #pragma unroll
    for (int t = 0; t < 2; t++)
        #pragma unroll
        for (int nt = 0; nt < 8; nt++)
            #pragma unroll
            for (int j = 0; j < 4; j++) acc[t][nt][j] = 0.0f;

    int nchunk = K >> 6;

    auto load_chunk = [&](int c, int st) {
        uint32_t stb = sbase + st * X1_ST;
        #pragma unroll
        for (int i = 0; i < 4; i++) {
            int idx = tid + i * 256;
            int row = idx >> 3, ch = idx & 7;
            uint32_t so = stb + (uint32_t)(row * MG_PAD + ch * 8) * 2;
            size_t go = (size_t)row * K + c * 64 + ch * 8;
            cp16(so, Aat + go);
            cp16(so + X1_OFF_B, Bbt + go);
        }
        CP_COMMIT();
    };

    load_chunk(0, 0);
    load_chunk(1 < nchunk ? 1 : 0, 1);   // K>=128 always here (K=512/2048)

    for (int c = 0; c < nchunk; c++) {
        int stage = c % 3;
        CP_WAIT1();
        __syncthreads();
        if (c + 2 < nchunk) load_chunk(c + 2, (c + 2) % 3);
        else CP_COMMIT();

        uint32_t sa = sbase + stage * X1_ST;
        uint32_t sb = sa + X1_OFF_B;

        #pragma unroll
        for (int ks = 0; ks < 4; ks++) {
            int kk = ks * 16;
            uint32_t ah[2][4];
            #pragma unroll
            for (int t = 0; t < 2; t++) {
                uint32_t off = (uint32_t)((warp_m + t * 16 + (lane & 15)) * MG_PAD
                             + kk + ((lane >> 4) << 3)) * 2;
                LDSM4(ah[t], sa + off);
            }
            uint32_t bh[8][2];
            #pragma unroll
            for (int p = 0; p < 4; p++) {
                uint32_t off = (uint32_t)((warp_n + p * 16 + ((lane >> 3) & 1) * 8 + (lane & 7)) * MG_PAD
                             + kk + ((lane >> 4) << 3)) * 2;
                uint32_t r[4];
                LDSM4(r, sb + off);
                bh[2*p][0] = r[0]; bh[2*p][1] = r[2];
                bh[2*p+1][0] = r[1]; bh[2*p+1][1] = r[3];
            }
            #pragma unroll
            for (int t = 0; t < 2; t++)
                #pragma unroll
                for (int nt = 0; nt < 8; nt++)
                    mma_bf16(acc[t][nt], ah[t], bh[nt]);
        }
    }

    int r0 = lane >> 2, c0 = (lane & 3) * 2;
    #pragma unroll
    for (int t = 0; t < 2; t++) {
        #pragma unroll
        for (int half = 0; half < 2; half++) {
            int grow = brow * 128 + warp_m + t * 16 + r0 + half * 8;
            #pragma unroll
            for (int nt = 0; nt < 8; nt++) {
                int gcol = bcol * 128 + warp_n + nt * 8 + c0;
                float ox = acc[t][nt][half * 2 + 0];
                float oy = acc[t][nt][half * 2 + 1];
                __nv_bfloat16* dst; const float* bs; int cc;
                if (Cb2 && gcol >= Nh) { dst = Cb2; bs = bias2; cc = gcol - Nh; }
                else                   { dst = Cb;  bs = bias;  cc = gcol; }
                int nw = Cb2 ? Nh : N;
                ox += bs[cc]; oy += bs[cc + 1];
                *(__nv_bfloat162*)(dst + (size_t)grow * nw + cc) =
                    __floats2bfloat162_rn(ox, oy);
            }
        }
    }
}

// =================== HMMA flash attention, cp.async double-buffered K/V ===================
#define FB_BQ 64
#define FB_BK 64
#define FB_PAD 72
#define FB_KV_BYTES (FB_BK * FB_PAD * 2)

__global__ __launch_bounds__(128) void flash_mma_kernel(
    const __nv_bfloat16* __restrict__ Qb, const __nv_bfloat16* __restrict__ Vb,
    const float* __restrict__ AA,
    __nv_bfloat16* __restrict__ Ohi, __nv_bfloat16* __restrict__ Olo)
{
    __shared__ __nv_bfloat16 sQ[FB_BQ * FB_PAD];
    __shared__ __nv_bfloat16 sK[2][FB_BK * FB_PAD];
    __shared__ __nv_bfloat16 sV[2][FB_BK * FB_PAD];
    __shared__ float sAA[2][FB_BK];

    int b = blockIdx.z, h = blockIdx.y;
    int q0 = blockIdx.x * FB_BQ;
    int tid = threadIdx.x, lane = tid & 31, w = tid >> 5;

    uint32_t sq_a = smem_u32(sQ);
    uint32_t sk_a = smem_u32(sK);
    uint32_t sv_a = smem_u32(sV);

    #pragma unroll
    for (int i = 0; i < 4; i++) {
        int idx = tid + i * 128;
        int r = idx >> 3, c = idx & 7;
        size_t off = (size_t)(b * NSEQ + r) * DIM + h * DHEAD + c * 8;
        uint32_t so = (uint32_t)(r * FB_PAD + c * 8) * 2;
        cp16(sk_a + so, Qb + off);
        cp16(sv_a + so, Vb + off);
    }
    CP_COMMIT();

    #pragma unroll
    for (int i = 0; i < 4; i++) {
        int idx = tid + i * 128;
        int r = idx >> 3, c = idx & 7;
        size_t off = (size_t)(b * NSEQ + q0 + r) * DIM + h * DHEAD + c * 8;
        *(uint4*)&sQ[r * FB_PAD + c * 8] = *(const uint4*)(Qb + off);
    }
    __syncthreads();

    uint32_t qa[4][4];
    #pragma unroll
    for (int ks = 0; ks < 4; ks++) {
        uint32_t off = (uint32_t)((w * 16 + (lane & 15)) * FB_PAD + ks * 16 + ((lane >> 4) << 3)) * 2;
        LDSM4(qa[ks], sq_a + off);
    }

    float m0 = -1e30f, m1 = -1e30f, l0 = 0.0f, l1 = 0.0f;
    float o[8][4];
    #pragma unroll
    for (int t = 0; t < 8; t++)
        #pragma unroll
        for (int j = 0; j < 4; j++) o[t][j] = 0.0f;

    const float* aab = AA + ((size_t)(b * NHEAD + h)) * NSEQ;
    const int ntiles = NSEQ / FB_BK;

    for (int it = 0; it < ntiles; it++) {
        int buf = it & 1;
        __syncthreads();

        if (it + 1 < ntiles) {
            uint32_t dst_k = sk_a + (buf ^ 1) * FB_KV_BYTES;
            uint32_t dst_v = sv_a + (buf ^ 1) * FB_KV_BYTES;
            #pragma unroll
            for (int i = 0; i < 4; i++) {
                int idx = tid + i * 128;
                int r = idx >> 3, c = idx & 7;
                size_t off = (size_t)(b * NSEQ + (it + 1) * FB_BK + r) * DIM + h * DHEAD + c * 8;
                uint32_t so = (uint32_t)(r * FB_PAD + c * 8) * 2;
                cp16(dst_k + so, Qb + off);
                cp16(dst_v + so, Vb + off);
            }
        }
        CP_COMMIT();
        if (tid < FB_BK) sAA[buf][tid] = aab[it * FB_BK + tid];
        CP_WAIT1();
        __syncthreads();

        uint32_t skb = sk_a + buf * FB_KV_BYTES;
        uint32_t svb = sv_a + buf * FB_KV_BYTES;

        float sc[8][4];
        #pragma unroll
        for (int t = 0; t < 8; t++)
            #pragma unroll
            for (int j = 0; j < 4; j++) sc[t][j] = 0.0f;

        #pragma unroll
        for (int ks = 0; ks < 4; ks++) {
            uint32_t kb[8][2];
            #pragma unroll
            for (int p = 0; p < 4; p++) {
                uint32_t off = (uint32_t)((p * 16 + ((lane >> 3) & 1) * 8 + (lane & 7)) * FB_PAD
                             + ks * 16 + ((lane >> 4) << 3)) * 2;
                uint32_t r[4];
                LDSM4(r, skb + off);
                kb[2*p][0] = r[0]; kb[2*p][1] = r[2];
                kb[2*p+1][0] = r[1]; kb[2*p+1][1] = r[3];
            }
            #pragma unroll
            for (int t = 0; t < 8; t++) mma_bf16(sc[t], qa[ks], kb[t]);
        }

        float mt0 = -1e30f, mt1 = -1e30f;
        #pragma unroll
        for (int t = 0; t < 8; t++) {
            float a0 = sAA[buf][t * 8 + (lane & 3) * 2];
            float a1 = sAA[buf][t * 8 + (lane & 3) * 2 + 1];
            sc[t][0] = 0.25f * sc[t][0] - 0.125f * a0;
            sc[t][1] = 0.25f * sc[t][1] - 0.125f * a1;
            sc[t][2] = 0.25f * sc[t][2] - 0.125f * a0;
            sc[t][3] = 0.25f * sc[t][3] - 0.125f * a1;
            mt0 = fmaxf(mt0, fmaxf(sc[t][0], sc[t][1]));
            mt1 = fmaxf(mt1, fmaxf(sc[t][2], sc[t][3]));
        }
        mt0 = fmaxf(mt0, __shfl_xor_sync(0xffffffffu, mt0, 1));
        mt0 = fmaxf(mt0, __shfl_xor_sync(0xffffffffu, mt0, 2));
        mt1 = fmaxf(mt1, __shfl_xor_sync(0xffffffffu, mt1, 1));
        mt1 = fmaxf(mt1, __shfl_xor_sync(0xffffffffu, mt1, 2));

        float mn0 = fmaxf(m0, mt0), mn1 = fmaxf(m1, mt1);
        float al0 = __expf(m0 - mn0), al1 = __expf(m1 - mn1);
        m0 = mn0; m1 = mn1;
        l0 *= al0; l1 *= al1;
        #pragma unroll
        for (int t = 0; t < 8; t++) {
            o[t][0] *= al0; o[t][1] *= al0;
            o[t][2] *= al1; o[t][3] *= al1;
        }

        #pragma unroll
        for (int t = 0; t < 8; t++) {
            sc[t][0] = __expf(sc[t][0] - m0);
            sc[t][1] = __expf(sc[t][1] - m0);
            sc[t][2] = __expf(sc[t][2] - m1);
            sc[t][3] = __expf(sc[t][3] - m1);
            l0 += sc[t][0] + sc[t][1];
            l1 += sc[t][2] + sc[t][3];
        }

        #pragma unroll
        for (int j = 0; j < 4; j++) {
            uint32_t pa[4];
            __nv_bfloat162 t2;
            t2 = __floats2bfloat162_rn(sc[2*j][0],   sc[2*j][1]);   pa[0] = *(uint32_t*)&t2;
            t2 = __floats2bfloat162_rn(sc[2*j][2],   sc[2*j][3]);   pa[1] = *(uint32_t*)&t2;
            t2 = __floats2bfloat162_rn(sc[2*j+1][0], sc[2*j+1][1]); pa[2] = *(uint32_t*)&t2;
            t2 = __floats2bfloat162_rn(sc[2*j+1][2], sc[2*j+1][3]); pa[3] = *(uint32_t*)&t2;

            uint32_t vb[8][2];
            #pragma unroll
            for (int dp = 0; dp < 4; dp++) {
                int g = lane >> 3, rr = lane & 7;
                uint32_t off = (uint32_t)((j * 16 + (g & 1) * 8 + rr) * FB_PAD
                             + dp * 16 + (g >> 1) * 8) * 2;
                uint32_t r[4];
                LDSM4T(r, svb + off);
                vb[2*dp][0]   = r[0]; vb[2*dp][1]   = r[1];
                vb[2*dp+1][0] = r[2]; vb[2*dp+1][1] = r[3];
            }
            #pragma unroll
            for (int t = 0; t < 8; t++) mma_bf16(o[t], pa, vb[t]);
        }
    }

    l0 += __shfl_xor_sync(0xffffffffu, l0, 1);
    l0 += __shfl_xor_sync(0xffffffffu, l0, 2);
    l1 += __shfl_xor_sync(0xffffffffu, l1, 1);
    l1 += __shfl_xor_sync(0xffffffffu, l1, 2);
    float inv0 = 1.0f / l0, inv1 = 1.0f / l1;

    int r0g = q0 + w * 16 + (lane >> 2);
    #pragma unroll
    for (int t = 0; t < 8; t++) {
        int c = h * DHEAD + t * 8 + (lane & 3) * 2;
        float o00 = o[t][0] * inv0, o01 = o[t][1] * inv0;
        float o10 = o[t][2] * inv1, o11 = o[t][3] * inv1;
        size_t off0 = (size_t)(b * NSEQ + r0g) * DIM + c;
        size_t off1 = (size_t)(b * NSEQ + r0g + 8) * DIM + c;
        __nv_bfloat162 h0 = __floats2bfloat162_rn(o00, o01);
        __nv_bfloat162 h1 = __floats2bfloat162_rn(o10, o11);
        *(__nv_bfloat162*)(Ohi + off0) = h0;
        *(__nv_bfloat162*)(Ohi + off1) = h1;
        *(__nv_bfloat162*)(Olo + off0) = __floats2bfloat162_rn(
            o00 - __bfloat162float(h0.x), o01 - __bfloat162float(h0.y));
        *(__nv_bfloat162*)(Olo + off1) = __floats2bfloat162_rn(
            o10 - __bfloat162float(h1.x), o11 - __bfloat162float(h1.y));
    }
}

// ---------------- fused LayerNorm + hi/lo split ----------------
__global__ __launch_bounds__(128) void ln_split_kernel(
    const float* __restrict__ X, const float* __restrict__ w,
    const float* __restrict__ bb, __nv_bfloat16* __restrict__ Hi,
    __nv_bfloat16* __restrict__ Lo)
{
    int row = blockIdx.x;
    int tid = threadIdx.x;
    const float* xp = X + (size_t)row * DIM;
    float4 v = *(const float4*)(xp + tid * 4);
    float s  = v.x + v.y + v.z + v.w;
    float sq = v.x*v.x + v.y*v.y + v.z*v.z + v.w*v.w;
    #pragma unroll
    for (int o = 16; o > 0; o >>= 1) {
        s  += __shfl_xor_sync(0xffffffffu, s,  o);
        sq += __shfl_xor_sync(0xffffffffu, sq, o);
    }
    __shared__ float reds[4], redq[4];
    int wid = tid >> 5, lane = tid & 31;
    if (lane == 0) { reds[wid] = s; redq[wid] = sq; }
    __syncthreads();
    s  = reds[0] + reds[1] + reds[2] + reds[3];
    sq = redq[0] + redq[1] + redq[2] + redq[3];
    float mu   = s * (1.0f / DIM);
    float var  = sq * (1.0f / DIM) - mu * mu;
    float rstd = rsqrtf(var + 1e-5f);
    float4 wv = *(const float4*)(w  + tid * 4);
    float4 bv = *(const float4*)(bb + tid * 4);
    float o0 = (v.x - mu) * rstd * wv.x + bv.x;
    float o1 = (v.y - mu) * rstd * wv.y + bv.y;
    float o2 = (v.z - mu) * rstd * wv.z + bv.z;
    float o3 = (v.w - mu) * rstd * wv.w + bv.w;
    __nv_bfloat162 h0 = __floats2bfloat162_rn(o0, o1);
    __nv_bfloat162 h1 = __floats2bfloat162_rn(o2, o3);
    __nv_bfloat162 l0 = __floats2bfloat162_rn(o0 - __bfloat162float(h0.x),
                                              o1 - __bfloat162float(h0.y));
    __nv_bfloat162 l1 = __floats2bfloat162_rn(o2 - __bfloat162float(h1.x),
                                              o3 - __bfloat162float(h1.y));
    size_t off = (size_t)row * DIM + tid * 4;
    *(__nv_bfloat162*)(Hi + off) = h0;
    *(__nv_bfloat162*)(Hi + off + 2) = h1;
    *(__nv_bfloat162*)(Lo + off) = l0;
    *(__nv_bfloat162*)(Lo + off + 2) = l1;
}

// ---------------- weight transpose+split (vectorized) ----------------
__global__ __launch_bounds__(256) void conv_wt_kernel(
    const float* __restrict__ W, __nv_bfloat16* __restrict__ Thi,
    __nv_bfloat16* __restrict__ Tlo, int K, int N)
{
    __shared__ __nv_bfloat16 shi[32][132];
    __shared__ __nv_bfloat16 slo[32][132];
    int tid = threadIdx.x;
    int tx = tid & 31;
    int ty = tid >> 5;
    int n0 = blockIdx.x * 128, k0 = blockIdx.y * 32;

    #pragma unroll
    for (int j = 0; j < 4; j++) {
        int k = ty + j * 8;
        float4 wv = *(const float4*)(W + (size_t)(k0 + k) * N + n0 + tx * 4);
        float f[4] = {wv.x, wv.y, wv.z, wv.w};
        #pragma unroll
        for (int i = 0; i < 4; i++) {
            __nv_bfloat16 hb = __float2bfloat16_rn(f[i]);
            shi[k][tx * 4 + i] = hb;
            slo[k][tx * 4 + i] = __float2bfloat16_rn(f[i] - __bfloat162float(hb));
        }
    }
    __syncthreads();

    int n  = tid >> 1;
    int kh = (tid & 1) * 16;
    uint4 uh, ul;
    uint32_t* uhp = (uint32_t*)&uh;
    uint32_t* ulp = (uint32_t*)&ul;
    #pragma unroll
    for (int half = 0; half < 2; half++) {
        #pragma unroll
        for (int p = 0; p < 4; p++) {
            int k = kh + half * 8 + p * 2;
            uhp[p] = (uint32_t)*(uint16_t*)&shi[k][n] |
                     ((uint32_t)*(uint16_t*)&shi[k + 1][n] << 16);
            ulp[p] = (uint32_t)*(uint16_t*)&slo[k][n] |
                     ((uint32_t)*(uint16_t*)&slo[k + 1][n] << 16);
        }
        size_t off = (size_t)(n0 + n) * K + k0 + kh + half * 8;
        *(uint4*)(Thi + off) = uh;
        *(uint4*)(Tlo + off) = ul;
    }
}

// ---------------- AA_j = |q_j|^2 from bf16 q ----------------
__global__ void aa_kernel(const __nv_bfloat16* __restrict__ Qb, float* __restrict__ AA)
{
    int idx = blockIdx.x * blockDim.x + threadIdx.x;
    if (idx >= ROWS * NHEAD) return;
    int h = idx & 7;
    int row = idx >> 3;
    const uint4* qp = (const uint4*)(Qb + (size_t)row * DIM + h * DHEAD);
    float s = 0.0f;
    #pragma unroll
    for (int i = 0; i < 8; i++) {
        uint4 u = qp[i];
        const __nv_bfloat162* p = (const __nv_bfloat162*)&u;
        #pragma unroll
        for (int j = 0; j < 4; j++) {
            float2 f = __bfloat1622float2(p[j]);
            s += f.x * f.x + f.y * f.y;
        }
    }
    int b = row >> 11, n = row & 2047;
    AA[((size_t)(b * NHEAD + h)) * NSEQ + n] = s;
}

// ---------------- GEGLU (bf16 input) + hi/lo split ----------------
__device__ __forceinline__ float gelu_exact(float x) {
    return 0.5f * x * (1.0f + erff(x * 0.70710678118654752f));
}
__global__ void geglu_split_kernel(const __nv_bfloat16* __restrict__ H,
                                   __nv_bfloat16* __restrict__ Hi,
                                   __nv_bfloat16* __restrict__ Lo)
{
    int idx = blockIdx.x * blockDim.x + threadIdx.x;
    if (idx >= ROWS * (IFF / 8)) return;
    int row = idx / (IFF / 8);
    int c8  = idx % (IFF / 8);
    const __nv_bfloat16* base = H + (size_t)row * (2 * IFF);
    uint4 au = *(const uint4*)(base + c8 * 8);
    uint4 gu = *(const uint4*)(base + IFF + c8 * 8);
    const __nv_bfloat162* ap = (const __nv_bfloat162*)&au;
    const __nv_bfloat162* gp = (const __nv_bfloat162*)&gu;
    uint4 ho, lo;
    uint32_t* hop = (uint32_t*)&ho;
    uint32_t* lop = (uint32_t*)&lo;
    #pragma unroll
    for (int j = 0; j < 4; j++) {
        float2 af = __bfloat1622float2(ap[j]);
        float2 gf = __bfloat1622float2(gp[j]);
        float r0 = af.x * gelu_exact(gf.x);
        float r1 = af.y * gelu_exact(gf.y);
        __nv_bfloat162 hb = __floats2bfloat162_rn(r0, r1);
        __nv_bfloat162 lb = __floats2bfloat162_rn(r0 - __bfloat162float(hb.x),
                                                  r1 - __bfloat162float(hb.y));
        hop[j] = *(uint32_t*)&hb;
        lop[j] = *(uint32_t*)&lb;
    }
    size_t off = (size_t)row * IFF + c8 * 8;
    *(uint4*)(Hi + off) = ho;
    *(uint4*)(Lo + off) = lo;
}

// ---------------- host orchestration ----------------
struct Bufs {
    float *x1, *x2, *aa;
    __nv_bfloat16 *hb;
    __nv_bfloat16 *ahi, *alo, *whi, *wlo, *qb, *vb;
};

static void conv_wt(const float* W, __nv_bfloat16* hi, __nv_bfloat16* lo, int K, int N) {
    dim3 grid(N / 128, K / 32);
    conv_wt_kernel<<<grid, 256>>>(W, hi, lo, K, N);
}
static void tc_gemm_f32_lo(const Bufs& B, const float* bias, const float* res,
                           float* C, int M, int N, int K) {
    dim3 grid(N / 64, M / 128);
    mma_gemm_lo_kernel<<<grid, 256, LO_SMEM>>>(
        B.ahi, B.alo, B.whi, B.wlo, bias, res, C, M, N, K);
}
static void tc_gemm_bf16_1x(const Bufs& B, const float* bias,
                            __nv_bfloat16* C, int M, int N, int K) {
    dim3 grid(N / 128, M / 128);
    mma_gemm1x_kernel<<<grid, 256, X1_SMEM>>>(
        B.ahi, B.whi, bias, nullptr, C, nullptr, M, N, K, 0);
}
static void tc_gemm_qv(const Bufs& B, const float* bq, const float* bv,
                       int M, int K) {
    dim3 grid(1024 / 128, M / 128);
    mma_gemm1x_kernel<<<grid, 256, X1_SMEM>>>(
        B.ahi, B.whi, bq, bv, B.qb, B.vb, M, 1024, K, 512);
}
static void run_attention(const Bufs& B) {
    int aa_blocks = (ROWS * NHEAD + 255) / 256;
    aa_kernel<<<aa_blocks, 256>>>(B.qb, B.aa);
    dim3 fa_grid(NSEQ / FB_BQ, NHEAD, NBATCH);
    flash_mma_kernel<<<fa_grid, 128>>>(B.qb, B.vb, B.aa, B.ahi, B.alo);
}

extern "C" void kernel_launch(void* const* d_in, const int* in_sizes, int n_in,
                              void* d_out, int out_size)
{
    const float* x     = (const float*)d_in[0];
    const float* sa_w  = (const float*)d_in[1];
    const float* sa_b  = (const float*)d_in[2];
    const float* ca_w  = (const float*)d_in[3];
    const float* ca_b  = (const float*)d_in[4];
    const float* ff_nw = (const float*)d_in[5];
    const float* ff_nb = (const float*)d_in[6];
    const float* a1_wq = (const float*)d_in[7];
    const float* a1_bq = (const float*)d_in[8];
    const float* a1_wv = (const float*)d_in[9];
    const float* a1_bv = (const float*)d_in[10];
    const float* a1_wo = (const float*)d_in[11];
    const float* a1_bo = (const float*)d_in[12];
    const float* a2_wq = (const float*)d_in[13];
    const float* a2_bq = (const float*)d_in[14];
    const float* a2_wv = (const float*)d_in[15];
    const float* a2_bv = (const float*)d_in[16];
    const float* a2_wo = (const float*)d_in[17];
    const float* a2_bo = (const float*)d_in[18];
    const float* ff_w1 = (const float*)d_in[19];
    const float* ff_b1 = (const float*)d_in[20];
    const float* ff_w2 = (const float*)d_in[21];
    const float* ff_b2 = (const float*)d_in[22];
    float* out = (float*)d_out;

    Bufs B;
    cudaGetSymbolAddress((void**)&B.x1,  g_x1);
    cudaGetSymbolAddress((void**)&B.x2,  g_x2);
    cudaGetSymbolAddress((void**)&B.aa,  g_aa);
    cudaGetSymbolAddress((void**)&B.hb,  g_h);
    cudaGetSymbolAddress((void**)&B.ahi, g_ahi);
    cudaGetSymbolAddress((void**)&B.alo, g_alo);
    cudaGetSymbolAddress((void**)&B.whi, g_whi);
    cudaGetSymbolAddress((void**)&B.wlo, g_wlo);
    cudaGetSymbolAddress((void**)&B.qb,  g_qb);
    cudaGetSymbolAddress((void**)&B.vb,  g_vb);

    cudaFuncSetAttribute(mma_gemm_lo_kernel,
                         cudaFuncAttributeMaxDynamicSharedMemorySize, LO_SMEM);
    cudaFuncSetAttribute(mma_gemm1x_kernel,
                         cudaFuncAttributeMaxDynamicSharedMemorySize, X1_SMEM);

    // ---- self-attention (attn1) ----
    ln_split_kernel<<<ROWS, 128>>>(x, sa_w, sa_b, B.ahi, B.alo);
    conv_wt(a1_wq, B.whi, B.wlo, DIM, DIM);
    conv_wt(a1_wv, B.whi + DIM * DIM, B.wlo + DIM * DIM, DIM, DIM);
    tc_gemm_qv(B, a1_bq, a1_bv, ROWS, DIM);
    run_attention(B);
    conv_wt(a1_wo, B.whi, B.wlo, DIM, DIM);
    tc_gemm_f32_lo(B, a1_bo, x, B.x1, ROWS, DIM, DIM);

    // ---- attn2 (k=q, v from x) ----
    ln_split_kernel<<<ROWS, 128>>>(B.x1, ca_w, ca_b, B.ahi, B.alo);
    conv_wt(a2_wq, B.whi, B.wlo, DIM, DIM);
    conv_wt(a2_wv, B.whi + DIM * DIM, B.wlo + DIM * DIM, DIM, DIM);
    tc_gemm_qv(B, a2_bq, a2_bv, ROWS, DIM);
    run_attention(B);
    conv_wt(a2_wo, B.whi, B.wlo, DIM, DIM);
    tc_gemm_f32_lo(B, a2_bo, B.x1, B.x2, ROWS, DIM, DIM);

    // ---- GEGLU FFN ----
    ln_split_kernel<<<ROWS, 128>>>(B.x2, ff_nw, ff_nb, B.ahi, B.alo);
    conv_wt(ff_w1, B.whi, B.wlo, DIM, 2 * IFF);
    tc_gemm_bf16_1x(B, ff_b1, B.hb, ROWS, 2 * IFF, DIM);
    int ge_blocks = (ROWS * (IFF / 8) + 255) / 256;
    geglu_split_kernel<<<ge_blocks, 256>>>(B.hb, B.ahi, B.alo);
    conv_wt(ff_w2, B.whi, B.wlo, IFF, DIM);
    tc_gemm_f32_lo(B, ff_b2, B.x2, out, ROWS, DIM, IFF);
}

// round 17
// speedup vs baseline: 6.8178x; 1.0333x over previous
#include <cuda_runtime.h>
#include <cuda_bf16.h>
#include <cstdint>
#include <math.h>

#define ROWS 8192
#define DIM  512
#define NSEQ 2048
#define NBATCH 4
#define NHEAD 8
#define DHEAD 64
#define IFF  2048
#define WS   (DIM * DIM)   // 262144 elems, unit weight slab

// ---------------- scratch ----------------
__device__ float g_x1 [ROWS * DIM];
__device__ float g_x2 [ROWS * DIM];
__device__ float g_aa [NBATCH * NHEAD * NSEQ];
__device__ float g_h  [ROWS * 2 * IFF];        // FF1 out (bf16 reuse)
__device__ __nv_bfloat16 g_ahi[ROWS * IFF];
__device__ __nv_bfloat16 g_alo[ROWS * IFF];
__device__ __nv_bfloat16 g_whi[18 * WS];       // all transposed weights, hi
__device__ __nv_bfloat16 g_wlo[18 * WS];       // all transposed weights, lo
__device__ __nv_bfloat16 g_qb[ROWS * DIM];
__device__ __nv_bfloat16 g_vb[ROWS * DIM];

// =================== helpers ===================
__device__ __forceinline__ uint32_t smem_u32(const void* p) {
    uint32_t a;
    asm("{ .reg .u64 t; cvta.to.shared.u64 t, %1; cvt.u32.u64 %0, t; }" : "=r"(a) : "l"(p));
    return a;
}
#define LDSM4(r, addr) \
    asm volatile("ldmatrix.sync.aligned.m8n8.x4.shared.b16 {%0,%1,%2,%3}, [%4];" \
        : "=r"((r)[0]), "=r"((r)[1]), "=r"((r)[2]), "=r"((r)[3]) : "r"(addr))
#define LDSM4T(r, addr) \
    asm volatile("ldmatrix.sync.aligned.m8n8.x4.trans.shared.b16 {%0,%1,%2,%3}, [%4];" \
        : "=r"((r)[0]), "=r"((r)[1]), "=r"((r)[2]), "=r"((r)[3]) : "r"(addr))

__device__ __forceinline__ void mma_bf16(float* d, const uint32_t* a, const uint32_t* b) {
    asm volatile("mma.sync.aligned.m16n8k16.row.col.f32.bf16.bf16.f32 "
        "{%0,%1,%2,%3}, {%4,%5,%6,%7}, {%8,%9}, {%0,%1,%2,%3};"
        : "+f"(d[0]), "+f"(d[1]), "+f"(d[2]), "+f"(d[3])
        : "r"(a[0]), "r"(a[1]), "r"(a[2]), "r"(a[3]), "r"(b[0]), "r"(b[1]));
}
__device__ __forceinline__ void cp16(uint32_t saddr, const void* g) {
    asm volatile("cp.async.cg.shared.global [%0], [%1], 16;" :: "r"(saddr), "l"(g));
}
#define CP_COMMIT() asm volatile("cp.async.commit_group;" ::: "memory")
#define CP_WAIT1()  asm volatile("cp.async.wait_group 1;" ::: "memory")

#define MG_PAD    72
#define SA_BYTES  (128 * MG_PAD * 2)   // 18432
#define SB_BYTES  (64 * MG_PAD * 2)    // 9216

// =================== LO (hi/lo 3-MMA) GEMM: 128x64 tile, BK=64, 2-stage ===================
#define LO_OFF_AL SA_BYTES
#define LO_OFF_BH (2 * SA_BYTES)
#define LO_OFF_BL (2 * SA_BYTES + SB_BYTES)
#define LO_ST     (2 * SA_BYTES + 2 * SB_BYTES)   // 55296
#define LO_SMEM   (2 * LO_ST)                      // 110592

__global__ __launch_bounds__(256, 2) void mma_gemm_lo_kernel(
    const __nv_bfloat16* __restrict__ Ahi, const __nv_bfloat16* __restrict__ Alo,
    const __nv_bfloat16* __restrict__ Bhi, const __nv_bfloat16* __restrict__ Blo,
    const float* __restrict__ bias, const float* __restrict__ res,
    float* __restrict__ Cf, int M, int N, int K)
{
    extern __shared__ __nv_bfloat16 smem[];
    uint32_t sbase = smem_u32(smem);

    int tid = threadIdx.x, lane = tid & 31, wid = tid >> 5;
    int brow = blockIdx.y, bcol = blockIdx.x;
    int warp_m = (wid >> 1) * 32;
    int warp_n = (wid & 1) * 32;

    const __nv_bfloat16* Aat = Ahi + (size_t)(brow * 128) * K;
    const __nv_bfloat16* Aal = Alo + (size_t)(brow * 128) * K;
    const __nv_bfloat16* Bbt = Bhi + (size_t)(bcol * 64) * K;
    const __nv_bfloat16* Bbl = Blo + (size_t)(bcol * 64) * K;

    float acc[2][4][4];
    #pragma unroll
    for (int t = 0; t < 2; t++)
        #pragma unroll
        for (int nt = 0; nt < 4; nt++)
            #pragma unroll
            for (int j = 0; j < 4; j++) acc[t][nt][j] = 0.0f;

    int nchunk = K >> 6;

    auto load_chunk = [&](int c, int st) {
        uint32_t stb = sbase + st * LO_ST;
        #pragma unroll
        for (int i = 0; i < 4; i++) {
            int idx = tid + i * 256;
            int row = idx >> 3, ch = idx & 7;
            uint32_t so = stb + (uint32_t)(row * MG_PAD + ch * 8) * 2;
            size_t go = (size_t)row * K + c * 64 + ch * 8;
            cp16(so, Aat + go);
            cp16(so + LO_OFF_AL, Aal + go);
        }
        #pragma unroll
        for (int i = 0; i < 2; i++) {
            int idx = tid + i * 256;
            int row = idx >> 3, ch = idx & 7;
            uint32_t so = stb + (uint32_t)(row * MG_PAD + ch * 8) * 2;
            size_t go = (size_t)row * K + c * 64 + ch * 8;
            cp16(so + LO_OFF_BH, Bbt + go);
            cp16(so + LO_OFF_BL, Bbl + go);
        }
        CP_COMMIT();
    };

    load_chunk(0, 0);

    for (int c = 0; c < nchunk; c++) {
        int stage = c & 1;
        __syncthreads();
        if (c + 1 < nchunk) load_chunk(c + 1, (c + 1) & 1);
        else CP_COMMIT();
        CP_WAIT1();
        __syncthreads();

        uint32_t sa_h = sbase + stage * LO_ST;
        uint32_t sa_l = sa_h + LO_OFF_AL;
        uint32_t sb_h = sa_h + LO_OFF_BH;
        uint32_t sb_l = sa_h + LO_OFF_BL;

        #pragma unroll
        for (int ks = 0; ks < 4; ks++) {
            int kk = ks * 16;
            uint32_t ah[2][4], al[2][4];
            #pragma unroll
            for (int t = 0; t < 2; t++) {
                uint32_t off = (uint32_t)((warp_m + t * 16 + (lane & 15)) * MG_PAD
                             + kk + ((lane >> 4) << 3)) * 2;
                LDSM4(ah[t], sa_h + off);
                LDSM4(al[t], sa_l + off);
            }
            uint32_t bh[4][2], bl[4][2];
            #pragma unroll
            for (int p = 0; p < 2; p++) {
                uint32_t off = (uint32_t)((warp_n + p * 16 + ((lane >> 3) & 1) * 8 + (lane & 7)) * MG_PAD
                             + kk + ((lane >> 4) << 3)) * 2;
                uint32_t r[4];
                LDSM4(r, sb_h + off);
                bh[2*p][0] = r[0]; bh[2*p][1] = r[2];
                bh[2*p+1][0] = r[1]; bh[2*p+1][1] = r[3];
                LDSM4(r, sb_l + off);
                bl[2*p][0] = r[0]; bl[2*p][1] = r[2];
                bl[2*p+1][0] = r[1]; bl[2*p+1][1] = r[3];
            }
            #pragma unroll
            for (int t = 0; t < 2; t++)
                #pragma unroll
                for (int nt = 0; nt < 4; nt++) {
                    mma_bf16(acc[t][nt], ah[t], bh[nt]);
                    mma_bf16(acc[t][nt], ah[t], bl[nt]);
                    mma_bf16(acc[t][nt], al[t], bh[nt]);
                }
        }
    }

    int r0 = lane >> 2, c0 = (lane & 3) * 2;
    #pragma unroll
    for (int t = 0; t < 2; t++) {
        #pragma unroll
        for (int half = 0; half < 2; half++) {
            int grow = brow * 128 + warp_m + t * 16 + r0 + half * 8;
            #pragma unroll
            for (int nt = 0; nt < 4; nt++) {
                int gcol = bcol * 64 + warp_n + nt * 8 + c0;
                float ox = acc[t][nt][half * 2 + 0] + bias[gcol];
                float oy = acc[t][nt][half * 2 + 1] + bias[gcol + 1];
                if (res) {
                    float2 rv = *(const float2*)(res + (size_t)grow * N + gcol);
                    ox += rv.x; oy += rv.y;
                }
                float2 o; o.x = ox; o.y = oy;
                *(float2*)(Cf + (size_t)grow * N + gcol) = o;
            }
        }
    }
}

// =================== 1x GEMM: 128x128 tile, warp 32x64, BK=64, 3-stage ===================
// Optional fused AA (|q|^2 per head-row) when AA != nullptr (qv mode, q half only).
#define X1_OFF_B  SA_BYTES
#define X1_ST     (2 * SA_BYTES)     // 36864
#define X1_SMEM   (3 * X1_ST)        // 110592

__global__ __launch_bounds__(256, 2) void mma_gemm1x_kernel(
    const __nv_bfloat16* __restrict__ Ahi,
    const __nv_bfloat16* __restrict__ Bhi,
    const float* __restrict__ bias, const float* __restrict__ bias2,
    __nv_bfloat16* __restrict__ Cb, __nv_bfloat16* __restrict__ Cb2,
    float* __restrict__ AAout,
    int M, int N, int K, int Nh)
{
    extern __shared__ __nv_bfloat16 smem[];
    uint32_t sbase = smem_u32(smem);

    int tid = threadIdx.x, lane = tid & 31, wid = tid >> 5;
    int brow = blockIdx.y, bcol = blockIdx.x;
    int warp_m = (wid >> 1) * 32;
    int warp_n = (wid & 1) * 64;

    const __nv_bfloat16* Aat = Ahi + (size_t)(brow * 128) * K;
    const __nv_bfloat16* Bbt = Bhi + (size_t)(bcol * 128) * K;

    float acc[2][8][4];
    #pragma unroll
    for (int t = 0; t < 2; t++)
        #pragma unroll
        for (int nt = 0; nt < 8; nt++)
            #pragma unroll
            for (int j = 0; j < 4; j++) acc[t][nt][j] = 0.0f;

    int nchunk = K >> 6;

    auto load_chunk = [&](int c, int st) {
        uint32_t stb = sbase + st * X1_ST;
        #pragma unroll
        for (int i = 0; i < 4; i++) {
            int idx = tid + i * 256;
            int row = idx >> 3, ch = idx & 7;
            uint32_t so = stb + (uint32_t)(row * MG_PAD + ch * 8) * 2;
            size_t go = (size_t)row * K + c * 64 + ch * 8;
            cp16(so, Aat + go);
            cp16(so + X1_OFF_B, Bbt + go);
        }
        CP_COMMIT();
    };

    load_chunk(0, 0);
    load_chunk(1 < nchunk ? 1 : 0, 1);

    for (int c = 0; c < nchunk; c++) {
        int stage = c % 3;
        CP_WAIT1();
        __syncthreads();
        if (c + 2 < nchunk) load_chunk(c + 2, (c + 2) % 3);
        else CP_COMMIT();

        uint32_t sa = sbase + stage * X1_ST;
        uint32_t sb = sa + X1_OFF_B;

        #pragma unroll
        for (int ks = 0; ks < 4; ks++) {
            int kk = ks * 16;
            uint32_t ah[2][4];
            #pragma unroll
            for (int t = 0; t < 2; t++) {
                uint32_t off = (uint32_t)((warp_m + t * 16 + (lane & 15)) * MG_PAD
                             + kk + ((lane >> 4) << 3)) * 2;
                LDSM4(ah[t], sa + off);
            }
            uint32_t bh[8][2];
            #pragma unroll
            for (int p = 0; p < 4; p++) {
                uint32_t off = (uint32_t)((warp_n + p * 16 + ((lane >> 3) & 1) * 8 + (lane & 7)) * MG_PAD
                             + kk + ((lane >> 4) << 3)) * 2;
                uint32_t r[4];
                LDSM4(r, sb + off);
                bh[2*p][0] = r[0]; bh[2*p][1] = r[2];
                bh[2*p+1][0] = r[1]; bh[2*p+1][1] = r[3];
            }
            #pragma unroll
            for (int t = 0; t < 2; t++)
                #pragma unroll
                for (int nt = 0; nt < 8; nt++)
                    mma_bf16(acc[t][nt], ah[t], bh[nt]);
        }
    }

    int r0 = lane >> 2, c0 = (lane & 3) * 2;
    bool qhalf = (AAout != nullptr) && (bcol * 128 + warp_n < Nh);
    int head = (bcol * 128 + warp_n) / 64;   // valid when qhalf

    #pragma unroll
    for (int t = 0; t < 2; t++) {
        #pragma unroll
        for (int half = 0; half < 2; half++) {
            int grow = brow * 128 + warp_m + t * 16 + r0 + half * 8;
            float aasum = 0.0f;
            #pragma unroll
            for (int nt = 0; nt < 8; nt++) {
                int gcol = bcol * 128 + warp_n + nt * 8 + c0;
                float ox = acc[t][nt][half * 2 + 0];
                float oy = acc[t][nt][half * 2 + 1];
                __nv_bfloat16* dst; const float* bs; int cc;
                if (Cb2 && gcol >= Nh) { dst = Cb2; bs = bias2; cc = gcol - Nh; }
                else                   { dst = Cb;  bs = bias;  cc = gcol; }
                int nw = Cb2 ? Nh : N;
                ox += bs[cc]; oy += bs[cc + 1];
                __nv_bfloat162 hv = __floats2bfloat162_rn(ox, oy);
                *(__nv_bfloat162*)(dst + (size_t)grow * nw + cc) = hv;
                if (qhalf) {
                    float2 f = __bfloat1622float2(hv);
                    aasum += f.x * f.x + f.y * f.y;
                }
            }
            if (qhalf) {
                aasum += __shfl_xor_sync(0xffffffffu, aasum, 1);
                aasum += __shfl_xor_sync(0xffffffffu, aasum, 2);
                if ((lane & 3) == 0) {
                    int b = grow >> 11, n = grow & 2047;
                    AAout[((size_t)(b * NHEAD + head)) * NSEQ + n] = aasum;
                }
            }
        }
    }
}

// =================== HMMA flash attention, cp.async double-buffered K/V ===================
#define FB_BQ 64
#define FB_BK 64
#define FB_PAD 72
#define FB_KV_BYTES (FB_BK * FB_PAD * 2)

__global__ __launch_bounds__(128) void flash_mma_kernel(
    const __nv_bfloat16* __restrict__ Qb, const __nv_bfloat16* __restrict__ Vb,
    const float* __restrict__ AA,
    __nv_bfloat16* __restrict__ Ohi, __nv_bfloat16* __restrict__ Olo)
{
    __shared__ __nv_bfloat16 sQ[FB_BQ * FB_PAD];
    __shared__ __nv_bfloat16 sK[2][FB_BK * FB_PAD];
    __shared__ __nv_bfloat16 sV[2][FB_BK * FB_PAD];
    __shared__ float sAA[2][FB_BK];

    int b = blockIdx.z, h = blockIdx.y;
    int q0 = blockIdx.x * FB_BQ;
    int tid = threadIdx.x, lane = tid & 31, w = tid >> 5;

    uint32_t sq_a = smem_u32(sQ);
    uint32_t sk_a = smem_u32(sK);
    uint32_t sv_a = smem_u32(sV);

    #pragma unroll
    for (int i = 0; i < 4; i++) {
        int idx = tid + i * 128;
        int r = idx >> 3, c = idx & 7;
        size_t off = (size_t)(b * NSEQ + r) * DIM + h * DHEAD + c * 8;
        uint32_t so = (uint32_t)(r * FB_PAD + c * 8) * 2;
        cp16(sk_a + so, Qb + off);
        cp16(sv_a + so, Vb + off);
    }
    CP_COMMIT();

    #pragma unroll
    for (int i = 0; i < 4; i++) {
        int idx = tid + i * 128;
        int r = idx >> 3, c = idx & 7;
        size_t off = (size_t)(b * NSEQ + q0 + r) * DIM + h * DHEAD + c * 8;
        *(uint4*)&sQ[r * FB_PAD + c * 8] = *(const uint4*)(Qb + off);
    }
    __syncthreads();

    uint32_t qa[4][4];
    #pragma unroll
    for (int ks = 0; ks < 4; ks++) {
        uint32_t off = (uint32_t)((w * 16 + (lane & 15)) * FB_PAD + ks * 16 + ((lane >> 4) << 3)) * 2;
        LDSM4(qa[ks], sq_a + off);
    }

    float m0 = -1e30f, m1 = -1e30f, l0 = 0.0f, l1 = 0.0f;
    float o[8][4];
    #pragma unroll
    for (int t = 0; t < 8; t++)
        #pragma unroll
        for (int j = 0; j < 4; j++) o[t][j] = 0.0f;

    const float* aab = AA + ((size_t)(b * NHEAD + h)) * NSEQ;
    const int ntiles = NSEQ / FB_BK;

    for (int it = 0; it < ntiles; it++) {
        int buf = it & 1;
        __syncthreads();

        if (it + 1 < ntiles) {
            uint32_t dst_k = sk_a + (buf ^ 1) * FB_KV_BYTES;
            uint32_t dst_v = sv_a + (buf ^ 1) * FB_KV_BYTES;
            #pragma unroll
            for (int i = 0; i < 4; i++) {
                int idx = tid + i * 128;
                int r = idx >> 3, c = idx & 7;
                size_t off = (size_t)(b * NSEQ + (it + 1) * FB_BK + r) * DIM + h * DHEAD + c * 8;
                uint32_t so = (uint32_t)(r * FB_PAD + c * 8) * 2;
                cp16(dst_k + so, Qb + off);
                cp16(dst_v + so, Vb + off);
            }
        }
        CP_COMMIT();
        if (tid < FB_BK) sAA[buf][tid] = aab[it * FB_BK + tid];
        CP_WAIT1();
        __syncthreads();

        uint32_t skb = sk_a + buf * FB_KV_BYTES;
        uint32_t svb = sv_a + buf * FB_KV_BYTES;

        float sc[8][4];
        #pragma unroll
        for (int t = 0; t < 8; t++)
            #pragma unroll
            for (int j = 0; j < 4; j++) sc[t][j] = 0.0f;

        #pragma unroll
        for (int ks = 0; ks < 4; ks++) {
            uint32_t kb[8][2];
            #pragma unroll
            for (int p = 0; p < 4; p++) {
                uint32_t off = (uint32_t)((p * 16 + ((lane >> 3) & 1) * 8 + (lane & 7)) * FB_PAD
                             + ks * 16 + ((lane >> 4) << 3)) * 2;
                uint32_t r[4];
                LDSM4(r, skb + off);
                kb[2*p][0] = r[0]; kb[2*p][1] = r[2];
                kb[2*p+1][0] = r[1]; kb[2*p+1][1] = r[3];
            }
            #pragma unroll
            for (int t = 0; t < 8; t++) mma_bf16(sc[t], qa[ks], kb[t]);
        }

        float mt0 = -1e30f, mt1 = -1e30f;
        #pragma unroll
        for (int t = 0; t < 8; t++) {
            float a0 = sAA[buf][t * 8 + (lane & 3) * 2];
            float a1 = sAA[buf][t * 8 + (lane & 3) * 2 + 1];
            sc[t][0] = 0.25f * sc[t][0] - 0.125f * a0;
            sc[t][1] = 0.25f * sc[t][1] - 0.125f * a1;
            sc[t][2] = 0.25f * sc[t][2] - 0.125f * a0;
            sc[t][3] = 0.25f * sc[t][3] - 0.125f * a1;
            mt0 = fmaxf(mt0, fmaxf(sc[t][0], sc[t][1]));
            mt1 = fmaxf(mt1, fmaxf(sc[t][2], sc[t][3]));
        }
        mt0 = fmaxf(mt0, __shfl_xor_sync(0xffffffffu, mt0, 1));
        mt0 = fmaxf(mt0, __shfl_xor_sync(0xffffffffu, mt0, 2));
        mt1 = fmaxf(mt1, __shfl_xor_sync(0xffffffffu, mt1, 1));
        mt1 = fmaxf(mt1, __shfl_xor_sync(0xffffffffu, mt1, 2));

        float mn0 = fmaxf(m0, mt0), mn1 = fmaxf(m1, mt1);
        float al0 = __expf(m0 - mn0), al1 = __expf(m1 - mn1);
        m0 = mn0; m1 = mn1;
        l0 *= al0; l1 *= al1;
        #pragma unroll
        for (int t = 0; t < 8; t++) {
            o[t][0] *= al0; o[t][1] *= al0;
            o[t][2] *= al1; o[t][3] *= al1;
        }

        #pragma unroll
        for (int t = 0; t < 8; t++) {
            sc[t][0] = __expf(sc[t][0] - m0);
            sc[t][1] = __expf(sc[t][1] - m0);
            sc[t][2] = __expf(sc[t][2] - m1);
            sc[t][3] = __expf(sc[t][3] - m1);
            l0 += sc[t][0] + sc[t][1];
            l1 += sc[t][2] + sc[t][3];
        }

        #pragma unroll
        for (int j = 0; j < 4; j++) {
            uint32_t pa[4];
            __nv_bfloat162 t2;
            t2 = __floats2bfloat162_rn(sc[2*j][0],   sc[2*j][1]);   pa[0] = *(uint32_t*)&t2;
            t2 = __floats2bfloat162_rn(sc[2*j][2],   sc[2*j][3]);   pa[1] = *(uint32_t*)&t2;
            t2 = __floats2bfloat162_rn(sc[2*j+1][0], sc[2*j+1][1]); pa[2] = *(uint32_t*)&t2;
            t2 = __floats2bfloat162_rn(sc[2*j+1][2], sc[2*j+1][3]); pa[3] = *(uint32_t*)&t2;

            uint32_t vb[8][2];
            #pragma unroll
            for (int dp = 0; dp < 4; dp++) {
                int g = lane >> 3, rr = lane & 7;
                uint32_t off = (uint32_t)((j * 16 + (g & 1) * 8 + rr) * FB_PAD
                             + dp * 16 + (g >> 1) * 8) * 2;
                uint32_t r[4];
                LDSM4T(r, svb + off);
                vb[2*dp][0]   = r[0]; vb[2*dp][1]   = r[1];
                vb[2*dp+1][0] = r[2]; vb[2*dp+1][1] = r[3];
            }
            #pragma unroll
            for (int t = 0; t < 8; t++) mma_bf16(o[t], pa, vb[t]);
        }
    }

    l0 += __shfl_xor_sync(0xffffffffu, l0, 1);
    l0 += __shfl_xor_sync(0xffffffffu, l0, 2);
    l1 += __shfl_xor_sync(0xffffffffu, l1, 1);
    l1 += __shfl_xor_sync(0xffffffffu, l1, 2);
    float inv0 = 1.0f / l0, inv1 = 1.0f / l1;

    int r0g = q0 + w * 16 + (lane >> 2);
    #pragma unroll
    for (int t = 0; t < 8; t++) {
        int c = h * DHEAD + t * 8 + (lane & 3) * 2;
        float o00 = o[t][0] * inv0, o01 = o[t][1] * inv0;
        float o10 = o[t][2] * inv1, o11 = o[t][3] * inv1;
        size_t off0 = (size_t)(b * NSEQ + r0g) * DIM + c;
        size_t off1 = (size_t)(b * NSEQ + r0g + 8) * DIM + c;
        __nv_bfloat162 h0 = __floats2bfloat162_rn(o00, o01);
        __nv_bfloat162 h1 = __floats2bfloat162_rn(o10, o11);
        *(__nv_bfloat162*)(Ohi + off0) = h0;
        *(__nv_bfloat162*)(Ohi + off1) = h1;
        *(__nv_bfloat162*)(Olo + off0) = __floats2bfloat162_rn(
            o00 - __bfloat162float(h0.x), o01 - __bfloat162float(h0.y));
        *(__nv_bfloat162*)(Olo + off1) = __floats2bfloat162_rn(
            o10 - __bfloat162float(h1.x), o11 - __bfloat162float(h1.y));
    }
}

// ---------------- fused LayerNorm + hi/lo split ----------------
__global__ __launch_bounds__(128) void ln_split_kernel(
    const float* __restrict__ X, const float* __restrict__ w,
    const float* __restrict__ bb, __nv_bfloat16* __restrict__ Hi,
    __nv_bfloat16* __restrict__ Lo)
{
    int row = blockIdx.x;
    int tid = threadIdx.x;
    const float* xp = X + (size_t)row * DIM;
    float4 v = *(const float4*)(xp + tid * 4);
    float s  = v.x + v.y + v.z + v.w;
    float sq = v.x*v.x + v.y*v.y + v.z*v.z + v.w*v.w;
    #pragma unroll
    for (int o = 16; o > 0; o >>= 1) {
        s  += __shfl_xor_sync(0xffffffffu, s,  o);
        sq += __shfl_xor_sync(0xffffffffu, sq, o);
    }
    __shared__ float reds[4], redq[4];
    int wid = tid >> 5, lane = tid & 31;
    if (lane == 0) { reds[wid] = s; redq[wid] = sq; }
    __syncthreads();
    s  = reds[0] + reds[1] + reds[2] + reds[3];
    sq = redq[0] + redq[1] + redq[2] + redq[3];
    float mu   = s * (1.0f / DIM);
    float var  = sq * (1.0f / DIM) - mu * mu;
    float rstd = rsqrtf(var + 1e-5f);
    float4 wv = *(const float4*)(w  + tid * 4);
    float4 bv = *(const float4*)(bb + tid * 4);
    float o0 = (v.x - mu) * rstd * wv.x + bv.x;
    float o1 = (v.y - mu) * rstd * wv.y + bv.y;
    float o2 = (v.z - mu) * rstd * wv.z + bv.z;
    float o3 = (v.w - mu) * rstd * wv.w + bv.w;
    __nv_bfloat162 h0 = __floats2bfloat162_rn(o0, o1);
    __nv_bfloat162 h1 = __floats2bfloat162_rn(o2, o3);
    __nv_bfloat162 l0 = __floats2bfloat162_rn(o0 - __bfloat162float(h0.x),
                                              o1 - __bfloat162float(h0.y));
    __nv_bfloat162 l1 = __floats2bfloat162_rn(o2 - __bfloat162float(h1.x),
                                              o3 - __bfloat162float(h1.y));
    size_t off = (size_t)row * DIM + tid * 4;
    *(__nv_bfloat162*)(Hi + off) = h0;
    *(__nv_bfloat162*)(Hi + off + 2) = h1;
    *(__nv_bfloat162*)(Lo + off) = l0;
    *(__nv_bfloat162*)(Lo + off + 2) = l1;
}

// ---------------- ALL weight transposes+splits in ONE launch ----------------
// slab layout (units of WS elems): a1_wq@0, a1_wv@1, a1_wo@2, a2_wq@3, a2_wv@4,
// a2_wo@5, ff_w1@6 (8 slabs), ff_w2@14 (4 slabs)
__global__ __launch_bounds__(256) void conv_wt_all_kernel(
    const float* __restrict__ w0, const float* __restrict__ w1,
    const float* __restrict__ w2, const float* __restrict__ w3,
    const float* __restrict__ w4, const float* __restrict__ w5,
    const float* __restrict__ w6, const float* __restrict__ w7,
    __nv_bfloat16* __restrict__ Thi, __nv_bfloat16* __restrict__ Tlo)
{
    int tile = blockIdx.x;
    const float* W; size_t woff; int K, N, n0, k0;
    if (tile < 384) {
        int wsel = tile >> 6, rem = tile & 63;
        switch (wsel) {
            case 0: W = w0; break; case 1: W = w1; break; case 2: W = w2; break;
            case 3: W = w3; break; case 4: W = w4; break; default: W = w5; break;
        }
        woff = (size_t)wsel * WS; K = 512; N = 512;
        n0 = (rem & 3) * 128; k0 = (rem >> 2) * 32;
    } else if (tile < 896) {
        int rem = tile - 384;
        W = w6; woff = (size_t)6 * WS; K = 512; N = 4096;
        n0 = (rem & 31) * 128; k0 = (rem >> 5) * 32;
    } else {
        int rem = tile - 896;
        W = w7; woff = (size_t)14 * WS; K = 2048; N = 512;
        n0 = (rem & 3) * 128; k0 = (rem >> 2) * 32;
    }
    __nv_bfloat16* This = Thi + woff;
    __nv_bfloat16* Tlos = Tlo + woff;

    __shared__ __nv_bfloat16 shi[32][132];
    __shared__ __nv_bfloat16 slo[32][132];
    int tid = threadIdx.x;
    int tx = tid & 31;
    int ty = tid >> 5;

    #pragma unroll
    for (int j = 0; j < 4; j++) {
        int k = ty + j * 8;
        float4 wv = *(const float4*)(W + (size_t)(k0 + k) * N + n0 + tx * 4);
        float f[4] = {wv.x, wv.y, wv.z, wv.w};
        #pragma unroll
        for (int i = 0; i < 4; i++) {
            __nv_bfloat16 hb = __float2bfloat16_rn(f[i]);
            shi[k][tx * 4 + i] = hb;
            slo[k][tx * 4 + i] = __float2bfloat16_rn(f[i] - __bfloat162float(hb));
        }
    }
    __syncthreads();

    int n  = tid >> 1;
    int kh = (tid & 1) * 16;
    uint4 uh, ul;
    uint32_t* uhp = (uint32_t*)&uh;
    uint32_t* ulp = (uint32_t*)&ul;
    #pragma unroll
    for (int half = 0; half < 2; half++) {
        #pragma unroll
        for (int p = 0; p < 4; p++) {
            int k = kh + half * 8 + p * 2;
            uhp[p] = (uint32_t)*(uint16_t*)&shi[k][n] |
                     ((uint32_t)*(uint16_t*)&shi[k + 1][n] << 16);
            ulp[p] = (uint32_t)*(uint16_t*)&slo[k][n] |
                     ((uint32_t)*(uint16_t*)&slo[k + 1][n] << 16);
        }
        size_t off = (size_t)(n0 + n) * K + k0 + kh + half * 8;
        *(uint4*)(This + off) = uh;
        *(uint4*)(Tlos + off) = ul;
    }
}

// ---------------- GEGLU (bf16 input) + hi/lo split ----------------
__device__ __forceinline__ float gelu_exact(float x) {
    return 0.5f * x * (1.0f + erff(x * 0.70710678118654752f));
}
__global__ void geglu_split_kernel(const __nv_bfloat16* __restrict__ H,
                                   __nv_bfloat16* __restrict__ Hi,
                                   __nv_bfloat16* __restrict__ Lo)
{
    int idx = blockIdx.x * blockDim.x + threadIdx.x;
    if (idx >= ROWS * (IFF / 8)) return;
    int row = idx / (IFF / 8);
    int c8  = idx % (IFF / 8);
    const __nv_bfloat16* base = H + (size_t)row * (2 * IFF);
    uint4 au = *(const uint4*)(base + c8 * 8);
    uint4 gu = *(const uint4*)(base + IFF + c8 * 8);
    const __nv_bfloat162* ap = (const __nv_bfloat162*)&au;
    const __nv_bfloat162* gp = (const __nv_bfloat162*)&gu;
    uint4 ho, lo;
    uint32_t* hop = (uint32_t*)&ho;
    uint32_t* lop = (uint32_t*)&lo;
    #pragma unroll
    for (int j = 0; j < 4; j++) {
        float2 af = __bfloat1622float2(ap[j]);
        float2 gf = __bfloat1622float2(gp[j]);
        float r0 = af.x * gelu_exact(gf.x);
        float r1 = af.y * gelu_exact(gf.y);
        __nv_bfloat162 hb = __floats2bfloat162_rn(r0, r1);
        __nv_bfloat162 lb = __floats2bfloat162_rn(r0 - __bfloat162float(hb.x),
                                                  r1 - __bfloat162float(hb.y));
        hop[j] = *(uint32_t*)&hb;
        lop[j] = *(uint32_t*)&lb;
    }
    size_t off = (size_t)row * IFF + c8 * 8;
    *(uint4*)(Hi + off) = ho;
    *(uint4*)(Lo + off) = lo;
}

// ---------------- host orchestration ----------------
struct Bufs {
    float *x1, *x2, *aa;
    __nv_bfloat16 *hb;
    __nv_bfloat16 *ahi, *alo, *whi, *wlo, *qb, *vb;
};

static void tc_gemm_f32_lo(const Bufs& B, size_t wslab, const float* bias,
                           const float* res, float* C, int M, int N, int K) {
    dim3 grid(N / 64, M / 128);
    mma_gemm_lo_kernel<<<grid, 256, LO_SMEM>>>(
        B.ahi, B.alo, B.whi + wslab * WS, B.wlo + wslab * WS, bias, res, C, M, N, K);
}
static void tc_gemm_bf16_1x(const Bufs& B, size_t wslab, const float* bias,
                            __nv_bfloat16* C, int M, int N, int K) {
    dim3 grid(N / 128, M / 128);
    mma_gemm1x_kernel<<<grid, 256, X1_SMEM>>>(
        B.ahi, B.whi + wslab * WS, bias, nullptr, C, nullptr, nullptr, M, N, K, 0);
}
static void tc_gemm_qv(const Bufs& B, size_t wslab, const float* bq, const float* bv,
                       int M, int K) {
    dim3 grid(1024 / 128, M / 128);
    mma_gemm1x_kernel<<<grid, 256, X1_SMEM>>>(
        B.ahi, B.whi + wslab * WS, bq, bv, B.qb, B.vb, B.aa, M, 1024, K, 512);
}
static void run_attention(const Bufs& B) {
    dim3 fa_grid(NSEQ / FB_BQ, NHEAD, NBATCH);
    flash_mma_kernel<<<fa_grid, 128>>>(B.qb, B.vb, B.aa, B.ahi, B.alo);
}

extern "C" void kernel_launch(void* const* d_in, const int* in_sizes, int n_in,
                              void* d_out, int out_size)
{
    const float* x     = (const float*)d_in[0];
    const float* sa_w  = (const float*)d_in[1];
    const float* sa_b  = (const float*)d_in[2];
    const float* ca_w  = (const float*)d_in[3];
    const float* ca_b  = (const float*)d_in[4];
    const float* ff_nw = (const float*)d_in[5];
    const float* ff_nb = (const float*)d_in[6];
    const float* a1_wq = (const float*)d_in[7];
    const float* a1_bq = (const float*)d_in[8];
    const float* a1_wv = (const float*)d_in[9];
    const float* a1_bv = (const float*)d_in[10];
    const float* a1_wo = (const float*)d_in[11];
    const float* a1_bo = (const float*)d_in[12];
    const float* a2_wq = (const float*)d_in[13];
    const float* a2_bq = (const float*)d_in[14];
    const float* a2_wv = (const float*)d_in[15];
    const float* a2_bv = (const float*)d_in[16];
    const float* a2_wo = (const float*)d_in[17];
    const float* a2_bo = (const float*)d_in[18];
    const float* ff_w1 = (const float*)d_in[19];
    const float* ff_b1 = (const float*)d_in[20];
    const float* ff_w2 = (const float*)d_in[21];
    const float* ff_b2 = (const float*)d_in[22];
    float* out = (float*)d_out;

    Bufs B;
    cudaGetSymbolAddress((void**)&B.x1,  g_x1);
    cudaGetSymbolAddress((void**)&B.x2,  g_x2);
    cudaGetSymbolAddress((void**)&B.aa,  g_aa);
    cudaGetSymbolAddress((void**)&B.hb,  g_h);
    cudaGetSymbolAddress((void**)&B.ahi, g_ahi);
    cudaGetSymbolAddress((void**)&B.alo, g_alo);
    cudaGetSymbolAddress((void**)&B.whi, g_whi);
    cudaGetSymbolAddress((void**)&B.wlo, g_wlo);
    cudaGetSymbolAddress((void**)&B.qb,  g_qb);
    cudaGetSymbolAddress((void**)&B.vb,  g_vb);

    cudaFuncSetAttribute(mma_gemm_lo_kernel,
                         cudaFuncAttributeMaxDynamicSharedMemorySize, LO_SMEM);
    cudaFuncSetAttribute(mma_gemm1x_kernel,
                         cudaFuncAttributeMaxDynamicSharedMemorySize, X1_SMEM);

    // ---- all weight transposes in one launch ----
    conv_wt_all_kernel<<<1152, 256>>>(a1_wq, a1_wv, a1_wo, a2_wq, a2_wv, a2_wo,
                                      ff_w1, ff_w2, B.whi, B.wlo);

    // ---- self-attention (attn1) ----
    ln_split_kernel<<<ROWS, 128>>>(x, sa_w, sa_b, B.ahi, B.alo);
    tc_gemm_qv(B, 0, a1_bq, a1_bv, ROWS, DIM);        // AA fused
    run_attention(B);
    tc_gemm_f32_lo(B, 2, a1_bo, x, B.x1, ROWS, DIM, DIM);

    // ---- attn2 (k=q, v from x) ----
    ln_split_kernel<<<ROWS, 128>>>(B.x1, ca_w, ca_b, B.ahi, B.alo);
    tc_gemm_qv(B, 3, a2_bq, a2_bv, ROWS, DIM);        // AA fused
    run_attention(B);
    tc_gemm_f32_lo(B, 5, a2_bo, B.x1, B.x2, ROWS, DIM, DIM);

    // ---- GEGLU FFN ----
    ln_split_kernel<<<ROWS, 128>>>(B.x2, ff_nw, ff_nb, B.ahi, B.alo);
    tc_gemm_bf16_1x(B, 6, ff_b1, B.hb, ROWS, 2 * IFF, DIM);
    int ge_blocks = (ROWS * (IFF / 8) + 255) / 256;
    geglu_split_kernel<<<ge_blocks, 256>>>(B.hb, B.ahi, B.alo);
    tc_gemm_f32_lo(B, 14, ff_b2, B.x2, out, ROWS, DIM, IFF);
}